// round 1
// baseline (speedup 1.0000x reference)
#include <cuda_runtime.h>
#include <cstdint>
#include <math.h>

#define Bn 16
#define Nn 3136
#define Cc 512
#define Hpix 56
#define HEADS 8
#define Dd 64
#define AG 49

// ---------------- scratch (device globals; no allocation allowed) ----------------
__device__ float g_q[(size_t)Bn * Nn * Cc];            //  98 MB  (b,n,c)
__device__ float g_kv[(size_t)Bn * Nn * 2 * Cc];       // 196 MB  (b,n,2c) k=[0,512) v=[512,1024)
__device__ float g_agent[(size_t)Bn * AG * Cc];        // (b,a,c)
__device__ float g_bias_ak[(size_t)HEADS * AG * Nn];   // (h,a,n)
__device__ float g_bias_qa[(size_t)HEADS * Nn * AG];   // (h,n,a)
__device__ float g_attn1[(size_t)Bn * HEADS * AG * Nn];// (b,h,a,n)  ~79 MB
__device__ float g_agentv[(size_t)Bn * HEADS * AG * Dd];
__device__ float g_acc[(size_t)Bn * Nn * Cc];          // attention out + dwc

// ---------------- generic fp32 GEMM: C[M,Nc] = A[M,K] @ W[K,Nc] (+bias) ----------
// BM=128, BN=64, BK=16, 256 threads, 8x4 per-thread tile. All dims divide evenly.
__global__ __launch_bounds__(256) void gemm_kernel(
    const float* __restrict__ A, const float* __restrict__ W,
    float* __restrict__ Cout, int M, int K, int Nc, const float* __restrict__ bias)
{
    __shared__ float As[16][132];   // transposed A tile, padded
    __shared__ float Bs[16][68];    // B tile, padded (16B-aligned rows)
    const int tid = threadIdx.x;
    const int bm = blockIdx.y * 128;
    const int bn = blockIdx.x * 64;
    const int tx = tid & 15;        // n-direction (4 cols)
    const int ty = tid >> 4;        // m-direction (8 rows)

    float acc[8][4];
#pragma unroll
    for (int i = 0; i < 8; i++)
#pragma unroll
        for (int j = 0; j < 4; j++) acc[i][j] = 0.f;

    for (int k0 = 0; k0 < K; k0 += 16) {
        // load A tile 128x16 (2 float4 per thread), store transposed
#pragma unroll
        for (int jj = 0; jj < 2; jj++) {
            int f = tid * 2 + jj;               // 0..511
            int row = f >> 2;                   // 0..127
            int c4 = (f & 3) * 4;               // 0,4,8,12
            float4 v = *(const float4*)&A[(size_t)(bm + row) * K + k0 + c4];
            As[c4 + 0][row] = v.x;
            As[c4 + 1][row] = v.y;
            As[c4 + 2][row] = v.z;
            As[c4 + 3][row] = v.w;
        }
        // load B tile 16x64 (1 float4 per thread)
        {
            int row = tid >> 4;                 // 0..15
            int c4 = (tid & 15) * 4;
            *(float4*)&Bs[row][c4] = *(const float4*)&W[(size_t)(k0 + row) * Nc + bn + c4];
        }
        __syncthreads();
#pragma unroll
        for (int k = 0; k < 16; k++) {
            float a[8], b[4];
            *(float4*)&a[0] = *(const float4*)&As[k][ty * 8];
            *(float4*)&a[4] = *(const float4*)&As[k][ty * 8 + 4];
            *(float4*)&b[0] = *(const float4*)&Bs[k][tx * 4];
#pragma unroll
            for (int i = 0; i < 8; i++)
#pragma unroll
                for (int j = 0; j < 4; j++)
                    acc[i][j] = fmaf(a[i], b[j], acc[i][j]);
        }
        __syncthreads();
    }

    float b4[4] = {0.f, 0.f, 0.f, 0.f};
    if (bias) {
#pragma unroll
        for (int j = 0; j < 4; j++) b4[j] = bias[bn + tx * 4 + j];
    }
#pragma unroll
    for (int i = 0; i < 8; i++) {
        float4 o;
        o.x = acc[i][0] + b4[0];
        o.y = acc[i][1] + b4[1];
        o.z = acc[i][2] + b4[2];
        o.w = acc[i][3] + b4[3];
        *(float4*)&Cout[(size_t)(bm + ty * 8 + i) * Nc + bn + tx * 4] = o;
    }
}

// ---------------- 8x8 mean pool: agent[b,a,c] ----------------
__global__ __launch_bounds__(256) void pool_kernel()
{
    int idx = blockIdx.x * 256 + threadIdx.x;   // < B*AG*C (exact)
    int c = idx % Cc;
    int ba = idx / Cc;
    int a = ba % AG;
    int b = ba / AG;
    int py = a / 7, px = a % 7;
    float s = 0.f;
#pragma unroll
    for (int dy = 0; dy < 8; dy++) {
        int n_base = (py * 8 + dy) * Hpix + px * 8;
#pragma unroll
        for (int dx = 0; dx < 8; dx++)
            s += g_q[((size_t)b * Nn + n_base + dx) * Cc + c];
    }
    g_agent[idx] = s * (1.0f / 64.0f);
}

// ---------------- bilinear 7x7 -> 56x56 (half-pixel centers, edge clamp) ----------
__device__ __forceinline__ float bilerp7(const float* __restrict__ t, int y, int x)
{
    float sy = (y + 0.5f) * 0.125f - 0.5f;
    float sx = (x + 0.5f) * 0.125f - 0.5f;
    int y0f = (int)floorf(sy);
    int x0f = (int)floorf(sx);
    float wy = sy - (float)y0f;
    float wx = sx - (float)x0f;
    int y0 = min(6, max(0, y0f));
    int y1 = min(6, max(0, y0f + 1));
    int x0 = min(6, max(0, x0f));
    int x1 = min(6, max(0, x0f + 1));
    float v00 = t[y0 * 7 + x0], v01 = t[y0 * 7 + x1];
    float v10 = t[y1 * 7 + x0], v11 = t[y1 * 7 + x1];
    float top = v00 + wx * (v01 - v00);
    float bot = v10 + wx * (v11 - v10);
    return top + wy * (bot - top);
}

__global__ __launch_bounds__(256) void biasak_kernel(
    const float* __restrict__ an, const float* __restrict__ ah, const float* __restrict__ aw)
{
    int idx = blockIdx.x * 256 + threadIdx.x;   // < H*AG*Nn (exact)
    int n = idx % Nn;
    int haa = idx / Nn;                          // h*49+a
    int y = n / Hpix, x = n % Hpix;
    g_bias_ak[idx] = bilerp7(an + haa * 49, y, x) + ah[haa] + aw[haa];
}

__global__ __launch_bounds__(256) void biasqa_kernel(
    const float* __restrict__ na, const float* __restrict__ ha, const float* __restrict__ wa)
{
    int idx = blockIdx.x * 256 + threadIdx.x;   // < H*Nn*AG (exact)
    int a = idx % AG;
    int hn = idx / AG;
    int n = hn % Nn;
    int h = hn / Nn;
    int y = n / Hpix, x = n % Hpix;
    int haa = h * AG + a;
    g_bias_qa[idx] = bilerp7(na + haa * 49, y, x) + ha[haa] + wa[haa];
}

// ---------------- stage 1 scores: s1[b,h,a,n] = (agent*scale)·k + bias ------------
__global__ __launch_bounds__(256) void scores1_kernel()
{
    const int bh = blockIdx.x;
    const int b = bh / HEADS, h = bh % HEADS;
    __shared__ float a_s[52][64];     // agents (padded to 52, zero-filled)
    __shared__ float ks[128][68];     // 272B row stride -> conflict-free f4 reads
    const int tid = threadIdx.x;

    for (int f = tid; f < 52 * 64; f += 256) {
        int a = f >> 6, d = f & 63;
        a_s[a][d] = (a < AG) ? g_agent[((size_t)b * AG + a) * Cc + h * Dd + d] * 0.125f : 0.f;
    }
    const int nt = tid & 31;
    const int at0 = tid >> 5;

    for (int n0 = 0; n0 < Nn; n0 += 128) {
        __syncthreads();
        for (int f = tid; f < 128 * 16; f += 256) {
            int row = f >> 4, c4 = (f & 15) * 4;
            *(float4*)&ks[row][c4] =
                *(const float4*)&g_kv[((size_t)(b * Nn + n0 + row)) * (2 * Cc) + h * Dd + c4];
        }
        __syncthreads();
        for (int at = at0; at < 13; at += 8) {
            int a0 = at * 4;
            float acc[4][4];
#pragma unroll
            for (int i = 0; i < 4; i++)
#pragma unroll
                for (int j = 0; j < 4; j++) acc[i][j] = 0.f;
#pragma unroll 4
            for (int d4 = 0; d4 < 16; d4++) {
                float4 av[4], kf[4];
#pragma unroll
                for (int i = 0; i < 4; i++) av[i] = *(const float4*)&a_s[a0 + i][d4 * 4];
#pragma unroll
                for (int j = 0; j < 4; j++) kf[j] = *(const float4*)&ks[nt + 32 * j][d4 * 4];
#pragma unroll
                for (int i = 0; i < 4; i++)
#pragma unroll
                    for (int j = 0; j < 4; j++) {
                        acc[i][j] = fmaf(av[i].x, kf[j].x, acc[i][j]);
                        acc[i][j] = fmaf(av[i].y, kf[j].y, acc[i][j]);
                        acc[i][j] = fmaf(av[i].z, kf[j].z, acc[i][j]);
                        acc[i][j] = fmaf(av[i].w, kf[j].w, acc[i][j]);
                    }
            }
#pragma unroll
            for (int i = 0; i < 4; i++) {
                int a = a0 + i;
                if (a < AG) {
#pragma unroll
                    for (int j = 0; j < 4; j++) {
                        int n = n0 + nt + 32 * j;
                        g_attn1[((size_t)bh * AG + a) * Nn + n] =
                            acc[i][j] + g_bias_ak[((size_t)(h * AG + a)) * Nn + n];
                    }
                }
            }
        }
    }
}

// ---------------- softmax over n (row length 3136) ----------------
__global__ __launch_bounds__(256) void softmax1_kernel()
{
    float* p = g_attn1 + (size_t)blockIdx.x * Nn;
    const int tid = threadIdx.x;
    float vals[13];
    float m = -1e30f;
#pragma unroll
    for (int i = 0; i < 13; i++) {
        int n = tid + 256 * i;
        vals[i] = (n < Nn) ? p[n] : -1e30f;
        m = fmaxf(m, vals[i]);
    }
    __shared__ float red[8];
#pragma unroll
    for (int o = 16; o > 0; o >>= 1) m = fmaxf(m, __shfl_xor_sync(0xffffffffu, m, o));
    if ((tid & 31) == 0) red[tid >> 5] = m;
    __syncthreads();
    float bm = red[0];
#pragma unroll
    for (int i = 1; i < 8; i++) bm = fmaxf(bm, red[i]);
    __syncthreads();

    float s = 0.f;
#pragma unroll
    for (int i = 0; i < 13; i++) {
        float e = __expf(vals[i] - bm);
        vals[i] = e;
        s += e;
    }
#pragma unroll
    for (int o = 16; o > 0; o >>= 1) s += __shfl_xor_sync(0xffffffffu, s, o);
    if ((tid & 31) == 0) red[tid >> 5] = s;
    __syncthreads();
    float tot = 0.f;
#pragma unroll
    for (int i = 0; i < 8; i++) tot += red[i];
    float inv = 1.0f / tot;
#pragma unroll
    for (int i = 0; i < 13; i++) {
        int n = tid + 256 * i;
        if (n < Nn) p[n] = vals[i] * inv;
    }
}

// ---------------- agent_v[b,h,a,d] = attn1 @ v ----------------
__global__ __launch_bounds__(256) void agentv_kernel()
{
    const int bh = blockIdx.x;
    const int b = bh / HEADS, h = bh % HEADS;
    __shared__ float p_s[AG][64];
    __shared__ float v_s[64][68];
    const int tid = threadIdx.x;
    const int dp = tid & 31;        // owns d = dp and d = dp+32
    const int ag = tid >> 5;        // 0..7 : agents ag, ag+8, ...

    float acc0[7], acc1[7];
#pragma unroll
    for (int i = 0; i < 7; i++) { acc0[i] = 0.f; acc1[i] = 0.f; }

    for (int n0 = 0; n0 < Nn; n0 += 64) {
        __syncthreads();
        for (int f = tid; f < AG * 64; f += 256) {
            int a = f >> 6, nn = f & 63;
            p_s[a][nn] = g_attn1[((size_t)bh * AG + a) * Nn + n0 + nn];
        }
        for (int f = tid; f < 64 * 16; f += 256) {
            int row = f >> 4, c4 = (f & 15) * 4;
            *(float4*)&v_s[row][c4] =
                *(const float4*)&g_kv[((size_t)(b * Nn + n0 + row)) * (2 * Cc) + Cc + h * Dd + c4];
        }
        __syncthreads();
        for (int nn = 0; nn < 64; nn++) {
            float v0 = v_s[nn][dp];
            float v1 = v_s[nn][dp + 32];
#pragma unroll
            for (int i = 0; i < 7; i++) {
                int a = ag + 8 * i;
                if (a < AG) {
                    float pp = p_s[a][nn];
                    acc0[i] = fmaf(pp, v0, acc0[i]);
                    acc1[i] = fmaf(pp, v1, acc1[i]);
                }
            }
        }
    }
#pragma unroll
    for (int i = 0; i < 7; i++) {
        int a = ag + 8 * i;
        if (a < AG) {
            g_agentv[((size_t)bh * AG + a) * Dd + dp] = acc0[i];
            g_agentv[((size_t)bh * AG + a) * Dd + dp + 32] = acc1[i];
        }
    }
}

// ---------------- stage 2: per (b,h,n) row softmax over 49 agents ----------------
__global__ __launch_bounds__(64) void stage2_kernel()
{
    const int bh = blockIdx.y;
    const int b = bh / HEADS, h = bh % HEADS;
    const int tid = threadIdx.x;
    const int n = blockIdx.x * 64 + tid;
    __shared__ float a4s[AG][64];
    __shared__ float avs[AG][64];
    __shared__ float sc[AG][64];

    for (int f = tid; f < AG * 64; f += 64) {
        int a = f >> 6, d = f & 63;
        a4s[a][d] = g_agent[((size_t)b * AG + a) * Cc + h * Dd + d] * 0.125f;
        avs[a][d] = g_agentv[((size_t)bh * AG + a) * Dd + d];
    }
    __syncthreads();

    float4 qv[16];
    const float* qrow = g_q + ((size_t)(b * Nn + n)) * Cc + h * Dd;
#pragma unroll
    for (int i = 0; i < 16; i++) qv[i] = *(const float4*)&qrow[i * 4];

    const float* bq = g_bias_qa + ((size_t)(h * Nn + n)) * AG;
    float m = -1e30f;
    for (int a = 0; a < AG; a++) {
        float dot = 0.f;
#pragma unroll
        for (int d4 = 0; d4 < 16; d4++) {
            float4 av = *(const float4*)&a4s[a][d4 * 4];
            dot = fmaf(qv[d4].x, av.x, dot);
            dot = fmaf(qv[d4].y, av.y, dot);
            dot = fmaf(qv[d4].z, av.z, dot);
            dot = fmaf(qv[d4].w, av.w, dot);
        }
        float s = dot + bq[a];
        sc[a][tid] = s;
        m = fmaxf(m, s);
    }
    float sum = 0.f;
    for (int a = 0; a < AG; a++) {
        float e = __expf(sc[a][tid] - m);
        sc[a][tid] = e;
        sum += e;
    }
    float inv = 1.0f / sum;

    float4 acc[16];
#pragma unroll
    for (int i = 0; i < 16; i++) acc[i] = make_float4(0.f, 0.f, 0.f, 0.f);
    for (int a = 0; a < AG; a++) {
        float pp = sc[a][tid];
#pragma unroll
        for (int d4 = 0; d4 < 16; d4++) {
            float4 av = *(const float4*)&avs[a][d4 * 4];
            acc[d4].x = fmaf(pp, av.x, acc[d4].x);
            acc[d4].y = fmaf(pp, av.y, acc[d4].y);
            acc[d4].z = fmaf(pp, av.z, acc[d4].z);
            acc[d4].w = fmaf(pp, av.w, acc[d4].w);
        }
    }
    float* orow = g_acc + ((size_t)(b * Nn + n)) * Cc + h * Dd;
#pragma unroll
    for (int d4 = 0; d4 < 16; d4++) {
        acc[d4].x *= inv; acc[d4].y *= inv; acc[d4].z *= inv; acc[d4].w *= inv;
        *(float4*)&orow[d4 * 4] = acc[d4];
    }
}

// ---------------- depthwise 3x3 conv on v, added into g_acc ----------------
__global__ __launch_bounds__(256) void dwc_kernel(
    const float* __restrict__ w, const float* __restrict__ bias)
{
    size_t idx = (size_t)blockIdx.x * 256 + threadIdx.x;  // < B*Nn*Cc (exact)
    int c = (int)(idx % Cc);
    size_t bnv = idx / Cc;
    int n = (int)(bnv % Nn);
    int b = (int)(bnv / Nn);
    int y = n / Hpix, x = n % Hpix;
    float s = bias[c];
#pragma unroll
    for (int dy = -1; dy <= 1; dy++) {
        int yy = y + dy;
        if (yy < 0 || yy >= Hpix) continue;
#pragma unroll
        for (int dx = -1; dx <= 1; dx++) {
            int xx = x + dx;
            if (xx < 0 || xx >= Hpix) continue;
            s = fmaf(g_kv[((size_t)(b * Nn + yy * Hpix + xx)) * (2 * Cc) + Cc + c],
                     w[c * 9 + (dy + 1) * 3 + (dx + 1)], s);
        }
    }
    g_acc[idx] += s;
}

// ---------------- launch ----------------
extern "C" void kernel_launch(void* const* d_in, const int* in_sizes, int n_in,
                              void* d_out, int out_size)
{
    const float* x      = (const float*)d_in[0];
    const float* q_w    = (const float*)d_in[1];
    const float* kv_w   = (const float*)d_in[2];
    const float* proj_w = (const float*)d_in[3];
    const float* proj_b = (const float*)d_in[4];
    const float* dwc_w  = (const float*)d_in[5];
    const float* dwc_b  = (const float*)d_in[6];
    const float* an_b   = (const float*)d_in[7];
    const float* na_b   = (const float*)d_in[8];
    const float* ah     = (const float*)d_in[9];
    const float* aw     = (const float*)d_in[10];
    const float* ha     = (const float*)d_in[11];
    const float* wa     = (const float*)d_in[12];

    float *qp, *kvp, *accp;
    cudaGetSymbolAddress((void**)&qp, g_q);
    cudaGetSymbolAddress((void**)&kvp, g_kv);
    cudaGetSymbolAddress((void**)&accp, g_acc);

    const int M = Bn * Nn;  // 50176

    gemm_kernel<<<dim3(Cc / 64, M / 128), 256>>>(x, q_w, qp, M, Cc, Cc, nullptr);
    gemm_kernel<<<dim3(2 * Cc / 64, M / 128), 256>>>(x, kv_w, kvp, M, Cc, 2 * Cc, nullptr);
    pool_kernel<<<(Bn * AG * Cc) / 256, 256>>>();
    biasak_kernel<<<(HEADS * AG * Nn) / 256, 256>>>(an_b, ah, aw);
    biasqa_kernel<<<(HEADS * Nn * AG) / 256, 256>>>(na_b, ha, wa);
    scores1_kernel<<<Bn * HEADS, 256>>>();
    softmax1_kernel<<<Bn * HEADS * AG, 256>>>();
    agentv_kernel<<<Bn * HEADS, 256>>>();
    stage2_kernel<<<dim3(Nn / 64, Bn * HEADS), 64>>>();
    dwc_kernel<<<(int)(((size_t)Bn * Nn * Cc) / 256), 256>>>(dwc_w, dwc_b);
    gemm_kernel<<<dim3(Cc / 64, M / 128), 256>>>(accp, proj_w, (float*)d_out, M, Cc, Cc, proj_b);
}

// round 2
// speedup vs baseline: 1.7934x; 1.7934x over previous
#include <cuda_runtime.h>
#include <cstdint>
#include <math.h>

#define Bn 16
#define Nn 3136
#define Cc 512
#define Hpix 56
#define HEADS 8
#define Dd 64
#define AG 49

// ---------------- scratch (device globals; no allocation allowed) ----------------
__device__ float g_q[(size_t)Bn * Nn * Cc];            //  98 MB  (b,n,c)
__device__ float g_kv[(size_t)Bn * Nn * 2 * Cc];       // 196 MB  (b,n,2c) k=[0,512) v=[512,1024)
__device__ float g_agent[(size_t)Bn * AG * Cc];        // (b,a,c)
__device__ float g_bias_ak[(size_t)HEADS * AG * Nn];   // (h,a,n)
__device__ float g_bias_qa[(size_t)HEADS * Nn * AG];   // (h,n,a)
__device__ float g_attn1[(size_t)Bn * HEADS * AG * Nn];// (b,h,a,n)  ~79 MB
__device__ float g_agentv[(size_t)Bn * HEADS * AG * Dd];
__device__ float g_acc[(size_t)Bn * Nn * Cc];          // attention out + dwc

// ---------------- tf32 tensor-core GEMM: C[M,Nc] = A[M,K] @ W[K,Nc] (+bias) ------
// BM=128 BN=128 BK=32, 256 threads (4x2 warps, warp tile 32x64), cp.async double buf.
// A smem stride 36 floats (144B, 16B aligned, frag-conflict-free: bank=4r+c distinct)
// B smem stride 132 floats (528B aligned, bank=4k+n distinct)
#define AS_STRIDE 36
#define BS_STRIDE 132
#define AS_BUF (128 * AS_STRIDE)   // 4608 floats
#define BS_BUF (32 * BS_STRIDE)    // 4224 floats
#define GEMM_SMEM ((2 * AS_BUF + 2 * BS_BUF) * 4)  // 70656 bytes

__device__ __forceinline__ uint32_t f2tf32(float f) {
    uint32_t r;
    asm("cvt.rna.tf32.f32 %0, %1;" : "=r"(r) : "f"(f));
    return r;
}

__global__ __launch_bounds__(256) void gemm_tc(
    const float* __restrict__ A, const float* __restrict__ W,
    float* __restrict__ Cout, int M, int K, int Nc, const float* __restrict__ bias)
{
    extern __shared__ float sm[];
    float* As = sm;                 // 2 x 128 x 36
    float* Bs = sm + 2 * AS_BUF;    // 2 x 32 x 132

    const int tid = threadIdx.x;
    const int bm = blockIdx.y * 128;
    const int bn = blockIdx.x * 128;
    const int w = tid >> 5, lane = tid & 31;
    const int wm = w & 3, wn = w >> 2;
    const int g = lane >> 2, c = lane & 3;

    float acc[2][8][4];
#pragma unroll
    for (int i = 0; i < 2; i++)
#pragma unroll
        for (int j = 0; j < 8; j++)
#pragma unroll
            for (int t = 0; t < 4; t++) acc[i][j][t] = 0.f;

    // ---- cp.async tile loaders ----
    auto issueA = [&](int buf, int k0) {
        float* dst = As + buf * AS_BUF;
#pragma unroll
        for (int i = 0; i < 4; i++) {
            int idx = tid + 256 * i;          // 1024 float4s = 128 rows x 8
            int m = idx >> 3, kc = (idx & 7) * 4;
            uint32_t s = (uint32_t)__cvta_generic_to_shared(dst + m * AS_STRIDE + kc);
            const float* gp = A + (size_t)(bm + m) * K + k0 + kc;
            asm volatile("cp.async.cg.shared.global [%0], [%1], 16;\n" :: "r"(s), "l"(gp));
        }
    };
    auto issueB = [&](int buf, int k0) {
        float* dst = Bs + buf * BS_BUF;
#pragma unroll
        for (int i = 0; i < 4; i++) {
            int idx = tid + 256 * i;          // 1024 float4s = 32 rows x 32
            int k = idx >> 5, nc = (idx & 31) * 4;
            uint32_t s = (uint32_t)__cvta_generic_to_shared(dst + k * BS_STRIDE + nc);
            const float* gp = W + (size_t)(k0 + k) * Nc + bn + nc;
            asm volatile("cp.async.cg.shared.global [%0], [%1], 16;\n" :: "r"(s), "l"(gp));
        }
    };

    issueA(0, 0);
    issueB(0, 0);
    asm volatile("cp.async.commit_group;\n");

    const int KT = K / 32;
    for (int kt = 0; kt < KT; kt++) {
        asm volatile("cp.async.wait_group 0;\n");
        __syncthreads();
        if (kt + 1 < KT) {
            issueA((kt + 1) & 1, (kt + 1) * 32);
            issueB((kt + 1) & 1, (kt + 1) * 32);
            asm volatile("cp.async.commit_group;\n");
        }
        const float* Ab = As + (kt & 1) * AS_BUF;
        const float* Bb = Bs + (kt & 1) * BS_BUF;

#pragma unroll
        for (int ks = 0; ks < 4; ks++) {
            const int k = ks * 8;
            uint32_t af[2][4];
#pragma unroll
            for (int i = 0; i < 2; i++) {
                int mb = wm * 32 + i * 16;
                af[i][0] = f2tf32(Ab[(mb + g)     * AS_STRIDE + k + c]);
                af[i][1] = f2tf32(Ab[(mb + g + 8) * AS_STRIDE + k + c]);
                af[i][2] = f2tf32(Ab[(mb + g)     * AS_STRIDE + k + c + 4]);
                af[i][3] = f2tf32(Ab[(mb + g + 8) * AS_STRIDE + k + c + 4]);
            }
#pragma unroll
            for (int j = 0; j < 8; j++) {
                int nb = wn * 64 + j * 8;
                uint32_t b0 = f2tf32(Bb[(k + c)     * BS_STRIDE + nb + g]);
                uint32_t b1 = f2tf32(Bb[(k + c + 4) * BS_STRIDE + nb + g]);
#pragma unroll
                for (int i = 0; i < 2; i++) {
                    asm volatile(
                        "mma.sync.aligned.m16n8k8.row.col.f32.tf32.tf32.f32 "
                        "{%0,%1,%2,%3}, {%4,%5,%6,%7}, {%8,%9}, {%0,%1,%2,%3};"
                        : "+f"(acc[i][j][0]), "+f"(acc[i][j][1]),
                          "+f"(acc[i][j][2]), "+f"(acc[i][j][3])
                        : "r"(af[i][0]), "r"(af[i][1]), "r"(af[i][2]), "r"(af[i][3]),
                          "r"(b0), "r"(b1));
                }
            }
        }
        __syncthreads();
    }

    // ---- epilogue: float2 stores, optional bias ----
#pragma unroll
    for (int j = 0; j < 8; j++) {
        int col = bn + wn * 64 + j * 8 + 2 * c;
        float bx = 0.f, by = 0.f;
        if (bias) { bx = bias[col]; by = bias[col + 1]; }
#pragma unroll
        for (int i = 0; i < 2; i++) {
            int r0 = bm + wm * 32 + i * 16 + g;
            float2 v0 = make_float2(acc[i][j][0] + bx, acc[i][j][1] + by);
            float2 v1 = make_float2(acc[i][j][2] + bx, acc[i][j][3] + by);
            *(float2*)&Cout[(size_t)r0 * Nc + col] = v0;
            *(float2*)&Cout[(size_t)(r0 + 8) * Nc + col] = v1;
        }
    }
}

// ---------------- 8x8 mean pool: agent[b,a,c] ----------------
__global__ __launch_bounds__(256) void pool_kernel()
{
    int idx = blockIdx.x * 256 + threadIdx.x;   // < B*AG*C (exact)
    int c = idx % Cc;
    int ba = idx / Cc;
    int a = ba % AG;
    int b = ba / AG;
    int py = a / 7, px = a % 7;
    float s = 0.f;
#pragma unroll
    for (int dy = 0; dy < 8; dy++) {
        int n_base = (py * 8 + dy) * Hpix + px * 8;
#pragma unroll
        for (int dx = 0; dx < 8; dx++)
            s += g_q[((size_t)b * Nn + n_base + dx) * Cc + c];
    }
    g_agent[idx] = s * (1.0f / 64.0f);
}

// ---------------- bilinear 7x7 -> 56x56 (half-pixel centers, edge clamp) ----------
__device__ __forceinline__ float bilerp7(const float* __restrict__ t, int y, int x)
{
    float sy = (y + 0.5f) * 0.125f - 0.5f;
    float sx = (x + 0.5f) * 0.125f - 0.5f;
    int y0f = (int)floorf(sy);
    int x0f = (int)floorf(sx);
    float wy = sy - (float)y0f;
    float wx = sx - (float)x0f;
    int y0 = min(6, max(0, y0f));
    int y1 = min(6, max(0, y0f + 1));
    int x0 = min(6, max(0, x0f));
    int x1 = min(6, max(0, x0f + 1));
    float v00 = t[y0 * 7 + x0], v01 = t[y0 * 7 + x1];
    float v10 = t[y1 * 7 + x0], v11 = t[y1 * 7 + x1];
    float top = v00 + wx * (v01 - v00);
    float bot = v10 + wx * (v11 - v10);
    return top + wy * (bot - top);
}

__global__ __launch_bounds__(256) void biasak_kernel(
    const float* __restrict__ an, const float* __restrict__ ah, const float* __restrict__ aw)
{
    int idx = blockIdx.x * 256 + threadIdx.x;   // < H*AG*Nn (exact)
    int n = idx % Nn;
    int haa = idx / Nn;                          // h*49+a
    int y = n / Hpix, x = n % Hpix;
    g_bias_ak[idx] = bilerp7(an + haa * 49, y, x) + ah[haa] + aw[haa];
}

__global__ __launch_bounds__(256) void biasqa_kernel(
    const float* __restrict__ na, const float* __restrict__ ha, const float* __restrict__ wa)
{
    int idx = blockIdx.x * 256 + threadIdx.x;   // < H*Nn*AG (exact)
    int a = idx % AG;
    int hn = idx / AG;
    int n = hn % Nn;
    int h = hn / Nn;
    int y = n / Hpix, x = n % Hpix;
    int haa = h * AG + a;
    g_bias_qa[idx] = bilerp7(na + haa * 49, y, x) + ha[haa] + wa[haa];
}

// ---------------- stage 1 scores: s1[b,h,a,n] = (agent*scale)·k + bias ------------
__global__ __launch_bounds__(256) void scores1_kernel()
{
    const int bh = blockIdx.x;
    const int b = bh / HEADS, h = bh % HEADS;
    __shared__ float a_s[52][64];     // agents (padded to 52, zero-filled)
    __shared__ float ks[128][68];     // 272B row stride -> conflict-free f4 reads
    const int tid = threadIdx.x;

    for (int f = tid; f < 52 * 64; f += 256) {
        int a = f >> 6, d = f & 63;
        a_s[a][d] = (a < AG) ? g_agent[((size_t)b * AG + a) * Cc + h * Dd + d] * 0.125f : 0.f;
    }
    const int nt = tid & 31;
    const int at0 = tid >> 5;

    for (int n0 = 0; n0 < Nn; n0 += 128) {
        __syncthreads();
        for (int f = tid; f < 128 * 16; f += 256) {
            int row = f >> 4, c4 = (f & 15) * 4;
            *(float4*)&ks[row][c4] =
                *(const float4*)&g_kv[((size_t)(b * Nn + n0 + row)) * (2 * Cc) + h * Dd + c4];
        }
        __syncthreads();
        for (int at = at0; at < 13; at += 8) {
            int a0 = at * 4;
            float acc[4][4];
#pragma unroll
            for (int i = 0; i < 4; i++)
#pragma unroll
                for (int j = 0; j < 4; j++) acc[i][j] = 0.f;
#pragma unroll 4
            for (int d4 = 0; d4 < 16; d4++) {
                float4 av[4], kf[4];
#pragma unroll
                for (int i = 0; i < 4; i++) av[i] = *(const float4*)&a_s[a0 + i][d4 * 4];
#pragma unroll
                for (int j = 0; j < 4; j++) kf[j] = *(const float4*)&ks[nt + 32 * j][d4 * 4];
#pragma unroll
                for (int i = 0; i < 4; i++)
#pragma unroll
                    for (int j = 0; j < 4; j++) {
                        acc[i][j] = fmaf(av[i].x, kf[j].x, acc[i][j]);
                        acc[i][j] = fmaf(av[i].y, kf[j].y, acc[i][j]);
                        acc[i][j] = fmaf(av[i].z, kf[j].z, acc[i][j]);
                        acc[i][j] = fmaf(av[i].w, kf[j].w, acc[i][j]);
                    }
            }
#pragma unroll
            for (int i = 0; i < 4; i++) {
                int a = a0 + i;
                if (a < AG) {
#pragma unroll
                    for (int j = 0; j < 4; j++) {
                        int n = n0 + nt + 32 * j;
                        g_attn1[((size_t)bh * AG + a) * Nn + n] =
                            acc[i][j] + g_bias_ak[((size_t)(h * AG + a)) * Nn + n];
                    }
                }
            }
        }
    }
}

// ---------------- softmax over n (row length 3136) ----------------
__global__ __launch_bounds__(256) void softmax1_kernel()
{
    float* p = g_attn1 + (size_t)blockIdx.x * Nn;
    const int tid = threadIdx.x;
    float vals[13];
    float m = -1e30f;
#pragma unroll
    for (int i = 0; i < 13; i++) {
        int n = tid + 256 * i;
        vals[i] = (n < Nn) ? p[n] : -1e30f;
        m = fmaxf(m, vals[i]);
    }
    __shared__ float red[8];
#pragma unroll
    for (int o = 16; o > 0; o >>= 1) m = fmaxf(m, __shfl_xor_sync(0xffffffffu, m, o));
    if ((tid & 31) == 0) red[tid >> 5] = m;
    __syncthreads();
    float bm = red[0];
#pragma unroll
    for (int i = 1; i < 8; i++) bm = fmaxf(bm, red[i]);
    __syncthreads();

    float s = 0.f;
#pragma unroll
    for (int i = 0; i < 13; i++) {
        float e = __expf(vals[i] - bm);
        vals[i] = e;
        s += e;
    }
#pragma unroll
    for (int o = 16; o > 0; o >>= 1) s += __shfl_xor_sync(0xffffffffu, s, o);
    if ((tid & 31) == 0) red[tid >> 5] = s;
    __syncthreads();
    float tot = 0.f;
#pragma unroll
    for (int i = 0; i < 8; i++) tot += red[i];
    float inv = 1.0f / tot;
#pragma unroll
    for (int i = 0; i < 13; i++) {
        int n = tid + 256 * i;
        if (n < Nn) p[n] = vals[i] * inv;
    }
}

// ---------------- agent_v[b,h,a,d] = attn1 @ v ----------------
__global__ __launch_bounds__(256) void agentv_kernel()
{
    const int bh = blockIdx.x;
    const int b = bh / HEADS, h = bh % HEADS;
    __shared__ float p_s[AG][64];
    __shared__ float v_s[64][68];
    const int tid = threadIdx.x;
    const int dp = tid & 31;        // owns d = dp and d = dp+32
    const int ag = tid >> 5;        // 0..7 : agents ag, ag+8, ...

    float acc0[7], acc1[7];
#pragma unroll
    for (int i = 0; i < 7; i++) { acc0[i] = 0.f; acc1[i] = 0.f; }

    for (int n0 = 0; n0 < Nn; n0 += 64) {
        __syncthreads();
        for (int f = tid; f < AG * 64; f += 256) {
            int a = f >> 6, nn = f & 63;
            p_s[a][nn] = g_attn1[((size_t)bh * AG + a) * Nn + n0 + nn];
        }
        for (int f = tid; f < 64 * 16; f += 256) {
            int row = f >> 4, c4 = (f & 15) * 4;
            *(float4*)&v_s[row][c4] =
                *(const float4*)&g_kv[((size_t)(b * Nn + n0 + row)) * (2 * Cc) + Cc + h * Dd + c4];
        }
        __syncthreads();
        for (int nn = 0; nn < 64; nn++) {
            float v0 = v_s[nn][dp];
            float v1 = v_s[nn][dp + 32];
#pragma unroll
            for (int i = 0; i < 7; i++) {
                int a = ag + 8 * i;
                if (a < AG) {
                    float pp = p_s[a][nn];
                    acc0[i] = fmaf(pp, v0, acc0[i]);
                    acc1[i] = fmaf(pp, v1, acc1[i]);
                }
            }
        }
    }
#pragma unroll
    for (int i = 0; i < 7; i++) {
        int a = ag + 8 * i;
        if (a < AG) {
            g_agentv[((size_t)bh * AG + a) * Dd + dp] = acc0[i];
            g_agentv[((size_t)bh * AG + a) * Dd + dp + 32] = acc1[i];
        }
    }
}

// ---------------- stage 2: per (b,h,n) row softmax over 49 agents ----------------
__global__ __launch_bounds__(64) void stage2_kernel()
{
    const int bh = blockIdx.y;
    const int b = bh / HEADS, h = bh % HEADS;
    const int tid = threadIdx.x;
    const int n = blockIdx.x * 64 + tid;
    __shared__ float a4s[AG][64];
    __shared__ float avs[AG][64];
    __shared__ float sc[AG][64];

    for (int f = tid; f < AG * 64; f += 64) {
        int a = f >> 6, d = f & 63;
        a4s[a][d] = g_agent[((size_t)b * AG + a) * Cc + h * Dd + d] * 0.125f;
        avs[a][d] = g_agentv[((size_t)bh * AG + a) * Dd + d];
    }
    __syncthreads();

    float4 qv[16];
    const float* qrow = g_q + ((size_t)(b * Nn + n)) * Cc + h * Dd;
#pragma unroll
    for (int i = 0; i < 16; i++) qv[i] = *(const float4*)&qrow[i * 4];

    const float* bq = g_bias_qa + ((size_t)(h * Nn + n)) * AG;
    float m = -1e30f;
    for (int a = 0; a < AG; a++) {
        float dot = 0.f;
#pragma unroll
        for (int d4 = 0; d4 < 16; d4++) {
            float4 av = *(const float4*)&a4s[a][d4 * 4];
            dot = fmaf(qv[d4].x, av.x, dot);
            dot = fmaf(qv[d4].y, av.y, dot);
            dot = fmaf(qv[d4].z, av.z, dot);
            dot = fmaf(qv[d4].w, av.w, dot);
        }
        float s = dot + bq[a];
        sc[a][tid] = s;
        m = fmaxf(m, s);
    }
    float sum = 0.f;
    for (int a = 0; a < AG; a++) {
        float e = __expf(sc[a][tid] - m);
        sc[a][tid] = e;
        sum += e;
    }
    float inv = 1.0f / sum;

    float4 acc[16];
#pragma unroll
    for (int i = 0; i < 16; i++) acc[i] = make_float4(0.f, 0.f, 0.f, 0.f);
    for (int a = 0; a < AG; a++) {
        float pp = sc[a][tid];
#pragma unroll
        for (int d4 = 0; d4 < 16; d4++) {
            float4 av = *(const float4*)&avs[a][d4 * 4];
            acc[d4].x = fmaf(pp, av.x, acc[d4].x);
            acc[d4].y = fmaf(pp, av.y, acc[d4].y);
            acc[d4].z = fmaf(pp, av.z, acc[d4].z);
            acc[d4].w = fmaf(pp, av.w, acc[d4].w);
        }
    }
    float* orow = g_acc + ((size_t)(b * Nn + n)) * Cc + h * Dd;
#pragma unroll
    for (int d4 = 0; d4 < 16; d4++) {
        acc[d4].x *= inv; acc[d4].y *= inv; acc[d4].z *= inv; acc[d4].w *= inv;
        *(float4*)&orow[d4 * 4] = acc[d4];
    }
}

// ---------------- depthwise 3x3 conv on v, added into g_acc ----------------
__global__ __launch_bounds__(256) void dwc_kernel(
    const float* __restrict__ w, const float* __restrict__ bias)
{
    size_t idx = (size_t)blockIdx.x * 256 + threadIdx.x;  // < B*Nn*Cc (exact)
    int c = (int)(idx % Cc);
    size_t bnv = idx / Cc;
    int n = (int)(bnv % Nn);
    int b = (int)(bnv / Nn);
    int y = n / Hpix, x = n % Hpix;
    float s = bias[c];
#pragma unroll
    for (int dy = -1; dy <= 1; dy++) {
        int yy = y + dy;
        if (yy < 0 || yy >= Hpix) continue;
#pragma unroll
        for (int dx = -1; dx <= 1; dx++) {
            int xx = x + dx;
            if (xx < 0 || xx >= Hpix) continue;
            s = fmaf(g_kv[((size_t)(b * Nn + yy * Hpix + xx)) * (2 * Cc) + Cc + c],
                     w[c * 9 + (dy + 1) * 3 + (dx + 1)], s);
        }
    }
    g_acc[idx] += s;
}

// ---------------- launch ----------------
extern "C" void kernel_launch(void* const* d_in, const int* in_sizes, int n_in,
                              void* d_out, int out_size)
{
    const float* x      = (const float*)d_in[0];
    const float* q_w    = (const float*)d_in[1];
    const float* kv_w   = (const float*)d_in[2];
    const float* proj_w = (const float*)d_in[3];
    const float* proj_b = (const float*)d_in[4];
    const float* dwc_w  = (const float*)d_in[5];
    const float* dwc_b  = (const float*)d_in[6];
    const float* an_b   = (const float*)d_in[7];
    const float* na_b   = (const float*)d_in[8];
    const float* ah     = (const float*)d_in[9];
    const float* aw     = (const float*)d_in[10];
    const float* ha     = (const float*)d_in[11];
    const float* wa     = (const float*)d_in[12];

    float *qp, *kvp, *accp;
    cudaGetSymbolAddress((void**)&qp, g_q);
    cudaGetSymbolAddress((void**)&kvp, g_kv);
    cudaGetSymbolAddress((void**)&accp, g_acc);

    cudaFuncSetAttribute(gemm_tc, cudaFuncAttributeMaxDynamicSharedMemorySize, GEMM_SMEM);

    const int M = Bn * Nn;  // 50176

    gemm_tc<<<dim3(Cc / 128, M / 128), 256, GEMM_SMEM>>>(x, q_w, qp, M, Cc, Cc, nullptr);
    gemm_tc<<<dim3(2 * Cc / 128, M / 128), 256, GEMM_SMEM>>>(x, kv_w, kvp, M, Cc, 2 * Cc, nullptr);
    pool_kernel<<<(Bn * AG * Cc) / 256, 256>>>();
    biasak_kernel<<<(HEADS * AG * Nn) / 256, 256>>>(an_b, ah, aw);
    biasqa_kernel<<<(HEADS * Nn * AG) / 256, 256>>>(na_b, ha, wa);
    scores1_kernel<<<Bn * HEADS, 256>>>();
    softmax1_kernel<<<Bn * HEADS * AG, 256>>>();
    agentv_kernel<<<Bn * HEADS, 256>>>();
    stage2_kernel<<<dim3(Nn / 64, Bn * HEADS), 64>>>();
    dwc_kernel<<<(int)(((size_t)Bn * Nn * Cc) / 256), 256>>>(dwc_w, dwc_b);
    gemm_tc<<<dim3(Cc / 128, M / 128), 256, GEMM_SMEM>>>(accp, proj_w, (float*)d_out, M, Cc, Cc, proj_b);
}

// round 5
// speedup vs baseline: 2.4809x; 1.3833x over previous
#include <cuda_runtime.h>
#include <cuda_fp16.h>
#include <cstdint>
#include <math.h>

#define Bn 16
#define Nn 3136
#define Cc 512
#define Hpix 56
#define HEADS 8
#define Dd 64
#define AG 49

// ---------------- scratch (device globals; no allocation allowed) ----------------
__device__ float g_q[(size_t)Bn * Nn * Cc];            // (b,n,c)
__device__ float g_kv[(size_t)Bn * Nn * 2 * Cc];       // (b,n,2c) k=[0,512) v=[512,1024)
__device__ float g_agent[(size_t)Bn * AG * Cc];        // (b,a,c)
__device__ float g_bias_ak[(size_t)HEADS * AG * Nn];   // (h,a,n)
__device__ float g_bias_qa[(size_t)HEADS * Nn * AG];   // (h,n,a)
__device__ float g_attn1[(size_t)Bn * HEADS * AG * Nn];// (b,h,a,n)
__device__ float g_agentv[(size_t)Bn * HEADS * AG * Dd];
__device__ float g_acc[(size_t)Bn * Nn * Cc];          // stage2 attention out (fp32)
__device__ __half g_xh[(size_t)Bn * Nn * Cc];          // x in fp16
__device__ __half g_acch[(size_t)Bn * Nn * Cc];        // (attn out + dwc) in fp16
// transposed fp16 weights: qT [512x512] | kvT [1024x512] | projT [512x512], K-major
__device__ __half g_wTh[(size_t)2048 * 512];
#define WT_Q 0
#define WT_KV (512 * 512)
#define WT_PROJ (512 * 512 + 1024 * 512)

// ---------------- fp16 tensor-core GEMM: C[M,Nc] = A[M,K] @ Bt[Nc,K]^T (+bias) ----
// BM=128 BN=128 BK=64, 256 threads (4x2 warps, warp tile 32x64), 3-stage cp.async.
// smem stride 72 halves: frag LDS bank = 4g + c (+const) -> conflict-free.
#define GAS 72
#define GBUF (128 * GAS)          // halves per operand per stage
#define GSTAGES 3
#define GT_SMEM (GSTAGES * 2 * GBUF * 2)   // 110592 bytes

__global__ __launch_bounds__(256, 2) void gemm_h(
    const __half* __restrict__ A, const __half* __restrict__ Bt,
    float* __restrict__ Cout, int M, int K, int Nc, const float* __restrict__ bias)
{
    extern __shared__ __half smh[];
    __half* smA = smh;                       // [3][128*72]
    __half* smB = smh + GSTAGES * GBUF;      // [3][128*72]
    const int tid = threadIdx.x;
    const int wid = tid >> 5, lane = tid & 31;
    const int wm = wid & 3, wn = wid >> 2;
    const int g = lane >> 2, cq = lane & 3;
    const int bm = blockIdx.y * 128, bn = blockIdx.x * 128;

    float acc[2][8][4];
#pragma unroll
    for (int i = 0; i < 2; i++)
#pragma unroll
        for (int j = 0; j < 8; j++)
#pragma unroll
            for (int t = 0; t < 4; t++) acc[i][j][t] = 0.f;

    auto loadAB = [&](int s, int kc) {
        const __half* ga = A + (size_t)bm * K + kc * 64;
        const __half* gb = Bt + (size_t)bn * K + kc * 64;
        __half* da = smA + s * GBUF;
        __half* db = smB + s * GBUF;
#pragma unroll
        for (int i = 0; i < 4; i++) {
            int idx = i * 256 + tid;        // 1024 = 128 rows x 8 segs
            int row = idx >> 3, seg = idx & 7;
            uint32_t pa = (uint32_t)__cvta_generic_to_shared(da + row * GAS + seg * 8);
            uint32_t pb = (uint32_t)__cvta_generic_to_shared(db + row * GAS + seg * 8);
            asm volatile("cp.async.cg.shared.global [%0], [%1], 16;\n"
                         :: "r"(pa), "l"(ga + (size_t)row * K + seg * 8));
            asm volatile("cp.async.cg.shared.global [%0], [%1], 16;\n"
                         :: "r"(pb), "l"(gb + (size_t)row * K + seg * 8));
        }
        asm volatile("cp.async.commit_group;\n");
    };

    const int KT = K / 64;   // 8
    loadAB(0, 0);
    loadAB(1, 1);
    loadAB(2, 2);

    for (int c = 0; c < KT; c++) {
        int s = c % GSTAGES;
        if (c + 2 < KT)      asm volatile("cp.async.wait_group 2;\n");
        else if (c + 1 < KT) asm volatile("cp.async.wait_group 1;\n");
        else                 asm volatile("cp.async.wait_group 0;\n");
        __syncthreads();
        const __half* Ab = smA + s * GBUF + (wm * 32) * GAS;
        const __half* Bb = smB + s * GBUF + (wn * 64) * GAS;
#pragma unroll
        for (int ks = 0; ks < 4; ks++) {
            const int k = ks * 16 + 2 * cq;
            uint32_t a[2][4];
#pragma unroll
            for (int i = 0; i < 2; i++) {
                int r = i * 16 + g;
                a[i][0] = *(const uint32_t*)&Ab[r * GAS + k];
                a[i][1] = *(const uint32_t*)&Ab[(r + 8) * GAS + k];
                a[i][2] = *(const uint32_t*)&Ab[r * GAS + k + 8];
                a[i][3] = *(const uint32_t*)&Ab[(r + 8) * GAS + k + 8];
            }
#pragma unroll
            for (int j = 0; j < 8; j++) {
                uint32_t b0 = *(const uint32_t*)&Bb[(j * 8 + g) * GAS + k];
                uint32_t b1 = *(const uint32_t*)&Bb[(j * 8 + g) * GAS + k + 8];
#pragma unroll
                for (int i = 0; i < 2; i++) {
                    asm volatile(
                        "mma.sync.aligned.m16n8k16.row.col.f32.f16.f16.f32 "
                        "{%0,%1,%2,%3}, {%4,%5,%6,%7}, {%8,%9}, {%0,%1,%2,%3};"
                        : "+f"(acc[i][j][0]), "+f"(acc[i][j][1]),
                          "+f"(acc[i][j][2]), "+f"(acc[i][j][3])
                        : "r"(a[i][0]), "r"(a[i][1]), "r"(a[i][2]), "r"(a[i][3]),
                          "r"(b0), "r"(b1));
                }
            }
        }
        __syncthreads();
        if (c + GSTAGES < KT) loadAB(s, c + GSTAGES);
    }

    // epilogue: float2 stores, optional bias
#pragma unroll
    for (int j = 0; j < 8; j++) {
        int col = bn + wn * 64 + j * 8 + 2 * cq;
        float bx = 0.f, by = 0.f;
        if (bias) { bx = bias[col]; by = bias[col + 1]; }
#pragma unroll
        for (int i = 0; i < 2; i++) {
            int r0 = bm + wm * 32 + i * 16 + g;
            *(float2*)&Cout[(size_t)r0 * Nc + col] =
                make_float2(acc[i][j][0] + bx, acc[i][j][1] + by);
            *(float2*)&Cout[(size_t)(r0 + 8) * Nc + col] =
                make_float2(acc[i][j][2] + bx, acc[i][j][3] + by);
        }
    }
}

// ---------------- weight transpose + fp16 convert: Wt[n][k] = half(W[k][n]) ------
__global__ __launch_bounds__(256) void wtrans_kernel(
    const float* __restrict__ W, __half* __restrict__ Wt, int K, int Nc)
{
    __shared__ float t[32][33];
    int k0 = blockIdx.y * 32, n0 = blockIdx.x * 32;
    int tx = threadIdx.x & 31, ty = threadIdx.x >> 5;   // 32 x 8
#pragma unroll
    for (int i = 0; i < 32; i += 8)
        t[ty + i][tx] = W[(size_t)(k0 + ty + i) * Nc + n0 + tx];
    __syncthreads();
#pragma unroll
    for (int i = 0; i < 32; i += 8)
        Wt[(size_t)(n0 + ty + i) * K + k0 + tx] = __float2half(t[tx][ty + i]);
}

// ---------------- fp32 -> fp16 cast (8 elems/thread, exact grid) -----------------
__global__ __launch_bounds__(256) void xconv_kernel(
    const float* __restrict__ src, __half* __restrict__ dst)
{
    size_t i = (size_t)blockIdx.x * 256 + threadIdx.x;
    float4 v0 = ((const float4*)src)[2 * i];
    float4 v1 = ((const float4*)src)[2 * i + 1];
    __half2 h0 = __floats2half2_rn(v0.x, v0.y);
    __half2 h1 = __floats2half2_rn(v0.z, v0.w);
    __half2 h2 = __floats2half2_rn(v1.x, v1.y);
    __half2 h3 = __floats2half2_rn(v1.z, v1.w);
    uint4 o;
    o.x = *(uint32_t*)&h0;
    o.y = *(uint32_t*)&h1;
    o.z = *(uint32_t*)&h2;
    o.w = *(uint32_t*)&h3;
    ((uint4*)dst)[i] = o;
}

// ---------------- 8x8 mean pool: agent[b,a,c] ----------------
__global__ __launch_bounds__(256) void pool_kernel()
{
    int idx = blockIdx.x * 256 + threadIdx.x;   // < B*AG*C (exact)
    int c = idx % Cc;
    int ba = idx / Cc;
    int a = ba % AG;
    int b = ba / AG;
    int py = a / 7, px = a % 7;
    float s = 0.f;
#pragma unroll
    for (int dy = 0; dy < 8; dy++) {
        int n_base = (py * 8 + dy) * Hpix + px * 8;
#pragma unroll
        for (int dx = 0; dx < 8; dx++)
            s += g_q[((size_t)b * Nn + n_base + dx) * Cc + c];
    }
    g_agent[idx] = s * (1.0f / 64.0f);
}

// ---------------- bilinear 7x7 -> 56x56 (half-pixel centers, edge clamp) ----------
__device__ __forceinline__ float bilerp7(const float* __restrict__ t, int y, int x)
{
    float sy = (y + 0.5f) * 0.125f - 0.5f;
    float sx = (x + 0.5f) * 0.125f - 0.5f;
    int y0f = (int)floorf(sy);
    int x0f = (int)floorf(sx);
    float wy = sy - (float)y0f;
    float wx = sx - (float)x0f;
    int y0 = min(6, max(0, y0f));
    int y1 = min(6, max(0, y0f + 1));
    int x0 = min(6, max(0, x0f));
    int x1 = min(6, max(0, x0f + 1));
    float v00 = t[y0 * 7 + x0], v01 = t[y0 * 7 + x1];
    float v10 = t[y1 * 7 + x0], v11 = t[y1 * 7 + x1];
    float top = v00 + wx * (v01 - v00);
    float bot = v10 + wx * (v11 - v10);
    return top + wy * (bot - top);
}

__global__ __launch_bounds__(256) void biasak_kernel(
    const float* __restrict__ an, const float* __restrict__ ah, const float* __restrict__ aw)
{
    int idx = blockIdx.x * 256 + threadIdx.x;   // < H*AG*Nn (exact)
    int n = idx % Nn;
    int haa = idx / Nn;                          // h*49+a
    int y = n / Hpix, x = n % Hpix;
    g_bias_ak[idx] = bilerp7(an + haa * 49, y, x) + ah[haa] + aw[haa];
}

__global__ __launch_bounds__(256) void biasqa_kernel(
    const float* __restrict__ na, const float* __restrict__ ha, const float* __restrict__ wa)
{
    int idx = blockIdx.x * 256 + threadIdx.x;   // < H*Nn*AG (exact)
    int a = idx % AG;
    int hn = idx / AG;
    int n = hn % Nn;
    int h = hn / Nn;
    int y = n / Hpix, x = n % Hpix;
    int haa = h * AG + a;
    g_bias_qa[idx] = bilerp7(na + haa * 49, y, x) + ha[haa] + wa[haa];
}

// ---------------- stage 1 scores: s1[b,h,a,n] = (agent*scale)·k + bias ------------
// grid (4, Bn*HEADS): x = n-interleave, y = bh. OOB-safe on the 3136 % 128 tail.
__global__ __launch_bounds__(256) void scores1_kernel()
{
    const int bh = blockIdx.y;
    const int b = bh / HEADS, h = bh % HEADS;
    __shared__ float a_s[52][64];
    __shared__ float ks[128][68];
    const int tid = threadIdx.x;

    for (int f = tid; f < 52 * 64; f += 256) {
        int a = f >> 6, d = f & 63;
        a_s[a][d] = (a < AG) ? g_agent[((size_t)b * AG + a) * Cc + h * Dd + d] * 0.125f : 0.f;
    }
    const int nt = tid & 31;
    const int at0 = tid >> 5;

    for (int n0 = blockIdx.x * 128; n0 < Nn; n0 += 512) {
        __syncthreads();
        for (int f = tid; f < 128 * 16; f += 256) {
            int row = f >> 4, c4 = (f & 15) * 4;
            int nr = min(n0 + row, Nn - 1);      // clamp tail
            *(float4*)&ks[row][c4] =
                *(const float4*)&g_kv[((size_t)(b * Nn + nr)) * (2 * Cc) + h * Dd + c4];
        }
        __syncthreads();
        for (int at = at0; at < 13; at += 8) {
            int a0 = at * 4;
            float acc[4][4];
#pragma unroll
            for (int i = 0; i < 4; i++)
#pragma unroll
                for (int j = 0; j < 4; j++) acc[i][j] = 0.f;
#pragma unroll 4
            for (int d4 = 0; d4 < 16; d4++) {
                float4 av[4], kf[4];
#pragma unroll
                for (int i = 0; i < 4; i++) av[i] = *(const float4*)&a_s[a0 + i][d4 * 4];
#pragma unroll
                for (int j = 0; j < 4; j++) kf[j] = *(const float4*)&ks[nt + 32 * j][d4 * 4];
#pragma unroll
                for (int i = 0; i < 4; i++)
#pragma unroll
                    for (int j = 0; j < 4; j++) {
                        acc[i][j] = fmaf(av[i].x, kf[j].x, acc[i][j]);
                        acc[i][j] = fmaf(av[i].y, kf[j].y, acc[i][j]);
                        acc[i][j] = fmaf(av[i].z, kf[j].z, acc[i][j]);
                        acc[i][j] = fmaf(av[i].w, kf[j].w, acc[i][j]);
                    }
            }
#pragma unroll
            for (int i = 0; i < 4; i++) {
                int a = a0 + i;
                if (a < AG) {
#pragma unroll
                    for (int j = 0; j < 4; j++) {
                        int n = n0 + nt + 32 * j;
                        if (n < Nn)
                            g_attn1[((size_t)bh * AG + a) * Nn + n] =
                                acc[i][j] + g_bias_ak[((size_t)(h * AG + a)) * Nn + n];
                    }
                }
            }
        }
    }
}

// ---------------- softmax over n (row length 3136) ----------------
__global__ __launch_bounds__(256) void softmax1_kernel()
{
    float* p = g_attn1 + (size_t)blockIdx.x * Nn;
    const int tid = threadIdx.x;
    float vals[13];
    float m = -1e30f;
#pragma unroll
    for (int i = 0; i < 13; i++) {
        int n = tid + 256 * i;
        vals[i] = (n < Nn) ? p[n] : -1e30f;
        m = fmaxf(m, vals[i]);
    }
    __shared__ float red[8];
#pragma unroll
    for (int o = 16; o > 0; o >>= 1) m = fmaxf(m, __shfl_xor_sync(0xffffffffu, m, o));
    if ((tid & 31) == 0) red[tid >> 5] = m;
    __syncthreads();
    float bm = red[0];
#pragma unroll
    for (int i = 1; i < 8; i++) bm = fmaxf(bm, red[i]);
    __syncthreads();

    float s = 0.f;
#pragma unroll
    for (int i = 0; i < 13; i++) {
        float e = __expf(vals[i] - bm);
        vals[i] = e;
        s += e;
    }
#pragma unroll
    for (int o = 16; o > 0; o >>= 1) s += __shfl_xor_sync(0xffffffffu, s, o);
    if ((tid & 31) == 0) red[tid >> 5] = s;
    __syncthreads();
    float tot = 0.f;
#pragma unroll
    for (int i = 0; i < 8; i++) tot += red[i];
    float inv = 1.0f / tot;
#pragma unroll
    for (int i = 0; i < 13; i++) {
        int n = tid + 256 * i;
        if (n < Nn) p[n] = vals[i] * inv;
    }
}

// ---------------- agent_v[b,h,a,d] = attn1 @ v ----------------
__global__ __launch_bounds__(256) void agentv_kernel()
{
    const int bh = blockIdx.x;
    const int b = bh / HEADS, h = bh % HEADS;
    __shared__ float p_s[AG][64];
    __shared__ float v_s[64][68];
    const int tid = threadIdx.x;
    const int dp = tid & 31;
    const int ag = tid >> 5;

    float acc0[7], acc1[7];
#pragma unroll
    for (int i = 0; i < 7; i++) { acc0[i] = 0.f; acc1[i] = 0.f; }

    for (int n0 = 0; n0 < Nn; n0 += 64) {
        __syncthreads();
        for (int f = tid; f < AG * 64; f += 256) {
            int a = f >> 6, nn = f & 63;
            p_s[a][nn] = g_attn1[((size_t)bh * AG + a) * Nn + n0 + nn];
        }
        for (int f = tid; f < 64 * 16; f += 256) {
            int row = f >> 4, c4 = (f & 15) * 4;
            *(float4*)&v_s[row][c4] =
                *(const float4*)&g_kv[((size_t)(b * Nn + n0 + row)) * (2 * Cc) + Cc + h * Dd + c4];
        }
        __syncthreads();
        for (int nn = 0; nn < 64; nn++) {
            float v0 = v_s[nn][dp];
            float v1 = v_s[nn][dp + 32];
#pragma unroll
            for (int i = 0; i < 7; i++) {
                int a = ag + 8 * i;
                if (a < AG) {
                    float pp = p_s[a][nn];
                    acc0[i] = fmaf(pp, v0, acc0[i]);
                    acc1[i] = fmaf(pp, v1, acc1[i]);
                }
            }
        }
    }
#pragma unroll
    for (int i = 0; i < 7; i++) {
        int a = ag + 8 * i;
        if (a < AG) {
            g_agentv[((size_t)bh * AG + a) * Dd + dp] = acc0[i];
            g_agentv[((size_t)bh * AG + a) * Dd + dp + 32] = acc1[i];
        }
    }
}

// ---------------- stage 2: per (b,h,n) row softmax over 49 agents ----------------
__global__ __launch_bounds__(64) void stage2_kernel()
{
    const int bh = blockIdx.y;
    const int b = bh / HEADS, h = bh % HEADS;
    const int tid = threadIdx.x;
    const int n = blockIdx.x * 64 + tid;
    __shared__ float a4s[AG][64];
    __shared__ float avs[AG][64];
    __shared__ float sc[AG][64];

    for (int f = tid; f < AG * 64; f += 64) {
        int a = f >> 6, d = f & 63;
        a4s[a][d] = g_agent[((size_t)b * AG + a) * Cc + h * Dd + d] * 0.125f;
        avs[a][d] = g_agentv[((size_t)bh * AG + a) * Dd + d];
    }
    __syncthreads();

    float4 qv[16];
    const float* qrow = g_q + ((size_t)(b * Nn + n)) * Cc + h * Dd;
#pragma unroll
    for (int i = 0; i < 16; i++) qv[i] = *(const float4*)&qrow[i * 4];

    const float* bq = g_bias_qa + ((size_t)(h * Nn + n)) * AG;
    float m = -1e30f;
    for (int a = 0; a < AG; a++) {
        float dot = 0.f;
#pragma unroll
        for (int d4 = 0; d4 < 16; d4++) {
            float4 av = *(const float4*)&a4s[a][d4 * 4];
            dot = fmaf(qv[d4].x, av.x, dot);
            dot = fmaf(qv[d4].y, av.y, dot);
            dot = fmaf(qv[d4].z, av.z, dot);
            dot = fmaf(qv[d4].w, av.w, dot);
        }
        float s = dot + bq[a];
        sc[a][tid] = s;
        m = fmaxf(m, s);
    }
    float sum = 0.f;
    for (int a = 0; a < AG; a++) {
        float e = __expf(sc[a][tid] - m);
        sc[a][tid] = e;
        sum += e;
    }
    float inv = 1.0f / sum;

    float4 acc[16];
#pragma unroll
    for (int i = 0; i < 16; i++) acc[i] = make_float4(0.f, 0.f, 0.f, 0.f);
    for (int a = 0; a < AG; a++) {
        float pp = sc[a][tid];
#pragma unroll
        for (int d4 = 0; d4 < 16; d4++) {
            float4 av = *(const float4*)&avs[a][d4 * 4];
            acc[d4].x = fmaf(pp, av.x, acc[d4].x);
            acc[d4].y = fmaf(pp, av.y, acc[d4].y);
            acc[d4].z = fmaf(pp, av.z, acc[d4].z);
            acc[d4].w = fmaf(pp, av.w, acc[d4].w);
        }
    }
    float* orow = g_acc + ((size_t)(b * Nn + n)) * Cc + h * Dd;
#pragma unroll
    for (int d4 = 0; d4 < 16; d4++) {
        acc[d4].x *= inv; acc[d4].y *= inv; acc[d4].z *= inv; acc[d4].w *= inv;
        *(float4*)&orow[d4 * 4] = acc[d4];
    }
}

// ---------------- depthwise 3x3 conv on v + add attn out -> fp16 ------------------
__global__ __launch_bounds__(256) void dwc_kernel(
    const float* __restrict__ w, const float* __restrict__ bias)
{
    size_t idx = (size_t)blockIdx.x * 256 + threadIdx.x;  // < B*Nn*Cc (exact)
    int c = (int)(idx % Cc);
    size_t bnv = idx / Cc;
    int n = (int)(bnv % Nn);
    int b = (int)(bnv / Nn);
    int y = n / Hpix, x = n % Hpix;
    float s = bias[c];
#pragma unroll
    for (int dy = -1; dy <= 1; dy++) {
        int yy = y + dy;
        if (yy < 0 || yy >= Hpix) continue;
#pragma unroll
        for (int dx = -1; dx <= 1; dx++) {
            int xx = x + dx;
            if (xx < 0 || xx >= Hpix) continue;
            s = fmaf(g_kv[((size_t)(b * Nn + yy * Hpix + xx)) * (2 * Cc) + Cc + c],
                     w[c * 9 + (dy + 1) * 3 + (dx + 1)], s);
        }
    }
    g_acch[idx] = __float2half(g_acc[idx] + s);
}

// ---------------- launch ----------------
extern "C" void kernel_launch(void* const* d_in, const int* in_sizes, int n_in,
                              void* d_out, int out_size)
{
    const float* x      = (const float*)d_in[0];
    const float* q_w    = (const float*)d_in[1];
    const float* kv_w   = (const float*)d_in[2];
    const float* proj_w = (const float*)d_in[3];
    const float* proj_b = (const float*)d_in[4];
    const float* dwc_w  = (const float*)d_in[5];
    const float* dwc_b  = (const float*)d_in[6];
    const float* an_b   = (const float*)d_in[7];
    const float* na_b   = (const float*)d_in[8];
    const float* ah     = (const float*)d_in[9];
    const float* aw     = (const float*)d_in[10];
    const float* ha     = (const float*)d_in[11];
    const float* wa     = (const float*)d_in[12];

    float *qp, *kvp;
    __half *xhp, *acchp, *wtp;
    cudaGetSymbolAddress((void**)&qp, g_q);
    cudaGetSymbolAddress((void**)&kvp, g_kv);
    cudaGetSymbolAddress((void**)&xhp, g_xh);
    cudaGetSymbolAddress((void**)&acchp, g_acch);
    cudaGetSymbolAddress((void**)&wtp, g_wTh);

    cudaFuncSetAttribute(gemm_h, cudaFuncAttributeMaxDynamicSharedMemorySize, GT_SMEM);

    const int M = Bn * Nn;  // 50176

    // weight transpose->fp16, x cast->fp16
    wtrans_kernel<<<dim3(512 / 32, 512 / 32), 256>>>(q_w, wtp + WT_Q, 512, 512);
    wtrans_kernel<<<dim3(1024 / 32, 512 / 32), 256>>>(kv_w, wtp + WT_KV, 512, 1024);
    wtrans_kernel<<<dim3(512 / 32, 512 / 32), 256>>>(proj_w, wtp + WT_PROJ, 512, 512);
    xconv_kernel<<<(int)(((size_t)M * Cc / 8) / 256), 256>>>(x, xhp);

    gemm_h<<<dim3(512 / 128, M / 128), 256, GT_SMEM>>>(xhp, wtp + WT_Q, qp, M, Cc, Cc, nullptr);
    gemm_h<<<dim3(1024 / 128, M / 128), 256, GT_SMEM>>>(xhp, wtp + WT_KV, kvp, M, Cc, 2 * Cc, nullptr);
    pool_kernel<<<(Bn * AG * Cc) / 256, 256>>>();
    biasak_kernel<<<(HEADS * AG * Nn) / 256, 256>>>(an_b, ah, aw);
    biasqa_kernel<<<(HEADS * Nn * AG) / 256, 256>>>(na_b, ha, wa);
    scores1_kernel<<<dim3(4, Bn * HEADS), 256>>>();
    softmax1_kernel<<<Bn * HEADS * AG, 256>>>();
    agentv_kernel<<<Bn * HEADS, 256>>>();
    stage2_kernel<<<dim3(Nn / 64, Bn * HEADS), 64>>>();
    dwc_kernel<<<(int)(((size_t)Bn * Nn * Cc) / 256), 256>>>(dwc_w, dwc_b);
    gemm_h<<<dim3(512 / 128, M / 128), 256, GT_SMEM>>>(acchp, wtp + WT_PROJ, (float*)d_out, M, Cc, Cc, proj_b);
}

// round 6
// speedup vs baseline: 2.9496x; 1.1889x over previous
#include <cuda_runtime.h>
#include <cuda_fp16.h>
#include <cstdint>
#include <math.h>

#define Bn 16
#define Nn 3136
#define Cc 512
#define Hpix 56
#define HEADS 8
#define Dd 64
#define AG 49

// ---------------- scratch (device globals; no allocation allowed) ----------------
__device__ float g_q[(size_t)Bn * Nn * Cc];            // (b,n,c)
__device__ float g_kv[(size_t)Bn * Nn * 2 * Cc];       // (b,n,2c) k=[0,512) v=[512,1024)
__device__ float g_agent[(size_t)Bn * AG * Cc];        // (b,a,c)
__device__ float g_bias_ak[(size_t)HEADS * AG * Nn];   // (h,a,n)
__device__ float g_bias_qa[(size_t)HEADS * Nn * AG];   // (h,n,a)
__device__ float g_attn1[(size_t)Bn * HEADS * AG * Nn];// (b,h,a,n)
__device__ float g_agentv[(size_t)Bn * HEADS * AG * Dd];
__device__ float g_acc[(size_t)Bn * Nn * Cc];          // stage2 attention out (fp32)
__device__ __half g_xh[(size_t)Bn * Nn * Cc];          // x in fp16
__device__ __half g_acch[(size_t)Bn * Nn * Cc];        // (attn out + dwc) in fp16
// transposed fp16 weights: qT [512x512] | kvT [1024x512] | projT [512x512], K-major
__device__ __half g_wTh[(size_t)2048 * 512];
#define WT_Q 0
#define WT_KV (512 * 512)
#define WT_PROJ (512 * 512 + 1024 * 512)

#define MMA16816(acc, a0, a1, a2, a3, b0, b1)                                   \
    asm volatile(                                                               \
        "mma.sync.aligned.m16n8k16.row.col.f32.f16.f16.f32 "                    \
        "{%0,%1,%2,%3}, {%4,%5,%6,%7}, {%8,%9}, {%0,%1,%2,%3};"                 \
        : "+f"(acc[0]), "+f"(acc[1]), "+f"(acc[2]), "+f"(acc[3])                \
        : "r"(a0), "r"(a1), "r"(a2), "r"(a3), "r"(b0), "r"(b1))

// ---------------- fp16 tensor-core GEMM: C[M,Nc] = A[M,K] @ Bt[Nc,K]^T (+bias) ----
// BM=128 BN=128 BK=64, 256 threads (4x2 warps, warp tile 32x64), 3-stage cp.async.
// smem stride 72 halves: frag LDS bank = 4g + c (+const) -> conflict-free.
#define GAS 72
#define GBUF (128 * GAS)          // halves per operand per stage
#define GSTAGES 3
#define GT_SMEM (GSTAGES * 2 * GBUF * 2)   // 110592 bytes

__global__ __launch_bounds__(256, 2) void gemm_h(
    const __half* __restrict__ A, const __half* __restrict__ Bt,
    float* __restrict__ Cout, int M, int K, int Nc, const float* __restrict__ bias)
{
    extern __shared__ __half smh[];
    __half* smA = smh;                       // [3][128*72]
    __half* smB = smh + GSTAGES * GBUF;      // [3][128*72]
    const int tid = threadIdx.x;
    const int wid = tid >> 5, lane = tid & 31;
    const int wm = wid & 3, wn = wid >> 2;
    const int g = lane >> 2, cq = lane & 3;
    const int bm = blockIdx.y * 128, bn = blockIdx.x * 128;

    float acc[2][8][4];
#pragma unroll
    for (int i = 0; i < 2; i++)
#pragma unroll
        for (int j = 0; j < 8; j++)
#pragma unroll
            for (int t = 0; t < 4; t++) acc[i][j][t] = 0.f;

    auto loadAB = [&](int s, int kc) {
        const __half* ga = A + (size_t)bm * K + kc * 64;
        const __half* gb = Bt + (size_t)bn * K + kc * 64;
        __half* da = smA + s * GBUF;
        __half* db = smB + s * GBUF;
#pragma unroll
        for (int i = 0; i < 4; i++) {
            int idx = i * 256 + tid;        // 1024 = 128 rows x 8 segs
            int row = idx >> 3, seg = idx & 7;
            uint32_t pa = (uint32_t)__cvta_generic_to_shared(da + row * GAS + seg * 8);
            uint32_t pb = (uint32_t)__cvta_generic_to_shared(db + row * GAS + seg * 8);
            asm volatile("cp.async.cg.shared.global [%0], [%1], 16;\n"
                         :: "r"(pa), "l"(ga + (size_t)row * K + seg * 8));
            asm volatile("cp.async.cg.shared.global [%0], [%1], 16;\n"
                         :: "r"(pb), "l"(gb + (size_t)row * K + seg * 8));
        }
        asm volatile("cp.async.commit_group;\n");
    };

    const int KT = K / 64;   // 8
    loadAB(0, 0);
    loadAB(1, 1);
    loadAB(2, 2);

    for (int c = 0; c < KT; c++) {
        int s = c % GSTAGES;
        if (c + 2 < KT)      asm volatile("cp.async.wait_group 2;\n");
        else if (c + 1 < KT) asm volatile("cp.async.wait_group 1;\n");
        else                 asm volatile("cp.async.wait_group 0;\n");
        __syncthreads();
        const __half* Ab = smA + s * GBUF + (wm * 32) * GAS;
        const __half* Bb = smB + s * GBUF + (wn * 64) * GAS;
#pragma unroll
        for (int ks = 0; ks < 4; ks++) {
            const int k = ks * 16 + 2 * cq;
            uint32_t a[2][4];
#pragma unroll
            for (int i = 0; i < 2; i++) {
                int r = i * 16 + g;
                a[i][0] = *(const uint32_t*)&Ab[r * GAS + k];
                a[i][1] = *(const uint32_t*)&Ab[(r + 8) * GAS + k];
                a[i][2] = *(const uint32_t*)&Ab[r * GAS + k + 8];
                a[i][3] = *(const uint32_t*)&Ab[(r + 8) * GAS + k + 8];
            }
#pragma unroll
            for (int j = 0; j < 8; j++) {
                uint32_t b0 = *(const uint32_t*)&Bb[(j * 8 + g) * GAS + k];
                uint32_t b1 = *(const uint32_t*)&Bb[(j * 8 + g) * GAS + k + 8];
#pragma unroll
                for (int i = 0; i < 2; i++) {
                    MMA16816(acc[i][j], a[i][0], a[i][1], a[i][2], a[i][3], b0, b1);
                }
            }
        }
        __syncthreads();
        if (c + GSTAGES < KT) loadAB(s, c + GSTAGES);
    }

    // epilogue: float2 stores, optional bias
#pragma unroll
    for (int j = 0; j < 8; j++) {
        int col = bn + wn * 64 + j * 8 + 2 * cq;
        float bx = 0.f, by = 0.f;
        if (bias) { bx = bias[col]; by = bias[col + 1]; }
#pragma unroll
        for (int i = 0; i < 2; i++) {
            int r0 = bm + wm * 32 + i * 16 + g;
            *(float2*)&Cout[(size_t)r0 * Nc + col] =
                make_float2(acc[i][j][0] + bx, acc[i][j][1] + by);
            *(float2*)&Cout[(size_t)(r0 + 8) * Nc + col] =
                make_float2(acc[i][j][2] + bx, acc[i][j][3] + by);
        }
    }
}

// ---------------- weight transpose + fp16 convert: Wt[n][k] = half(W[k][n]) ------
__global__ __launch_bounds__(256) void wtrans_kernel(
    const float* __restrict__ W, __half* __restrict__ Wt, int K, int Nc)
{
    __shared__ float t[32][33];
    int k0 = blockIdx.y * 32, n0 = blockIdx.x * 32;
    int tx = threadIdx.x & 31, ty = threadIdx.x >> 5;   // 32 x 8
#pragma unroll
    for (int i = 0; i < 32; i += 8)
        t[ty + i][tx] = W[(size_t)(k0 + ty + i) * Nc + n0 + tx];
    __syncthreads();
#pragma unroll
    for (int i = 0; i < 32; i += 8)
        Wt[(size_t)(n0 + ty + i) * K + k0 + tx] = __float2half(t[tx][ty + i]);
}

// ---------------- fp32 -> fp16 cast (8 elems/thread, exact grid) -----------------
__global__ __launch_bounds__(256) void xconv_kernel(
    const float* __restrict__ src, __half* __restrict__ dst)
{
    size_t i = (size_t)blockIdx.x * 256 + threadIdx.x;
    float4 v0 = ((const float4*)src)[2 * i];
    float4 v1 = ((const float4*)src)[2 * i + 1];
    __half2 h0 = __floats2half2_rn(v0.x, v0.y);
    __half2 h1 = __floats2half2_rn(v0.z, v0.w);
    __half2 h2 = __floats2half2_rn(v1.x, v1.y);
    __half2 h3 = __floats2half2_rn(v1.z, v1.w);
    uint4 o;
    o.x = *(uint32_t*)&h0;
    o.y = *(uint32_t*)&h1;
    o.z = *(uint32_t*)&h2;
    o.w = *(uint32_t*)&h3;
    ((uint4*)dst)[i] = o;
}

// ---------------- 8x8 mean pool: agent[b,a,c] ----------------
__global__ __launch_bounds__(256) void pool_kernel()
{
    int idx = blockIdx.x * 256 + threadIdx.x;   // < B*AG*C (exact)
    int c = idx % Cc;
    int ba = idx / Cc;
    int a = ba % AG;
    int b = ba / AG;
    int py = a / 7, px = a % 7;
    float s = 0.f;
#pragma unroll
    for (int dy = 0; dy < 8; dy++) {
        int n_base = (py * 8 + dy) * Hpix + px * 8;
#pragma unroll
        for (int dx = 0; dx < 8; dx++)
            s += g_q[((size_t)b * Nn + n_base + dx) * Cc + c];
    }
    g_agent[idx] = s * (1.0f / 64.0f);
}

// ---------------- bilinear 7x7 -> 56x56 (half-pixel centers, edge clamp) ----------
__device__ __forceinline__ float bilerp7(const float* __restrict__ t, int y, int x)
{
    float sy = (y + 0.5f) * 0.125f - 0.5f;
    float sx = (x + 0.5f) * 0.125f - 0.5f;
    int y0f = (int)floorf(sy);
    int x0f = (int)floorf(sx);
    float wy = sy - (float)y0f;
    float wx = sx - (float)x0f;
    int y0 = min(6, max(0, y0f));
    int y1 = min(6, max(0, y0f + 1));
    int x0 = min(6, max(0, x0f));
    int x1 = min(6, max(0, x0f + 1));
    float v00 = t[y0 * 7 + x0], v01 = t[y0 * 7 + x1];
    float v10 = t[y1 * 7 + x0], v11 = t[y1 * 7 + x1];
    float top = v00 + wx * (v01 - v00);
    float bot = v10 + wx * (v11 - v10);
    return top + wy * (bot - top);
}

__global__ __launch_bounds__(256) void biasak_kernel(
    const float* __restrict__ an, const float* __restrict__ ah, const float* __restrict__ aw)
{
    int idx = blockIdx.x * 256 + threadIdx.x;   // < H*AG*Nn (exact)
    int n = idx % Nn;
    int haa = idx / Nn;                          // h*49+a
    int y = n / Hpix, x = n % Hpix;
    g_bias_ak[idx] = bilerp7(an + haa * 49, y, x) + ah[haa] + aw[haa];
}

__global__ __launch_bounds__(256) void biasqa_kernel(
    const float* __restrict__ na, const float* __restrict__ ha, const float* __restrict__ wa)
{
    int idx = blockIdx.x * 256 + threadIdx.x;   // < H*Nn*AG (exact)
    int a = idx % AG;
    int hn = idx / AG;
    int n = hn % Nn;
    int h = hn / Nn;
    int y = n / Hpix, x = n % Hpix;
    int haa = h * AG + a;
    g_bias_qa[idx] = bilerp7(na + haa * 49, y, x) + ha[haa] + wa[haa];
}

// ---------------- stage 1 scores: s1[b,h,a,n] = (agent*scale)·k + bias ------------
// grid (4, Bn*HEADS): x = n-interleave, y = bh. OOB-safe on the 3136 % 128 tail.
__global__ __launch_bounds__(256) void scores1_kernel()
{
    const int bh = blockIdx.y;
    const int b = bh / HEADS, h = bh % HEADS;
    __shared__ float a_s[52][64];
    __shared__ float ks[128][68];
    const int tid = threadIdx.x;

    for (int f = tid; f < 52 * 64; f += 256) {
        int a = f >> 6, d = f & 63;
        a_s[a][d] = (a < AG) ? g_agent[((size_t)b * AG + a) * Cc + h * Dd + d] * 0.125f : 0.f;
    }
    const int nt = tid & 31;
    const int at0 = tid >> 5;

    for (int n0 = blockIdx.x * 128; n0 < Nn; n0 += 512) {
        __syncthreads();
        for (int f = tid; f < 128 * 16; f += 256) {
            int row = f >> 4, c4 = (f & 15) * 4;
            int nr = min(n0 + row, Nn - 1);      // clamp tail
            *(float4*)&ks[row][c4] =
                *(const float4*)&g_kv[((size_t)(b * Nn + nr)) * (2 * Cc) + h * Dd + c4];
        }
        __syncthreads();
        for (int at = at0; at < 13; at += 8) {
            int a0 = at * 4;
            float acc[4][4];
#pragma unroll
            for (int i = 0; i < 4; i++)
#pragma unroll
                for (int j = 0; j < 4; j++) acc[i][j] = 0.f;
#pragma unroll 4
            for (int d4 = 0; d4 < 16; d4++) {
                float4 av[4], kf[4];
#pragma unroll
                for (int i = 0; i < 4; i++) av[i] = *(const float4*)&a_s[a0 + i][d4 * 4];
#pragma unroll
                for (int j = 0; j < 4; j++) kf[j] = *(const float4*)&ks[nt + 32 * j][d4 * 4];
#pragma unroll
                for (int i = 0; i < 4; i++)
#pragma unroll
                    for (int j = 0; j < 4; j++) {
                        acc[i][j] = fmaf(av[i].x, kf[j].x, acc[i][j]);
                        acc[i][j] = fmaf(av[i].y, kf[j].y, acc[i][j]);
                        acc[i][j] = fmaf(av[i].z, kf[j].z, acc[i][j]);
                        acc[i][j] = fmaf(av[i].w, kf[j].w, acc[i][j]);
                    }
            }
#pragma unroll
            for (int i = 0; i < 4; i++) {
                int a = a0 + i;
                if (a < AG) {
#pragma unroll
                    for (int j = 0; j < 4; j++) {
                        int n = n0 + nt + 32 * j;
                        if (n < Nn)
                            g_attn1[((size_t)bh * AG + a) * Nn + n] =
                                acc[i][j] + g_bias_ak[((size_t)(h * AG + a)) * Nn + n];
                    }
                }
            }
        }
    }
}

// ---------------- softmax over n (row length 3136) ----------------
__global__ __launch_bounds__(256) void softmax1_kernel()
{
    float* p = g_attn1 + (size_t)blockIdx.x * Nn;
    const int tid = threadIdx.x;
    float vals[13];
    float m = -1e30f;
#pragma unroll
    for (int i = 0; i < 13; i++) {
        int n = tid + 256 * i;
        vals[i] = (n < Nn) ? p[n] : -1e30f;
        m = fmaxf(m, vals[i]);
    }
    __shared__ float red[8];
#pragma unroll
    for (int o = 16; o > 0; o >>= 1) m = fmaxf(m, __shfl_xor_sync(0xffffffffu, m, o));
    if ((tid & 31) == 0) red[tid >> 5] = m;
    __syncthreads();
    float bm = red[0];
#pragma unroll
    for (int i = 1; i < 8; i++) bm = fmaxf(bm, red[i]);
    __syncthreads();

    float s = 0.f;
#pragma unroll
    for (int i = 0; i < 13; i++) {
        float e = __expf(vals[i] - bm);
        vals[i] = e;
        s += e;
    }
#pragma unroll
    for (int o = 16; o > 0; o >>= 1) s += __shfl_xor_sync(0xffffffffu, s, o);
    if ((tid & 31) == 0) red[tid >> 5] = s;
    __syncthreads();
    float tot = 0.f;
#pragma unroll
    for (int i = 0; i < 8; i++) tot += red[i];
    float inv = 1.0f / tot;
#pragma unroll
    for (int i = 0; i < 13; i++) {
        int n = tid + 256 * i;
        if (n < Nn) p[n] = vals[i] * inv;
    }
}

// ---------------- agent_v[b,h,a,d] = attn1 @ v ----------------
__global__ __launch_bounds__(256) void agentv_kernel()
{
    const int bh = blockIdx.x;
    const int b = bh / HEADS, h = bh % HEADS;
    __shared__ float p_s[AG][64];
    __shared__ float v_s[64][68];
    const int tid = threadIdx.x;
    const int dp = tid & 31;
    const int ag = tid >> 5;

    float acc0[7], acc1[7];
#pragma unroll
    for (int i = 0; i < 7; i++) { acc0[i] = 0.f; acc1[i] = 0.f; }

    for (int n0 = 0; n0 < Nn; n0 += 64) {
        __syncthreads();
        for (int f = tid; f < AG * 64; f += 256) {
            int a = f >> 6, nn = f & 63;
            p_s[a][nn] = g_attn1[((size_t)bh * AG + a) * Nn + n0 + nn];
        }
        for (int f = tid; f < 64 * 16; f += 256) {
            int row = f >> 4, c4 = (f & 15) * 4;
            *(float4*)&v_s[row][c4] =
                *(const float4*)&g_kv[((size_t)(b * Nn + n0 + row)) * (2 * Cc) + Cc + h * Dd + c4];
        }
        __syncthreads();
        for (int nn = 0; nn < 64; nn++) {
            float v0 = v_s[nn][dp];
            float v1 = v_s[nn][dp + 32];
#pragma unroll
            for (int i = 0; i < 7; i++) {
                int a = ag + 8 * i;
                if (a < AG) {
                    float pp = p_s[a][nn];
                    acc0[i] = fmaf(pp, v0, acc0[i]);
                    acc1[i] = fmaf(pp, v1, acc1[i]);
                }
            }
        }
    }
#pragma unroll
    for (int i = 0; i < 7; i++) {
        int a = ag + 8 * i;
        if (a < AG) {
            g_agentv[((size_t)bh * AG + a) * Dd + dp] = acc0[i];
            g_agentv[((size_t)bh * AG + a) * Dd + dp + 32] = acc1[i];
        }
    }
}

// ---------------- stage 2 (tensor-core fused): softmax(q·a^T + bias) @ agent_v ----
// grid (25, Bn*HEADS), 256 threads (8 warps, each an m16 strip of a 128-row tile).
// Agents padded 49->64 (masked -1e30 pre-softmax). Fragment conventions identical
// to gemm_h (verified): B-frag n=8j+g / k=2cq; C-frag col=8j+2cq, rows g,g+8.
#define S2S 72
__global__ __launch_bounds__(256) void stage2_mma()
{
    __shared__ __half qh[128 * S2S];
    __shared__ __half a4h[64 * S2S];   // [agent][d], scaled
    __shared__ __half avh[64 * S2S];   // [d][agent]  (agent_v transposed)
    const int bh = blockIdx.y;
    const int b = bh / HEADS, h = bh % HEADS;
    const int n0 = blockIdx.x * 128;
    const int tid = threadIdx.x;
    const int wid = tid >> 5, lane = tid & 31;
    const int g = lane >> 2, cq = lane & 3;

    // q tile 128x64 fp32 -> fp16 (rows clamped on the 3136 tail)
#pragma unroll
    for (int i = 0; i < 8; i++) {
        int idx = i * 256 + tid;              // 2048 = 128 rows x 16 segs
        int r = idx >> 4, seg = idx & 15;
        int n = min(n0 + r, Nn - 1);
        float4 v = *(const float4*)&g_q[((size_t)(b * Nn + n)) * Cc + h * Dd + seg * 4];
        __half2 h0 = __floats2half2_rn(v.x, v.y);
        __half2 h1 = __floats2half2_rn(v.z, v.w);
        *(__half2*)&qh[r * S2S + seg * 4] = h0;
        *(__half2*)&qh[r * S2S + seg * 4 + 2] = h1;
    }
    // agents (scaled) + agent_v transposed, zero-padded to 64
#pragma unroll
    for (int i = 0; i < 16; i++) {
        int idx = i * 256 + tid;              // 4096 = 64 x 64
        int a = idx >> 6, d = idx & 63;
        float av = (a < AG) ? g_agent[((size_t)b * AG + a) * Cc + h * Dd + d] * 0.125f : 0.f;
        float vv = (a < AG) ? g_agentv[((size_t)bh * AG + a) * Dd + d] : 0.f;
        a4h[a * S2S + d] = __float2half(av);
        avh[d * S2S + a] = __float2half(vv);
    }
    __syncthreads();

    // ---- S = q @ a4^T  (K = d = 64) ----
    float s[8][4];
#pragma unroll
    for (int j = 0; j < 8; j++)
#pragma unroll
        for (int t = 0; t < 4; t++) s[j][t] = 0.f;

    const __half* qa = qh + (wid * 16) * S2S;
#pragma unroll
    for (int t = 0; t < 4; t++) {
        int k = t * 16 + 2 * cq;
        uint32_t a0 = *(const uint32_t*)&qa[g * S2S + k];
        uint32_t a1 = *(const uint32_t*)&qa[(g + 8) * S2S + k];
        uint32_t a2 = *(const uint32_t*)&qa[g * S2S + k + 8];
        uint32_t a3 = *(const uint32_t*)&qa[(g + 8) * S2S + k + 8];
#pragma unroll
        for (int j = 0; j < 8; j++) {
            uint32_t b0 = *(const uint32_t*)&a4h[(j * 8 + g) * S2S + k];
            uint32_t b1 = *(const uint32_t*)&a4h[(j * 8 + g) * S2S + k + 8];
            MMA16816(s[j], a0, a1, a2, a3, b0, b1);
        }
    }

    // ---- bias + mask + row softmax (cols spread over quad lanes: shfl 1,2) ----
    const int r0 = n0 + wid * 16 + g;
    const int r1 = r0 + 8;
    float m0 = -1e30f, m1 = -1e30f;
#pragma unroll
    for (int j = 0; j < 8; j++) {
        int a = 8 * j + 2 * cq;
        if (a < AG) {
            float b00 = (r0 < Nn) ? g_bias_qa[((size_t)h * Nn + r0) * AG + a] : 0.f;
            float b10 = (r1 < Nn) ? g_bias_qa[((size_t)h * Nn + r1) * AG + a] : 0.f;
            s[j][0] += b00;
            s[j][2] += b10;
            if (a + 1 < AG) {
                float b01 = (r0 < Nn) ? g_bias_qa[((size_t)h * Nn + r0) * AG + a + 1] : 0.f;
                float b11 = (r1 < Nn) ? g_bias_qa[((size_t)h * Nn + r1) * AG + a + 1] : 0.f;
                s[j][1] += b01;
                s[j][3] += b11;
            } else {
                s[j][1] = -1e30f;
                s[j][3] = -1e30f;
            }
        } else {
            s[j][0] = -1e30f; s[j][1] = -1e30f;
            s[j][2] = -1e30f; s[j][3] = -1e30f;
        }
        m0 = fmaxf(m0, fmaxf(s[j][0], s[j][1]));
        m1 = fmaxf(m1, fmaxf(s[j][2], s[j][3]));
    }
    m0 = fmaxf(m0, __shfl_xor_sync(0xffffffffu, m0, 1));
    m0 = fmaxf(m0, __shfl_xor_sync(0xffffffffu, m0, 2));
    m1 = fmaxf(m1, __shfl_xor_sync(0xffffffffu, m1, 1));
    m1 = fmaxf(m1, __shfl_xor_sync(0xffffffffu, m1, 2));

    float sum0 = 0.f, sum1 = 0.f;
#pragma unroll
    for (int j = 0; j < 8; j++) {
        s[j][0] = __expf(s[j][0] - m0);
        s[j][1] = __expf(s[j][1] - m0);
        s[j][2] = __expf(s[j][2] - m1);
        s[j][3] = __expf(s[j][3] - m1);
        sum0 += s[j][0] + s[j][1];
        sum1 += s[j][2] + s[j][3];
    }
    sum0 += __shfl_xor_sync(0xffffffffu, sum0, 1);
    sum0 += __shfl_xor_sync(0xffffffffu, sum0, 2);
    sum1 += __shfl_xor_sync(0xffffffffu, sum1, 1);
    sum1 += __shfl_xor_sync(0xffffffffu, sum1, 2);
    const float inv0 = 1.0f / sum0, inv1 = 1.0f / sum1;

    // ---- repack P into A-fragments: k-tile t <- C n-tiles 2t, 2t+1 ----
    uint32_t pa[4][4];
#pragma unroll
    for (int t = 0; t < 4; t++) {
        __half2 h0 = __floats2half2_rn(s[2 * t][0], s[2 * t][1]);
        __half2 h1 = __floats2half2_rn(s[2 * t][2], s[2 * t][3]);
        __half2 h2 = __floats2half2_rn(s[2 * t + 1][0], s[2 * t + 1][1]);
        __half2 h3 = __floats2half2_rn(s[2 * t + 1][2], s[2 * t + 1][3]);
        pa[t][0] = *(uint32_t*)&h0;
        pa[t][1] = *(uint32_t*)&h1;
        pa[t][2] = *(uint32_t*)&h2;
        pa[t][3] = *(uint32_t*)&h3;
    }

    // ---- O = P @ agent_v  (K = a = 64 padded) ----
    float o[8][4];
#pragma unroll
    for (int j = 0; j < 8; j++)
#pragma unroll
        for (int t = 0; t < 4; t++) o[j][t] = 0.f;
#pragma unroll
    for (int t = 0; t < 4; t++) {
        int k = t * 16 + 2 * cq;
#pragma unroll
        for (int j = 0; j < 8; j++) {
            uint32_t b0 = *(const uint32_t*)&avh[(j * 8 + g) * S2S + k];
            uint32_t b1 = *(const uint32_t*)&avh[(j * 8 + g) * S2S + k + 8];
            MMA16816(o[j], pa[t][0], pa[t][1], pa[t][2], pa[t][3], b0, b1);
        }
    }

    // ---- normalize + store fp32 ----
#pragma unroll
    for (int j = 0; j < 8; j++) {
        int d = 8 * j + 2 * cq;
        if (r0 < Nn)
            *(float2*)&g_acc[((size_t)(b * Nn + r0)) * Cc + h * Dd + d] =
                make_float2(o[j][0] * inv0, o[j][1] * inv0);
        if (r1 < Nn)
            *(float2*)&g_acc[((size_t)(b * Nn + r1)) * Cc + h * Dd + d] =
                make_float2(o[j][2] * inv1, o[j][3] * inv1);
    }
}

// ---------------- depthwise 3x3 conv on v + add attn out -> fp16 ------------------
__global__ __launch_bounds__(256) void dwc_kernel(
    const float* __restrict__ w, const float* __restrict__ bias)
{
    size_t idx = (size_t)blockIdx.x * 256 + threadIdx.x;  // < B*Nn*Cc (exact)
    int c = (int)(idx % Cc);
    size_t bnv = idx / Cc;
    int n = (int)(bnv % Nn);
    int b = (int)(bnv / Nn);
    int y = n / Hpix, x = n % Hpix;
    float s = bias[c];
#pragma unroll
    for (int dy = -1; dy <= 1; dy++) {
        int yy = y + dy;
        if (yy < 0 || yy >= Hpix) continue;
#pragma unroll
        for (int dx = -1; dx <= 1; dx++) {
            int xx = x + dx;
            if (xx < 0 || xx >= Hpix) continue;
            s = fmaf(g_kv[((size_t)(b * Nn + yy * Hpix + xx)) * (2 * Cc) + Cc + c],
                     w[c * 9 + (dy + 1) * 3 + (dx + 1)], s);
        }
    }
    g_acch[idx] = __float2half(g_acc[idx] + s);
}

// ---------------- launch ----------------
extern "C" void kernel_launch(void* const* d_in, const int* in_sizes, int n_in,
                              void* d_out, int out_size)
{
    const float* x      = (const float*)d_in[0];
    const float* q_w    = (const float*)d_in[1];
    const float* kv_w   = (const float*)d_in[2];
    const float* proj_w = (const float*)d_in[3];
    const float* proj_b = (const float*)d_in[4];
    const float* dwc_w  = (const float*)d_in[5];
    const float* dwc_b  = (const float*)d_in[6];
    const float* an_b   = (const float*)d_in[7];
    const float* na_b   = (const float*)d_in[8];
    const float* ah     = (const float*)d_in[9];
    const float* aw     = (const float*)d_in[10];
    const float* ha     = (const float*)d_in[11];
    const float* wa     = (const float*)d_in[12];

    float *qp, *kvp;
    __half *xhp, *acchp, *wtp;
    cudaGetSymbolAddress((void**)&qp, g_q);
    cudaGetSymbolAddress((void**)&kvp, g_kv);
    cudaGetSymbolAddress((void**)&xhp, g_xh);
    cudaGetSymbolAddress((void**)&acchp, g_acch);
    cudaGetSymbolAddress((void**)&wtp, g_wTh);

    cudaFuncSetAttribute(gemm_h, cudaFuncAttributeMaxDynamicSharedMemorySize, GT_SMEM);

    const int M = Bn * Nn;  // 50176

    // weight transpose->fp16, x cast->fp16
    wtrans_kernel<<<dim3(512 / 32, 512 / 32), 256>>>(q_w, wtp + WT_Q, 512, 512);
    wtrans_kernel<<<dim3(1024 / 32, 512 / 32), 256>>>(kv_w, wtp + WT_KV, 512, 1024);
    wtrans_kernel<<<dim3(512 / 32, 512 / 32), 256>>>(proj_w, wtp + WT_PROJ, 512, 512);
    xconv_kernel<<<(int)(((size_t)M * Cc / 8) / 256), 256>>>(x, xhp);

    gemm_h<<<dim3(512 / 128, M / 128), 256, GT_SMEM>>>(xhp, wtp + WT_Q, qp, M, Cc, Cc, nullptr);
    gemm_h<<<dim3(1024 / 128, M / 128), 256, GT_SMEM>>>(xhp, wtp + WT_KV, kvp, M, Cc, 2 * Cc, nullptr);
    pool_kernel<<<(Bn * AG * Cc) / 256, 256>>>();
    biasak_kernel<<<(HEADS * AG * Nn) / 256, 256>>>(an_b, ah, aw);
    biasqa_kernel<<<(HEADS * Nn * AG) / 256, 256>>>(na_b, ha, wa);
    scores1_kernel<<<dim3(4, Bn * HEADS), 256>>>();
    softmax1_kernel<<<Bn * HEADS * AG, 256>>>();
    agentv_kernel<<<Bn * HEADS, 256>>>();
    stage2_mma<<<dim3(25, Bn * HEADS), 256>>>();
    dwc_kernel<<<(int)(((size_t)Bn * Nn * Cc) / 256), 256>>>(dwc_w, dwc_b);
    gemm_h<<<dim3(512 / 128, M / 128), 256, GT_SMEM>>>(acchp, wtp + WT_PROJ, (float*)d_out, M, Cc, Cc, proj_b);
}

// round 7
// speedup vs baseline: 4.4578x; 1.5113x over previous
#include <cuda_runtime.h>
#include <cuda_fp16.h>
#include <cstdint>
#include <math.h>

#define Bn 16
#define Nn 3136
#define Cc 512
#define Hpix 56
#define HEADS 8
#define Dd 64
#define AG 49

// ---------------- scratch (device globals; no allocation allowed) ----------------
__device__ float g_q[(size_t)Bn * Nn * Cc];            // (b,n,c) fp32
__device__ __half g_kvh[(size_t)Bn * Nn * 2 * Cc];     // (b,n,2c) fp16: k=[0,512) v=[512,1024)
__device__ float g_agent[(size_t)Bn * AG * Cc];        // (b,a,c)
__device__ float g_bias_ak[(size_t)HEADS * AG * Nn];   // (h,a,n)
__device__ float g_bias_qa[(size_t)HEADS * Nn * AG];   // (h,n,a)
__device__ float g_agentv[(size_t)Bn * HEADS * AG * Dd];
__device__ float g_acc[(size_t)Bn * Nn * Cc];          // stage2 attention out (fp32)
__device__ __half g_xh[(size_t)Bn * Nn * Cc];          // x in fp16
__device__ __half g_acch[(size_t)Bn * Nn * Cc];        // (attn out + dwc) in fp16
// transposed fp16 weights: qT [512x512] | kvT [1024x512] | projT [512x512], K-major
__device__ __half g_wTh[(size_t)2048 * 512];
#define WT_Q 0
#define WT_KV (512 * 512)
#define WT_PROJ (512 * 512 + 1024 * 512)

#define MMA16816(acc, a0, a1, a2, a3, b0, b1)                                   \
    asm volatile(                                                               \
        "mma.sync.aligned.m16n8k16.row.col.f32.f16.f16.f32 "                    \
        "{%0,%1,%2,%3}, {%4,%5,%6,%7}, {%8,%9}, {%0,%1,%2,%3};"                 \
        : "+f"(acc[0]), "+f"(acc[1]), "+f"(acc[2]), "+f"(acc[3])                \
        : "r"(a0), "r"(a1), "r"(a2), "r"(a3), "r"(b0), "r"(b1))

// ---------------- fp16 tensor-core GEMM: C = A[M,K] @ Bt[Nc,K]^T (+bias) ----------
// Output either fp32 (Cout) or fp16 (CoutH). BM=BN=128 BK=64, 8 warps, 3-stage.
#define GAS 72
#define GBUF (128 * GAS)
#define GSTAGES 3
#define GT_SMEM (GSTAGES * 2 * GBUF * 2)   // 110592 bytes

__global__ __launch_bounds__(256, 2) void gemm_h(
    const __half* __restrict__ A, const __half* __restrict__ Bt,
    float* __restrict__ Cout, __half* __restrict__ CoutH,
    int M, int K, int Nc, const float* __restrict__ bias)
{
    extern __shared__ __half smh[];
    __half* smA = smh;
    __half* smB = smh + GSTAGES * GBUF;
    const int tid = threadIdx.x;
    const int wid = tid >> 5, lane = tid & 31;
    const int wm = wid & 3, wn = wid >> 2;
    const int g = lane >> 2, cq = lane & 3;
    const int bm = blockIdx.y * 128, bn = blockIdx.x * 128;

    float acc[2][8][4];
#pragma unroll
    for (int i = 0; i < 2; i++)
#pragma unroll
        for (int j = 0; j < 8; j++)
#pragma unroll
            for (int t = 0; t < 4; t++) acc[i][j][t] = 0.f;

    auto loadAB = [&](int s, int kc) {
        const __half* ga = A + (size_t)bm * K + kc * 64;
        const __half* gb = Bt + (size_t)bn * K + kc * 64;
        __half* da = smA + s * GBUF;
        __half* db = smB + s * GBUF;
#pragma unroll
        for (int i = 0; i < 4; i++) {
            int idx = i * 256 + tid;
            int row = idx >> 3, seg = idx & 7;
            uint32_t pa = (uint32_t)__cvta_generic_to_shared(da + row * GAS + seg * 8);
            uint32_t pb = (uint32_t)__cvta_generic_to_shared(db + row * GAS + seg * 8);
            asm volatile("cp.async.cg.shared.global [%0], [%1], 16;\n"
                         :: "r"(pa), "l"(ga + (size_t)row * K + seg * 8));
            asm volatile("cp.async.cg.shared.global [%0], [%1], 16;\n"
                         :: "r"(pb), "l"(gb + (size_t)row * K + seg * 8));
        }
        asm volatile("cp.async.commit_group;\n");
    };

    const int KT = K / 64;
    loadAB(0, 0);
    loadAB(1, 1);
    loadAB(2, 2);

    for (int c = 0; c < KT; c++) {
        int s = c % GSTAGES;
        if (c + 2 < KT)      asm volatile("cp.async.wait_group 2;\n");
        else if (c + 1 < KT) asm volatile("cp.async.wait_group 1;\n");
        else                 asm volatile("cp.async.wait_group 0;\n");
        __syncthreads();
        const __half* Ab = smA + s * GBUF + (wm * 32) * GAS;
        const __half* Bb = smB + s * GBUF + (wn * 64) * GAS;
#pragma unroll
        for (int ks = 0; ks < 4; ks++) {
            const int k = ks * 16 + 2 * cq;
            uint32_t a[2][4];
#pragma unroll
            for (int i = 0; i < 2; i++) {
                int r = i * 16 + g;
                a[i][0] = *(const uint32_t*)&Ab[r * GAS + k];
                a[i][1] = *(const uint32_t*)&Ab[(r + 8) * GAS + k];
                a[i][2] = *(const uint32_t*)&Ab[r * GAS + k + 8];
                a[i][3] = *(const uint32_t*)&Ab[(r + 8) * GAS + k + 8];
            }
#pragma unroll
            for (int j = 0; j < 8; j++) {
                uint32_t b0 = *(const uint32_t*)&Bb[(j * 8 + g) * GAS + k];
                uint32_t b1 = *(const uint32_t*)&Bb[(j * 8 + g) * GAS + k + 8];
#pragma unroll
                for (int i = 0; i < 2; i++) {
                    MMA16816(acc[i][j], a[i][0], a[i][1], a[i][2], a[i][3], b0, b1);
                }
            }
        }
        __syncthreads();
        if (c + GSTAGES < KT) loadAB(s, c + GSTAGES);
    }

#pragma unroll
    for (int j = 0; j < 8; j++) {
        int col = bn + wn * 64 + j * 8 + 2 * cq;
        float bx = 0.f, by = 0.f;
        if (bias) { bx = bias[col]; by = bias[col + 1]; }
#pragma unroll
        for (int i = 0; i < 2; i++) {
            int r0 = bm + wm * 32 + i * 16 + g;
            if (CoutH) {
                __half2 h0 = __floats2half2_rn(acc[i][j][0] + bx, acc[i][j][1] + by);
                __half2 h1 = __floats2half2_rn(acc[i][j][2] + bx, acc[i][j][3] + by);
                *(__half2*)&CoutH[(size_t)r0 * Nc + col] = h0;
                *(__half2*)&CoutH[(size_t)(r0 + 8) * Nc + col] = h1;
            } else {
                *(float2*)&Cout[(size_t)r0 * Nc + col] =
                    make_float2(acc[i][j][0] + bx, acc[i][j][1] + by);
                *(float2*)&Cout[(size_t)(r0 + 8) * Nc + col] =
                    make_float2(acc[i][j][2] + bx, acc[i][j][3] + by);
            }
        }
    }
}

// ---------------- weight transpose + fp16 convert: Wt[n][k] = half(W[k][n]) ------
__global__ __launch_bounds__(256) void wtrans_kernel(
    const float* __restrict__ W, __half* __restrict__ Wt, int K, int Nc)
{
    __shared__ float t[32][33];
    int k0 = blockIdx.y * 32, n0 = blockIdx.x * 32;
    int tx = threadIdx.x & 31, ty = threadIdx.x >> 5;
#pragma unroll
    for (int i = 0; i < 32; i += 8)
        t[ty + i][tx] = W[(size_t)(k0 + ty + i) * Nc + n0 + tx];
    __syncthreads();
#pragma unroll
    for (int i = 0; i < 32; i += 8)
        Wt[(size_t)(n0 + ty + i) * K + k0 + tx] = __float2half(t[tx][ty + i]);
}

// ---------------- fp32 -> fp16 cast ----------------
__global__ __launch_bounds__(256) void xconv_kernel(
    const float* __restrict__ src, __half* __restrict__ dst)
{
    size_t i = (size_t)blockIdx.x * 256 + threadIdx.x;
    float4 v0 = ((const float4*)src)[2 * i];
    float4 v1 = ((const float4*)src)[2 * i + 1];
    __half2 h0 = __floats2half2_rn(v0.x, v0.y);
    __half2 h1 = __floats2half2_rn(v0.z, v0.w);
    __half2 h2 = __floats2half2_rn(v1.x, v1.y);
    __half2 h3 = __floats2half2_rn(v1.z, v1.w);
    uint4 o;
    o.x = *(uint32_t*)&h0;
    o.y = *(uint32_t*)&h1;
    o.z = *(uint32_t*)&h2;
    o.w = *(uint32_t*)&h3;
    ((uint4*)dst)[i] = o;
}

// ---------------- 8x8 mean pool: agent[b,a,c] ----------------
__global__ __launch_bounds__(256) void pool_kernel()
{
    int idx = blockIdx.x * 256 + threadIdx.x;
    int c = idx % Cc;
    int ba = idx / Cc;
    int a = ba % AG;
    int b = ba / AG;
    int py = a / 7, px = a % 7;
    float s = 0.f;
#pragma unroll
    for (int dy = 0; dy < 8; dy++) {
        int n_base = (py * 8 + dy) * Hpix + px * 8;
#pragma unroll
        for (int dx = 0; dx < 8; dx++)
            s += g_q[((size_t)b * Nn + n_base + dx) * Cc + c];
    }
    g_agent[idx] = s * (1.0f / 64.0f);
}

// ---------------- bilinear 7x7 -> 56x56 (half-pixel centers, edge clamp) ----------
__device__ __forceinline__ float bilerp7(const float* __restrict__ t, int y, int x)
{
    float sy = (y + 0.5f) * 0.125f - 0.5f;
    float sx = (x + 0.5f) * 0.125f - 0.5f;
    int y0f = (int)floorf(sy);
    int x0f = (int)floorf(sx);
    float wy = sy - (float)y0f;
    float wx = sx - (float)x0f;
    int y0 = min(6, max(0, y0f));
    int y1 = min(6, max(0, y0f + 1));
    int x0 = min(6, max(0, x0f));
    int x1 = min(6, max(0, x0f + 1));
    float v00 = t[y0 * 7 + x0], v01 = t[y0 * 7 + x1];
    float v10 = t[y1 * 7 + x0], v11 = t[y1 * 7 + x1];
    float top = v00 + wx * (v01 - v00);
    float bot = v10 + wx * (v11 - v10);
    return top + wy * (bot - top);
}

__global__ __launch_bounds__(256) void biasak_kernel(
    const float* __restrict__ an, const float* __restrict__ ah, const float* __restrict__ aw)
{
    int idx = blockIdx.x * 256 + threadIdx.x;
    int n = idx % Nn;
    int haa = idx / Nn;
    int y = n / Hpix, x = n % Hpix;
    g_bias_ak[idx] = bilerp7(an + haa * 49, y, x) + ah[haa] + aw[haa];
}

__global__ __launch_bounds__(256) void biasqa_kernel(
    const float* __restrict__ na, const float* __restrict__ ha, const float* __restrict__ wa)
{
    int idx = blockIdx.x * 256 + threadIdx.x;
    int a = idx % AG;
    int hn = idx / AG;
    int n = hn % Nn;
    int h = hn / Nn;
    int y = n / Hpix, x = n % Hpix;
    int haa = h * AG + a;
    g_bias_qa[idx] = bilerp7(na + haa * 49, y, x) + ha[haa] + wa[haa];
}

// ---------------- stage 1 (flash, tensor cores): agent_v = softmax(a·k^T+bias)@v --
// One block per (b,h). 8 warps: wm in 0..3 = m16 agent strip, wn in 0..1 = n-half.
// Per-warp independent online softmax over its 64-col halves; end merge wn pairs.
#define FS 72     // aq/ks row stride (halves)
#define VS 136    // vs row stride (halves): frag bank = 4g + cq -> conflict-free
#define S1_AQ 0
#define S1_KS 9216
#define S1_VS 27648
#define S1_BI 45056
#define S1_SMEM (45056 + AG * 132 * 4)   // 70928 bytes

__global__ __launch_bounds__(256) void stage1_mma()
{
    extern __shared__ char sm1[];
    __half* aq = (__half*)(sm1 + S1_AQ);       // 64 x FS
    __half* ks = (__half*)(sm1 + S1_KS);       // 128 x FS
    __half* vs = (__half*)(sm1 + S1_VS);       // 64 x VS (v transposed chunk)
    float* bias_s = (float*)(sm1 + S1_BI);     // 49 x 132
    float* mrg = (float*)(sm1 + S1_KS);        // end-merge area (reuses ks)

    const int bh = blockIdx.x;
    const int b = bh / HEADS, h = bh % HEADS;
    const int tid = threadIdx.x;
    const int wid = tid >> 5, lane = tid & 31;
    const int wm = wid & 3, wn = wid >> 2;
    const int g = lane >> 2, cq = lane & 3;

    // agents (scaled, padded 49->64 with zeros)
#pragma unroll
    for (int i = 0; i < 16; i++) {
        int f = i * 256 + tid;                 // 4096 = 64 x 64
        int a = f >> 6, d = f & 63;
        float v = (a < AG) ? g_agent[((size_t)b * AG + a) * Cc + h * Dd + d] * 0.125f : 0.f;
        aq[a * FS + d] = __float2half(v);
    }

    float m0 = -1e30f, m1 = -1e30f, l0 = 0.f, l1 = 0.f;
    float o[8][4];
#pragma unroll
    for (int j = 0; j < 8; j++)
#pragma unroll
        for (int t = 0; t < 4; t++) o[j][t] = 0.f;

    const int a0r = wm * 16 + g, a1r = a0r + 8;

    for (int n0 = 0; n0 < Nn; n0 += 128) {
        __syncthreads();
        // k chunk: 128 rows x 64 d (uint4 = 8 halves)
#pragma unroll
        for (int i = 0; i < 4; i++) {
            int idx = i * 256 + tid;
            int r = idx >> 3, seg = idx & 7;
            int n = min(n0 + r, Nn - 1);
            *(uint4*)&ks[r * FS + seg * 8] =
                *(const uint4*)&g_kvh[((size_t)(b * Nn + n)) * 1024 + h * 64 + seg * 8];
        }
        // v chunk transposed via 2x2 register repack (coalesced LDG rows)
#pragma unroll
        for (int i = 0; i < 8; i++) {
            int idx = i * 256 + tid;           // 2048 = 64 npair x 32 dpair
            int dp = idx & 31, np = idx >> 5;
            int na = min(n0 + 2 * np, Nn - 1);
            int nb = min(n0 + 2 * np + 1, Nn - 1);
            __half2 x = *(const __half2*)&g_kvh[((size_t)(b * Nn + na)) * 1024 + 512 + h * 64 + dp * 2];
            __half2 y = *(const __half2*)&g_kvh[((size_t)(b * Nn + nb)) * 1024 + 512 + h * 64 + dp * 2];
            *(__half2*)&vs[(2 * dp) * VS + 2 * np] = __lows2half2(x, y);
            *(__half2*)&vs[(2 * dp + 1) * VS + 2 * np] = __highs2half2(x, y);
        }
        // bias chunk 49 x 128 (coalesced rows)
        for (int f = tid; f < AG * 128; f += 256) {
            int a = f >> 7, nl = f & 127;
            int n = n0 + nl;
            bias_s[a * 132 + nl] = (n < Nn) ? g_bias_ak[((size_t)(h * AG + a)) * Nn + n] : 0.f;
        }
        __syncthreads();

        // ---- S = agents @ k^T ----
        float s[8][4];
#pragma unroll
        for (int j = 0; j < 8; j++)
#pragma unroll
            for (int t = 0; t < 4; t++) s[j][t] = 0.f;
#pragma unroll
        for (int t = 0; t < 4; t++) {
            int kk = t * 16 + 2 * cq;
            uint32_t A0 = *(const uint32_t*)&aq[(wm * 16 + g) * FS + kk];
            uint32_t A1 = *(const uint32_t*)&aq[(wm * 16 + g + 8) * FS + kk];
            uint32_t A2 = *(const uint32_t*)&aq[(wm * 16 + g) * FS + kk + 8];
            uint32_t A3 = *(const uint32_t*)&aq[(wm * 16 + g + 8) * FS + kk + 8];
#pragma unroll
            for (int j = 0; j < 8; j++) {
                int row = wn * 64 + j * 8 + g;
                uint32_t b0 = *(const uint32_t*)&ks[row * FS + kk];
                uint32_t b1 = *(const uint32_t*)&ks[row * FS + kk + 8];
                MMA16816(s[j], A0, A1, A2, A3, b0, b1);
            }
        }

        // ---- bias + mask + online softmax (per-warp, its own 64-col half) ----
        float cm0 = -1e30f, cm1 = -1e30f;
#pragma unroll
        for (int j = 0; j < 8; j++) {
            int nl = wn * 64 + j * 8 + 2 * cq;
            int n = n0 + nl;
            bool v0 = (n < Nn), v1 = (n + 1 < Nn);
            float ba00 = (a0r < AG) ? bias_s[a0r * 132 + nl] : 0.f;
            float ba01 = (a0r < AG) ? bias_s[a0r * 132 + nl + 1] : 0.f;
            float ba10 = (a1r < AG) ? bias_s[a1r * 132 + nl] : 0.f;
            float ba11 = (a1r < AG) ? bias_s[a1r * 132 + nl + 1] : 0.f;
            s[j][0] = v0 ? s[j][0] + ba00 : -1e30f;
            s[j][1] = v1 ? s[j][1] + ba01 : -1e30f;
            s[j][2] = v0 ? s[j][2] + ba10 : -1e30f;
            s[j][3] = v1 ? s[j][3] + ba11 : -1e30f;
            cm0 = fmaxf(cm0, fmaxf(s[j][0], s[j][1]));
            cm1 = fmaxf(cm1, fmaxf(s[j][2], s[j][3]));
        }
        cm0 = fmaxf(cm0, __shfl_xor_sync(0xffffffffu, cm0, 1));
        cm0 = fmaxf(cm0, __shfl_xor_sync(0xffffffffu, cm0, 2));
        cm1 = fmaxf(cm1, __shfl_xor_sync(0xffffffffu, cm1, 1));
        cm1 = fmaxf(cm1, __shfl_xor_sync(0xffffffffu, cm1, 2));

        float M0 = fmaxf(m0, cm0), M1 = fmaxf(m1, cm1);
        float r0 = __expf(m0 - M0), r1 = __expf(m1 - M1);
        float sum0 = 0.f, sum1 = 0.f;
#pragma unroll
        for (int j = 0; j < 8; j++) {
            s[j][0] = __expf(s[j][0] - M0);
            s[j][1] = __expf(s[j][1] - M0);
            s[j][2] = __expf(s[j][2] - M1);
            s[j][3] = __expf(s[j][3] - M1);
            sum0 += s[j][0] + s[j][1];
            sum1 += s[j][2] + s[j][3];
        }
        sum0 += __shfl_xor_sync(0xffffffffu, sum0, 1);
        sum0 += __shfl_xor_sync(0xffffffffu, sum0, 2);
        sum1 += __shfl_xor_sync(0xffffffffu, sum1, 1);
        sum1 += __shfl_xor_sync(0xffffffffu, sum1, 2);
        l0 = l0 * r0 + sum0;
        l1 = l1 * r1 + sum1;
        m0 = M0;
        m1 = M1;
#pragma unroll
        for (int j = 0; j < 8; j++) {
            o[j][0] *= r0; o[j][1] *= r0;
            o[j][2] *= r1; o[j][3] *= r1;
        }

        // ---- repack P -> A-frags (k16 tile t = C n-tiles 2t,2t+1) ----
        uint32_t pa[4][4];
#pragma unroll
        for (int t = 0; t < 4; t++) {
            __half2 h0 = __floats2half2_rn(s[2 * t][0], s[2 * t][1]);
            __half2 h1 = __floats2half2_rn(s[2 * t][2], s[2 * t][3]);
            __half2 h2 = __floats2half2_rn(s[2 * t + 1][0], s[2 * t + 1][1]);
            __half2 h3 = __floats2half2_rn(s[2 * t + 1][2], s[2 * t + 1][3]);
            pa[t][0] = *(uint32_t*)&h0;
            pa[t][1] = *(uint32_t*)&h1;
            pa[t][2] = *(uint32_t*)&h2;
            pa[t][3] = *(uint32_t*)&h3;
        }

        // ---- O += P @ V (V^T in smem: rows = d, k = this warp's n-half) ----
#pragma unroll
        for (int t = 0; t < 4; t++) {
            int kk = wn * 64 + t * 16 + 2 * cq;
#pragma unroll
            for (int j = 0; j < 8; j++) {
                uint32_t b0 = *(const uint32_t*)&vs[(j * 8 + g) * VS + kk];
                uint32_t b1 = *(const uint32_t*)&vs[(j * 8 + g) * VS + kk + 8];
                MMA16816(o[j], pa[t][0], pa[t][1], pa[t][2], pa[t][3], b0, b1);
            }
        }
    }

    // ---- merge wn=1 partials into wn=0 and store ----
    __syncthreads();
    float* p = mrg + ((size_t)(wm * 32 + lane)) * 36;
    if (wn == 1) {
#pragma unroll
        for (int j = 0; j < 8; j++) {
            p[4 * j] = o[j][0]; p[4 * j + 1] = o[j][1];
            p[4 * j + 2] = o[j][2]; p[4 * j + 3] = o[j][3];
        }
        p[32] = m0; p[33] = m1; p[34] = l0; p[35] = l1;
    }
    __syncthreads();
    if (wn == 0) {
        float pm0 = p[32], pm1 = p[33], pl0 = p[34], pl1 = p[35];
        float M0 = fmaxf(m0, pm0), M1 = fmaxf(m1, pm1);
        float ra0 = __expf(m0 - M0), rb0 = __expf(pm0 - M0);
        float ra1 = __expf(m1 - M1), rb1 = __expf(pm1 - M1);
        float i0 = 1.0f / (l0 * ra0 + pl0 * rb0);
        float i1 = 1.0f / (l1 * ra1 + pl1 * rb1);
#pragma unroll
        for (int j = 0; j < 8; j++) {
            int d = j * 8 + 2 * cq;
            if (a0r < AG) {
                float2 v = make_float2((o[j][0] * ra0 + p[4 * j] * rb0) * i0,
                                       (o[j][1] * ra0 + p[4 * j + 1] * rb0) * i0);
                *(float2*)&g_agentv[((size_t)bh * AG + a0r) * Dd + d] = v;
            }
            if (a1r < AG) {
                float2 v = make_float2((o[j][2] * ra1 + p[4 * j + 2] * rb1) * i1,
                                       (o[j][3] * ra1 + p[4 * j + 3] * rb1) * i1);
                *(float2*)&g_agentv[((size_t)bh * AG + a1r) * Dd + d] = v;
            }
        }
    }
}

// ---------------- stage 2 (tensor-core fused): softmax(q·a^T + bias) @ agent_v ----
#define S2S 72
__global__ __launch_bounds__(256) void stage2_mma()
{
    __shared__ __half qh[128 * S2S];
    __shared__ __half a4h[64 * S2S];
    __shared__ __half avh[64 * S2S];
    const int bh = blockIdx.y;
    const int b = bh / HEADS, h = bh % HEADS;
    const int n0 = blockIdx.x * 128;
    const int tid = threadIdx.x;
    const int wid = tid >> 5, lane = tid & 31;
    const int g = lane >> 2, cq = lane & 3;

#pragma unroll
    for (int i = 0; i < 8; i++) {
        int idx = i * 256 + tid;
        int r = idx >> 4, seg = idx & 15;
        int n = min(n0 + r, Nn - 1);
        float4 v = *(const float4*)&g_q[((size_t)(b * Nn + n)) * Cc + h * Dd + seg * 4];
        __half2 h0 = __floats2half2_rn(v.x, v.y);
        __half2 h1 = __floats2half2_rn(v.z, v.w);
        *(__half2*)&qh[r * S2S + seg * 4] = h0;
        *(__half2*)&qh[r * S2S + seg * 4 + 2] = h1;
    }
#pragma unroll
    for (int i = 0; i < 16; i++) {
        int idx = i * 256 + tid;
        int a = idx >> 6, d = idx & 63;
        float av = (a < AG) ? g_agent[((size_t)b * AG + a) * Cc + h * Dd + d] * 0.125f : 0.f;
        float vv = (a < AG) ? g_agentv[((size_t)bh * AG + a) * Dd + d] : 0.f;
        a4h[a * S2S + d] = __float2half(av);
        avh[d * S2S + a] = __float2half(vv);
    }
    __syncthreads();

    float s[8][4];
#pragma unroll
    for (int j = 0; j < 8; j++)
#pragma unroll
        for (int t = 0; t < 4; t++) s[j][t] = 0.f;

    const __half* qa = qh + (wid * 16) * S2S;
#pragma unroll
    for (int t = 0; t < 4; t++) {
        int k = t * 16 + 2 * cq;
        uint32_t a0 = *(const uint32_t*)&qa[g * S2S + k];
        uint32_t a1 = *(const uint32_t*)&qa[(g + 8) * S2S + k];
        uint32_t a2 = *(const uint32_t*)&qa[g * S2S + k + 8];
        uint32_t a3 = *(const uint32_t*)&qa[(g + 8) * S2S + k + 8];
#pragma unroll
        for (int j = 0; j < 8; j++) {
            uint32_t b0 = *(const uint32_t*)&a4h[(j * 8 + g) * S2S + k];
            uint32_t b1 = *(const uint32_t*)&a4h[(j * 8 + g) * S2S + k + 8];
            MMA16816(s[j], a0, a1, a2, a3, b0, b1);
        }
    }

    const int r0 = n0 + wid * 16 + g;
    const int r1 = r0 + 8;
    float m0 = -1e30f, m1 = -1e30f;
#pragma unroll
    for (int j = 0; j < 8; j++) {
        int a = 8 * j + 2 * cq;
        if (a < AG) {
            float b00 = (r0 < Nn) ? g_bias_qa[((size_t)h * Nn + r0) * AG + a] : 0.f;
            float b10 = (r1 < Nn) ? g_bias_qa[((size_t)h * Nn + r1) * AG + a] : 0.f;
            s[j][0] += b00;
            s[j][2] += b10;
            if (a + 1 < AG) {
                float b01 = (r0 < Nn) ? g_bias_qa[((size_t)h * Nn + r0) * AG + a + 1] : 0.f;
                float b11 = (r1 < Nn) ? g_bias_qa[((size_t)h * Nn + r1) * AG + a + 1] : 0.f;
                s[j][1] += b01;
                s[j][3] += b11;
            } else {
                s[j][1] = -1e30f;
                s[j][3] = -1e30f;
            }
        } else {
            s[j][0] = -1e30f; s[j][1] = -1e30f;
            s[j][2] = -1e30f; s[j][3] = -1e30f;
        }
        m0 = fmaxf(m0, fmaxf(s[j][0], s[j][1]));
        m1 = fmaxf(m1, fmaxf(s[j][2], s[j][3]));
    }
    m0 = fmaxf(m0, __shfl_xor_sync(0xffffffffu, m0, 1));
    m0 = fmaxf(m0, __shfl_xor_sync(0xffffffffu, m0, 2));
    m1 = fmaxf(m1, __shfl_xor_sync(0xffffffffu, m1, 1));
    m1 = fmaxf(m1, __shfl_xor_sync(0xffffffffu, m1, 2));

    float sum0 = 0.f, sum1 = 0.f;
#pragma unroll
    for (int j = 0; j < 8; j++) {
        s[j][0] = __expf(s[j][0] - m0);
        s[j][1] = __expf(s[j][1] - m0);
        s[j][2] = __expf(s[j][2] - m1);
        s[j][3] = __expf(s[j][3] - m1);
        sum0 += s[j][0] + s[j][1];
        sum1 += s[j][2] + s[j][3];
    }
    sum0 += __shfl_xor_sync(0xffffffffu, sum0, 1);
    sum0 += __shfl_xor_sync(0xffffffffu, sum0, 2);
    sum1 += __shfl_xor_sync(0xffffffffu, sum1, 1);
    sum1 += __shfl_xor_sync(0xffffffffu, sum1, 2);
    const float inv0 = 1.0f / sum0, inv1 = 1.0f / sum1;

    uint32_t pa[4][4];
#pragma unroll
    for (int t = 0; t < 4; t++) {
        __half2 h0 = __floats2half2_rn(s[2 * t][0], s[2 * t][1]);
        __half2 h1 = __floats2half2_rn(s[2 * t][2], s[2 * t][3]);
        __half2 h2 = __floats2half2_rn(s[2 * t + 1][0], s[2 * t + 1][1]);
        __half2 h3 = __floats2half2_rn(s[2 * t + 1][2], s[2 * t + 1][3]);
        pa[t][0] = *(uint32_t*)&h0;
        pa[t][1] = *(uint32_t*)&h1;
        pa[t][2] = *(uint32_t*)&h2;
        pa[t][3] = *(uint32_t*)&h3;
    }

    float o[8][4];
#pragma unroll
    for (int j = 0; j < 8; j++)
#pragma unroll
        for (int t = 0; t < 4; t++) o[j][t] = 0.f;
#pragma unroll
    for (int t = 0; t < 4; t++) {
        int k = t * 16 + 2 * cq;
#pragma unroll
        for (int j = 0; j < 8; j++) {
            uint32_t b0 = *(const uint32_t*)&avh[(j * 8 + g) * S2S + k];
            uint32_t b1 = *(const uint32_t*)&avh[(j * 8 + g) * S2S + k + 8];
            MMA16816(o[j], pa[t][0], pa[t][1], pa[t][2], pa[t][3], b0, b1);
        }
    }

#pragma unroll
    for (int j = 0; j < 8; j++) {
        int d = 8 * j + 2 * cq;
        if (r0 < Nn)
            *(float2*)&g_acc[((size_t)(b * Nn + r0)) * Cc + h * Dd + d] =
                make_float2(o[j][0] * inv0, o[j][1] * inv0);
        if (r1 < Nn)
            *(float2*)&g_acc[((size_t)(b * Nn + r1)) * Cc + h * Dd + d] =
                make_float2(o[j][2] * inv1, o[j][3] * inv1);
    }
}

// ---------------- depthwise 3x3 conv on v (fp16) + add attn out -> fp16 ----------
__global__ __launch_bounds__(256) void dwc_kernel(
    const float* __restrict__ w, const float* __restrict__ bias)
{
    size_t idx = (size_t)blockIdx.x * 256 + threadIdx.x;
    int c = (int)(idx % Cc);
    size_t bnv = idx / Cc;
    int n = (int)(bnv % Nn);
    int b = (int)(bnv / Nn);
    int y = n / Hpix, x = n % Hpix;
    float s = bias[c];
#pragma unroll
    for (int dy = -1; dy <= 1; dy++) {
        int yy = y + dy;
        if (yy < 0 || yy >= Hpix) continue;
#pragma unroll
        for (int dx = -1; dx <= 1; dx++) {
            int xx = x + dx;
            if (xx < 0 || xx >= Hpix) continue;
            float vv = __half2float(g_kvh[((size_t)(b * Nn + yy * Hpix + xx)) * 1024 + 512 + c]);
            s = fmaf(vv, w[c * 9 + (dy + 1) * 3 + (dx + 1)], s);
        }
    }
    g_acch[idx] = __float2half(g_acc[idx] + s);
}

// ---------------- launch ----------------
extern "C" void kernel_launch(void* const* d_in, const int* in_sizes, int n_in,
                              void* d_out, int out_size)
{
    const float* x      = (const float*)d_in[0];
    const float* q_w    = (const float*)d_in[1];
    const float* kv_w   = (const float*)d_in[2];
    const float* proj_w = (const float*)d_in[3];
    const float* proj_b = (const float*)d_in[4];
    const float* dwc_w  = (const float*)d_in[5];
    const float* dwc_b  = (const float*)d_in[6];
    const float* an_b   = (const float*)d_in[7];
    const float* na_b   = (const float*)d_in[8];
    const float* ah     = (const float*)d_in[9];
    const float* aw     = (const float*)d_in[10];
    const float* ha     = (const float*)d_in[11];
    const float* wa     = (const float*)d_in[12];

    float* qp;
    __half *xhp, *kvhp, *acchp, *wtp;
    cudaGetSymbolAddress((void**)&qp, g_q);
    cudaGetSymbolAddress((void**)&kvhp, g_kvh);
    cudaGetSymbolAddress((void**)&xhp, g_xh);
    cudaGetSymbolAddress((void**)&acchp, g_acch);
    cudaGetSymbolAddress((void**)&wtp, g_wTh);

    cudaFuncSetAttribute(gemm_h, cudaFuncAttributeMaxDynamicSharedMemorySize, GT_SMEM);
    cudaFuncSetAttribute(stage1_mma, cudaFuncAttributeMaxDynamicSharedMemorySize, S1_SMEM);

    const int M = Bn * Nn;  // 50176

    wtrans_kernel<<<dim3(512 / 32, 512 / 32), 256>>>(q_w, wtp + WT_Q, 512, 512);
    wtrans_kernel<<<dim3(1024 / 32, 512 / 32), 256>>>(kv_w, wtp + WT_KV, 512, 1024);
    wtrans_kernel<<<dim3(512 / 32, 512 / 32), 256>>>(proj_w, wtp + WT_PROJ, 512, 512);
    xconv_kernel<<<(int)(((size_t)M * Cc / 8) / 256), 256>>>(x, xhp);

    gemm_h<<<dim3(512 / 128, M / 128), 256, GT_SMEM>>>(xhp, wtp + WT_Q, qp, nullptr, M, Cc, Cc, nullptr);
    gemm_h<<<dim3(1024 / 128, M / 128), 256, GT_SMEM>>>(xhp, wtp + WT_KV, nullptr, kvhp, M, Cc, 2 * Cc, nullptr);
    pool_kernel<<<(Bn * AG * Cc) / 256, 256>>>();
    biasak_kernel<<<(HEADS * AG * Nn) / 256, 256>>>(an_b, ah, aw);
    biasqa_kernel<<<(HEADS * Nn * AG) / 256, 256>>>(na_b, ha, wa);
    stage1_mma<<<Bn * HEADS, 256, S1_SMEM>>>();
    stage2_mma<<<dim3(25, Bn * HEADS), 256>>>();
    dwc_kernel<<<(int)(((size_t)Bn * Nn * Cc) / 256), 256>>>(dwc_w, dwc_b);
    gemm_h<<<dim3(512 / 128, M / 128), 256, GT_SMEM>>>(acchp, wtp + WT_PROJ, (float*)d_out, nullptr, M, Cc, Cc, proj_b);
}

// round 8
// speedup vs baseline: 4.4620x; 1.0010x over previous
#include <cuda_runtime.h>
#include <cuda_fp16.h>
#include <cstdint>
#include <math.h>

#define Bn 16
#define Nn 3136
#define Cc 512
#define Hpix 56
#define HEADS 8
#define Dd 64
#define AG 49

// ---------------- scratch (device globals; no allocation allowed) ----------------
__device__ __half g_qh[(size_t)Bn * Nn * Cc];          // q in fp16 (b,n,c)
__device__ __half g_kvh[(size_t)Bn * Nn * 2 * Cc];     // (b,n,2c) fp16: k | v
__device__ float g_agent[(size_t)Bn * AG * Cc];        // (b,a,c)
__device__ float g_bias_ak[(size_t)HEADS * AG * Nn];   // (h,a,n)
__device__ float g_bias_qa[(size_t)HEADS * Nn * AG];   // (h,n,a)
__device__ float g_agentv[(size_t)Bn * HEADS * AG * Dd];
__device__ __half g_xh[(size_t)Bn * Nn * Cc];          // x in fp16
__device__ __half g_acch[(size_t)Bn * Nn * Cc];        // attn out, then += dwc
// transposed fp16 weights: qT [512x512] | kvT [1024x512] | projT [512x512], K-major
__device__ __half g_wTh[(size_t)2048 * 512];
#define WT_Q 0
#define WT_KV (512 * 512)
#define WT_PROJ (512 * 512 + 1024 * 512)

#define MMA16816(acc, a0, a1, a2, a3, b0, b1)                                   \
    asm volatile(                                                               \
        "mma.sync.aligned.m16n8k16.row.col.f32.f16.f16.f32 "                    \
        "{%0,%1,%2,%3}, {%4,%5,%6,%7}, {%8,%9}, {%0,%1,%2,%3};"                 \
        : "+f"(acc[0]), "+f"(acc[1]), "+f"(acc[2]), "+f"(acc[3])                \
        : "r"(a0), "r"(a1), "r"(a2), "r"(a3), "r"(b0), "r"(b1))

#define LDSM_X4(r0, r1, r2, r3, addr)                                           \
    asm volatile("ldmatrix.sync.aligned.m8n8.x4.shared.b16 {%0,%1,%2,%3}, [%4];" \
                 : "=r"(r0), "=r"(r1), "=r"(r2), "=r"(r3) : "r"(addr))

// ---------------- fp16 tensor-core GEMM: C = A[M,K] @ Bt[Nc,K]^T (+bias) ----------
// BM=BN=128 BK=64, 8 warps, 3-stage cp.async, ldmatrix fragment loads.
#define GAS 72
#define GBUF (128 * GAS)
#define GSTAGES 3
#define GT_SMEM (GSTAGES * 2 * GBUF * 2)   // 110592 bytes

__global__ __launch_bounds__(256, 2) void gemm_h(
    const __half* __restrict__ A, const __half* __restrict__ Bt,
    float* __restrict__ Cout, __half* __restrict__ CoutH,
    int M, int K, int Nc, const float* __restrict__ bias)
{
    extern __shared__ __half smh[];
    __half* smA = smh;
    __half* smB = smh + GSTAGES * GBUF;
    const int tid = threadIdx.x;
    const int wid = tid >> 5, lane = tid & 31;
    const int wm = wid & 3, wn = wid >> 2;
    const int g = lane >> 2, cq = lane & 3;
    const int bm = blockIdx.y * 128, bn = blockIdx.x * 128;

    // ldmatrix per-lane base addresses (bytes): rows lane&15, k-half (lane>>4)*8
    const uint32_t smA_u = (uint32_t)__cvta_generic_to_shared(smA);
    const uint32_t smB_u = (uint32_t)__cvta_generic_to_shared(smB);
    const uint32_t aRow = wm * 32 + (lane & 15);
    const uint32_t bRow = wn * 64 + (lane & 15);
    const uint32_t kHalf = (lane >> 4) * 16;       // bytes
    const uint32_t aOff = aRow * GAS * 2 + kHalf;
    const uint32_t bOff = bRow * GAS * 2 + kHalf;

    float acc[2][8][4];
#pragma unroll
    for (int i = 0; i < 2; i++)
#pragma unroll
        for (int j = 0; j < 8; j++)
#pragma unroll
            for (int t = 0; t < 4; t++) acc[i][j][t] = 0.f;

    auto loadAB = [&](int s, int kc) {
        const __half* ga = A + (size_t)bm * K + kc * 64;
        const __half* gb = Bt + (size_t)bn * K + kc * 64;
        __half* da = smA + s * GBUF;
        __half* db = smB + s * GBUF;
#pragma unroll
        for (int i = 0; i < 4; i++) {
            int idx = i * 256 + tid;
            int row = idx >> 3, seg = idx & 7;
            uint32_t pa = (uint32_t)__cvta_generic_to_shared(da + row * GAS + seg * 8);
            uint32_t pb = (uint32_t)__cvta_generic_to_shared(db + row * GAS + seg * 8);
            asm volatile("cp.async.cg.shared.global [%0], [%1], 16;\n"
                         :: "r"(pa), "l"(ga + (size_t)row * K + seg * 8));
            asm volatile("cp.async.cg.shared.global [%0], [%1], 16;\n"
                         :: "r"(pb), "l"(gb + (size_t)row * K + seg * 8));
        }
        asm volatile("cp.async.commit_group;\n");
    };

    const int KT = K / 64;
    loadAB(0, 0);
    loadAB(1, 1);
    loadAB(2, 2);

    for (int c = 0; c < KT; c++) {
        int s = c % GSTAGES;
        if (c + 2 < KT)      asm volatile("cp.async.wait_group 2;\n");
        else if (c + 1 < KT) asm volatile("cp.async.wait_group 1;\n");
        else                 asm volatile("cp.async.wait_group 0;\n");
        __syncthreads();
        const uint32_t aP = smA_u + s * (GBUF * 2) + aOff;
        const uint32_t bP = smB_u + s * (GBUF * 2) + bOff;
#pragma unroll
        for (int ks = 0; ks < 4; ks++) {
            const uint32_t kb = ks * 32;           // bytes per k16 step
            uint32_t a[2][4];
            LDSM_X4(a[0][0], a[0][1], a[0][2], a[0][3], aP + kb);
            LDSM_X4(a[1][0], a[1][1], a[1][2], a[1][3], aP + 16 * GAS * 2 + kb);
#pragma unroll
            for (int jj = 0; jj < 4; jj++) {
                uint32_t rb0, rb1, rb2, rb3;       // b0(2jj), b0(2jj+1), b1(2jj), b1(2jj+1)
                LDSM_X4(rb0, rb1, rb2, rb3, bP + jj * (16 * GAS * 2) + kb);
#pragma unroll
                for (int i = 0; i < 2; i++) {
                    MMA16816(acc[i][2 * jj],     a[i][0], a[i][1], a[i][2], a[i][3], rb0, rb2);
                    MMA16816(acc[i][2 * jj + 1], a[i][0], a[i][1], a[i][2], a[i][3], rb1, rb3);
                }
            }
        }
        __syncthreads();
        if (c + GSTAGES < KT) loadAB(s, c + GSTAGES);
    }

#pragma unroll
    for (int j = 0; j < 8; j++) {
        int col = bn + wn * 64 + j * 8 + 2 * cq;
        float bx = 0.f, by = 0.f;
        if (bias) { bx = bias[col]; by = bias[col + 1]; }
#pragma unroll
        for (int i = 0; i < 2; i++) {
            int r0 = bm + wm * 32 + i * 16 + g;
            if (CoutH) {
                __half2 h0 = __floats2half2_rn(acc[i][j][0] + bx, acc[i][j][1] + by);
                __half2 h1 = __floats2half2_rn(acc[i][j][2] + bx, acc[i][j][3] + by);
                *(__half2*)&CoutH[(size_t)r0 * Nc + col] = h0;
                *(__half2*)&CoutH[(size_t)(r0 + 8) * Nc + col] = h1;
            } else {
                *(float2*)&Cout[(size_t)r0 * Nc + col] =
                    make_float2(acc[i][j][0] + bx, acc[i][j][1] + by);
                *(float2*)&Cout[(size_t)(r0 + 8) * Nc + col] =
                    make_float2(acc[i][j][2] + bx, acc[i][j][3] + by);
            }
        }
    }
}

// ---------------- weight transpose + fp16 convert: Wt[n][k] = half(W[k][n]) ------
__global__ __launch_bounds__(256) void wtrans_kernel(
    const float* __restrict__ W, __half* __restrict__ Wt, int K, int Nc)
{
    __shared__ float t[32][33];
    int k0 = blockIdx.y * 32, n0 = blockIdx.x * 32;
    int tx = threadIdx.x & 31, ty = threadIdx.x >> 5;
#pragma unroll
    for (int i = 0; i < 32; i += 8)
        t[ty + i][tx] = W[(size_t)(k0 + ty + i) * Nc + n0 + tx];
    __syncthreads();
#pragma unroll
    for (int i = 0; i < 32; i += 8)
        Wt[(size_t)(n0 + ty + i) * K + k0 + tx] = __float2half(t[tx][ty + i]);
}

// ---------------- fp32 -> fp16 cast ----------------
__global__ __launch_bounds__(256) void xconv_kernel(
    const float* __restrict__ src, __half* __restrict__ dst)
{
    size_t i = (size_t)blockIdx.x * 256 + threadIdx.x;
    float4 v0 = ((const float4*)src)[2 * i];
    float4 v1 = ((const float4*)src)[2 * i + 1];
    __half2 h0 = __floats2half2_rn(v0.x, v0.y);
    __half2 h1 = __floats2half2_rn(v0.z, v0.w);
    __half2 h2 = __floats2half2_rn(v1.x, v1.y);
    __half2 h3 = __floats2half2_rn(v1.z, v1.w);
    uint4 o;
    o.x = *(uint32_t*)&h0;
    o.y = *(uint32_t*)&h1;
    o.z = *(uint32_t*)&h2;
    o.w = *(uint32_t*)&h3;
    ((uint4*)dst)[i] = o;
}

// ---------------- 8x8 mean pool on fp16 q: agent[b,a,c] ----------------
__global__ __launch_bounds__(256) void pool_kernel()
{
    int idx = blockIdx.x * 256 + threadIdx.x;
    int c = idx % Cc;
    int ba = idx / Cc;
    int a = ba % AG;
    int b = ba / AG;
    int py = a / 7, px = a % 7;
    float s = 0.f;
#pragma unroll
    for (int dy = 0; dy < 8; dy++) {
        int n_base = (py * 8 + dy) * Hpix + px * 8;
#pragma unroll
        for (int dx = 0; dx < 8; dx++)
            s += __half2float(g_qh[((size_t)b * Nn + n_base + dx) * Cc + c]);
    }
    g_agent[idx] = s * (1.0f / 64.0f);
}

// ---------------- bilinear 7x7 -> 56x56 (half-pixel centers, edge clamp) ----------
__device__ __forceinline__ float bilerp7(const float* __restrict__ t, int y, int x)
{
    float sy = (y + 0.5f) * 0.125f - 0.5f;
    float sx = (x + 0.5f) * 0.125f - 0.5f;
    int y0f = (int)floorf(sy);
    int x0f = (int)floorf(sx);
    float wy = sy - (float)y0f;
    float wx = sx - (float)x0f;
    int y0 = min(6, max(0, y0f));
    int y1 = min(6, max(0, y0f + 1));
    int x0 = min(6, max(0, x0f));
    int x1 = min(6, max(0, x0f + 1));
    float v00 = t[y0 * 7 + x0], v01 = t[y0 * 7 + x1];
    float v10 = t[y1 * 7 + x0], v11 = t[y1 * 7 + x1];
    float top = v00 + wx * (v01 - v00);
    float bot = v10 + wx * (v11 - v10);
    return top + wy * (bot - top);
}

__global__ __launch_bounds__(256) void biasak_kernel(
    const float* __restrict__ an, const float* __restrict__ ah, const float* __restrict__ aw)
{
    int idx = blockIdx.x * 256 + threadIdx.x;
    int n = idx % Nn;
    int haa = idx / Nn;
    int y = n / Hpix, x = n % Hpix;
    g_bias_ak[idx] = bilerp7(an + haa * 49, y, x) + ah[haa] + aw[haa];
}

__global__ __launch_bounds__(256) void biasqa_kernel(
    const float* __restrict__ na, const float* __restrict__ ha, const float* __restrict__ wa)
{
    int idx = blockIdx.x * 256 + threadIdx.x;
    int a = idx % AG;
    int hn = idx / AG;
    int n = hn % Nn;
    int h = hn / Nn;
    int y = n / Hpix, x = n % Hpix;
    int haa = h * AG + a;
    g_bias_qa[idx] = bilerp7(na + haa * 49, y, x) + ha[haa] + wa[haa];
}

// ---------------- stage 1 (flash, tensor cores): agent_v = softmax(a·k^T+bias)@v --
#define FS 72
#define VS 136
#define S1_AQ 0
#define S1_KS 9216
#define S1_VS 27648
#define S1_BI 45056
#define S1_SMEM (45056 + AG * 132 * 4)   // 70928 bytes

__global__ __launch_bounds__(256) void stage1_mma()
{
    extern __shared__ char sm1[];
    __half* aq = (__half*)(sm1 + S1_AQ);
    __half* ks = (__half*)(sm1 + S1_KS);
    __half* vs = (__half*)(sm1 + S1_VS);
    float* bias_s = (float*)(sm1 + S1_BI);
    float* mrg = (float*)(sm1 + S1_KS);

    const int bh = blockIdx.x;
    const int b = bh / HEADS, h = bh % HEADS;
    const int tid = threadIdx.x;
    const int wid = tid >> 5, lane = tid & 31;
    const int wm = wid & 3, wn = wid >> 2;
    const int g = lane >> 2, cq = lane & 3;

#pragma unroll
    for (int i = 0; i < 16; i++) {
        int f = i * 256 + tid;
        int a = f >> 6, d = f & 63;
        float v = (a < AG) ? g_agent[((size_t)b * AG + a) * Cc + h * Dd + d] * 0.125f : 0.f;
        aq[a * FS + d] = __float2half(v);
    }

    float m0 = -1e30f, m1 = -1e30f, l0 = 0.f, l1 = 0.f;
    float o[8][4];
#pragma unroll
    for (int j = 0; j < 8; j++)
#pragma unroll
        for (int t = 0; t < 4; t++) o[j][t] = 0.f;

    const int a0r = wm * 16 + g, a1r = a0r + 8;

    for (int n0 = 0; n0 < Nn; n0 += 128) {
        __syncthreads();
#pragma unroll
        for (int i = 0; i < 4; i++) {
            int idx = i * 256 + tid;
            int r = idx >> 3, seg = idx & 7;
            int n = min(n0 + r, Nn - 1);
            *(uint4*)&ks[r * FS + seg * 8] =
                *(const uint4*)&g_kvh[((size_t)(b * Nn + n)) * 1024 + h * 64 + seg * 8];
        }
#pragma unroll
        for (int i = 0; i < 8; i++) {
            int idx = i * 256 + tid;
            int dp = idx & 31, np = idx >> 5;
            int na = min(n0 + 2 * np, Nn - 1);
            int nb = min(n0 + 2 * np + 1, Nn - 1);
            __half2 x = *(const __half2*)&g_kvh[((size_t)(b * Nn + na)) * 1024 + 512 + h * 64 + dp * 2];
            __half2 y = *(const __half2*)&g_kvh[((size_t)(b * Nn + nb)) * 1024 + 512 + h * 64 + dp * 2];
            *(__half2*)&vs[(2 * dp) * VS + 2 * np] = __lows2half2(x, y);
            *(__half2*)&vs[(2 * dp + 1) * VS + 2 * np] = __highs2half2(x, y);
        }
        for (int f = tid; f < AG * 128; f += 256) {
            int a = f >> 7, nl = f & 127;
            int n = n0 + nl;
            bias_s[a * 132 + nl] = (n < Nn) ? g_bias_ak[((size_t)(h * AG + a)) * Nn + n] : 0.f;
        }
        __syncthreads();

        float s[8][4];
#pragma unroll
        for (int j = 0; j < 8; j++)
#pragma unroll
            for (int t = 0; t < 4; t++) s[j][t] = 0.f;
#pragma unroll
        for (int t = 0; t < 4; t++) {
            int kk = t * 16 + 2 * cq;
            uint32_t A0 = *(const uint32_t*)&aq[(wm * 16 + g) * FS + kk];
            uint32_t A1 = *(const uint32_t*)&aq[(wm * 16 + g + 8) * FS + kk];
            uint32_t A2 = *(const uint32_t*)&aq[(wm * 16 + g) * FS + kk + 8];
            uint32_t A3 = *(const uint32_t*)&aq[(wm * 16 + g + 8) * FS + kk + 8];
#pragma unroll
            for (int j = 0; j < 8; j++) {
                int row = wn * 64 + j * 8 + g;
                uint32_t b0 = *(const uint32_t*)&ks[row * FS + kk];
                uint32_t b1 = *(const uint32_t*)&ks[row * FS + kk + 8];
                MMA16816(s[j], A0, A1, A2, A3, b0, b1);
            }
        }

        float cm0 = -1e30f, cm1 = -1e30f;
#pragma unroll
        for (int j = 0; j < 8; j++) {
            int nl = wn * 64 + j * 8 + 2 * cq;
            int n = n0 + nl;
            bool v0 = (n < Nn), v1 = (n + 1 < Nn);
            float ba00 = (a0r < AG) ? bias_s[a0r * 132 + nl] : 0.f;
            float ba01 = (a0r < AG) ? bias_s[a0r * 132 + nl + 1] : 0.f;
            float ba10 = (a1r < AG) ? bias_s[a1r * 132 + nl] : 0.f;
            float ba11 = (a1r < AG) ? bias_s[a1r * 132 + nl + 1] : 0.f;
            s[j][0] = v0 ? s[j][0] + ba00 : -1e30f;
            s[j][1] = v1 ? s[j][1] + ba01 : -1e30f;
            s[j][2] = v0 ? s[j][2] + ba10 : -1e30f;
            s[j][3] = v1 ? s[j][3] + ba11 : -1e30f;
            cm0 = fmaxf(cm0, fmaxf(s[j][0], s[j][1]));
            cm1 = fmaxf(cm1, fmaxf(s[j][2], s[j][3]));
        }
        cm0 = fmaxf(cm0, __shfl_xor_sync(0xffffffffu, cm0, 1));
        cm0 = fmaxf(cm0, __shfl_xor_sync(0xffffffffu, cm0, 2));
        cm1 = fmaxf(cm1, __shfl_xor_sync(0xffffffffu, cm1, 1));
        cm1 = fmaxf(cm1, __shfl_xor_sync(0xffffffffu, cm1, 2));

        float M0 = fmaxf(m0, cm0), M1 = fmaxf(m1, cm1);
        float r0 = __expf(m0 - M0), r1 = __expf(m1 - M1);
        float sum0 = 0.f, sum1 = 0.f;
#pragma unroll
        for (int j = 0; j < 8; j++) {
            s[j][0] = __expf(s[j][0] - M0);
            s[j][1] = __expf(s[j][1] - M0);
            s[j][2] = __expf(s[j][2] - M1);
            s[j][3] = __expf(s[j][3] - M1);
            sum0 += s[j][0] + s[j][1];
            sum1 += s[j][2] + s[j][3];
        }
        sum0 += __shfl_xor_sync(0xffffffffu, sum0, 1);
        sum0 += __shfl_xor_sync(0xffffffffu, sum0, 2);
        sum1 += __shfl_xor_sync(0xffffffffu, sum1, 1);
        sum1 += __shfl_xor_sync(0xffffffffu, sum1, 2);
        l0 = l0 * r0 + sum0;
        l1 = l1 * r1 + sum1;
        m0 = M0;
        m1 = M1;
#pragma unroll
        for (int j = 0; j < 8; j++) {
            o[j][0] *= r0; o[j][1] *= r0;
            o[j][2] *= r1; o[j][3] *= r1;
        }

        uint32_t pa[4][4];
#pragma unroll
        for (int t = 0; t < 4; t++) {
            __half2 h0 = __floats2half2_rn(s[2 * t][0], s[2 * t][1]);
            __half2 h1 = __floats2half2_rn(s[2 * t][2], s[2 * t][3]);
            __half2 h2 = __floats2half2_rn(s[2 * t + 1][0], s[2 * t + 1][1]);
            __half2 h3 = __floats2half2_rn(s[2 * t + 1][2], s[2 * t + 1][3]);
            pa[t][0] = *(uint32_t*)&h0;
            pa[t][1] = *(uint32_t*)&h1;
            pa[t][2] = *(uint32_t*)&h2;
            pa[t][3] = *(uint32_t*)&h3;
        }

#pragma unroll
        for (int t = 0; t < 4; t++) {
            int kk = wn * 64 + t * 16 + 2 * cq;
#pragma unroll
            for (int j = 0; j < 8; j++) {
                uint32_t b0 = *(const uint32_t*)&vs[(j * 8 + g) * VS + kk];
                uint32_t b1 = *(const uint32_t*)&vs[(j * 8 + g) * VS + kk + 8];
                MMA16816(o[j], pa[t][0], pa[t][1], pa[t][2], pa[t][3], b0, b1);
            }
        }
    }

    __syncthreads();
    float* p = mrg + ((size_t)(wm * 32 + lane)) * 36;
    if (wn == 1) {
#pragma unroll
        for (int j = 0; j < 8; j++) {
            p[4 * j] = o[j][0]; p[4 * j + 1] = o[j][1];
            p[4 * j + 2] = o[j][2]; p[4 * j + 3] = o[j][3];
        }
        p[32] = m0; p[33] = m1; p[34] = l0; p[35] = l1;
    }
    __syncthreads();
    if (wn == 0) {
        float pm0 = p[32], pm1 = p[33], pl0 = p[34], pl1 = p[35];
        float M0 = fmaxf(m0, pm0), M1 = fmaxf(m1, pm1);
        float ra0 = __expf(m0 - M0), rb0 = __expf(pm0 - M0);
        float ra1 = __expf(m1 - M1), rb1 = __expf(pm1 - M1);
        float i0 = 1.0f / (l0 * ra0 + pl0 * rb0);
        float i1 = 1.0f / (l1 * ra1 + pl1 * rb1);
#pragma unroll
        for (int j = 0; j < 8; j++) {
            int d = j * 8 + 2 * cq;
            if (a0r < AG) {
                float2 v = make_float2((o[j][0] * ra0 + p[4 * j] * rb0) * i0,
                                       (o[j][1] * ra0 + p[4 * j + 1] * rb0) * i0);
                *(float2*)&g_agentv[((size_t)bh * AG + a0r) * Dd + d] = v;
            }
            if (a1r < AG) {
                float2 v = make_float2((o[j][2] * ra1 + p[4 * j + 2] * rb1) * i1,
                                       (o[j][3] * ra1 + p[4 * j + 3] * rb1) * i1);
                *(float2*)&g_agentv[((size_t)bh * AG + a1r) * Dd + d] = v;
            }
        }
    }
}

// ---------------- stage 2 (tensor-core fused): softmax(q·a^T + bias) @ agent_v ----
#define S2S 72
__global__ __launch_bounds__(256) void stage2_mma()
{
    __shared__ __half qh[128 * S2S];
    __shared__ __half a4h[64 * S2S];
    __shared__ __half avh[64 * S2S];
    const int bh = blockIdx.y;
    const int b = bh / HEADS, h = bh % HEADS;
    const int n0 = blockIdx.x * 128;
    const int tid = threadIdx.x;
    const int wid = tid >> 5, lane = tid & 31;
    const int g = lane >> 2, cq = lane & 3;

#pragma unroll
    for (int i = 0; i < 4; i++) {
        int idx = i * 256 + tid;               // 1024 = 128 rows x 8 segs
        int r = idx >> 3, seg = idx & 7;
        int n = min(n0 + r, Nn - 1);
        *(uint4*)&qh[r * S2S + seg * 8] =
            *(const uint4*)&g_qh[((size_t)(b * Nn + n)) * Cc + h * Dd + seg * 8];
    }
#pragma unroll
    for (int i = 0; i < 16; i++) {
        int idx = i * 256 + tid;
        int a = idx >> 6, d = idx & 63;
        float av = (a < AG) ? g_agent[((size_t)b * AG + a) * Cc + h * Dd + d] * 0.125f : 0.f;
        float vv = (a < AG) ? g_agentv[((size_t)bh * AG + a) * Dd + d] : 0.f;
        a4h[a * S2S + d] = __float2half(av);
        avh[d * S2S + a] = __float2half(vv);
    }
    __syncthreads();

    float s[8][4];
#pragma unroll
    for (int j = 0; j < 8; j++)
#pragma unroll
        for (int t = 0; t < 4; t++) s[j][t] = 0.f;

    const __half* qa = qh + (wid * 16) * S2S;
#pragma unroll
    for (int t = 0; t < 4; t++) {
        int k = t * 16 + 2 * cq;
        uint32_t a0 = *(const uint32_t*)&qa[g * S2S + k];
        uint32_t a1 = *(const uint32_t*)&qa[(g + 8) * S2S + k];
        uint32_t a2 = *(const uint32_t*)&qa[g * S2S + k + 8];
        uint32_t a3 = *(const uint32_t*)&qa[(g + 8) * S2S + k + 8];
#pragma unroll
        for (int j = 0; j < 8; j++) {
            uint32_t b0 = *(const uint32_t*)&a4h[(j * 8 + g) * S2S + k];
            uint32_t b1 = *(const uint32_t*)&a4h[(j * 8 + g) * S2S + k + 8];
            MMA16816(s[j], a0, a1, a2, a3, b0, b1);
        }
    }

    const int r0 = n0 + wid * 16 + g;
    const int r1 = r0 + 8;
    float m0 = -1e30f, m1 = -1e30f;
#pragma unroll
    for (int j = 0; j < 8; j++) {
        int a = 8 * j + 2 * cq;
        if (a < AG) {
            float b00 = (r0 < Nn) ? g_bias_qa[((size_t)h * Nn + r0) * AG + a] : 0.f;
            float b10 = (r1 < Nn) ? g_bias_qa[((size_t)h * Nn + r1) * AG + a] : 0.f;
            s[j][0] += b00;
            s[j][2] += b10;
            if (a + 1 < AG) {
                float b01 = (r0 < Nn) ? g_bias_qa[((size_t)h * Nn + r0) * AG + a + 1] : 0.f;
                float b11 = (r1 < Nn) ? g_bias_qa[((size_t)h * Nn + r1) * AG + a + 1] : 0.f;
                s[j][1] += b01;
                s[j][3] += b11;
            } else {
                s[j][1] = -1e30f;
                s[j][3] = -1e30f;
            }
        } else {
            s[j][0] = -1e30f; s[j][1] = -1e30f;
            s[j][2] = -1e30f; s[j][3] = -1e30f;
        }
        m0 = fmaxf(m0, fmaxf(s[j][0], s[j][1]));
        m1 = fmaxf(m1, fmaxf(s[j][2], s[j][3]));
    }
    m0 = fmaxf(m0, __shfl_xor_sync(0xffffffffu, m0, 1));
    m0 = fmaxf(m0, __shfl_xor_sync(0xffffffffu, m0, 2));
    m1 = fmaxf(m1, __shfl_xor_sync(0xffffffffu, m1, 1));
    m1 = fmaxf(m1, __shfl_xor_sync(0xffffffffu, m1, 2));

    float sum0 = 0.f, sum1 = 0.f;
#pragma unroll
    for (int j = 0; j < 8; j++) {
        s[j][0] = __expf(s[j][0] - m0);
        s[j][1] = __expf(s[j][1] - m0);
        s[j][2] = __expf(s[j][2] - m1);
        s[j][3] = __expf(s[j][3] - m1);
        sum0 += s[j][0] + s[j][1];
        sum1 += s[j][2] + s[j][3];
    }
    sum0 += __shfl_xor_sync(0xffffffffu, sum0, 1);
    sum0 += __shfl_xor_sync(0xffffffffu, sum0, 2);
    sum1 += __shfl_xor_sync(0xffffffffu, sum1, 1);
    sum1 += __shfl_xor_sync(0xffffffffu, sum1, 2);
    const float inv0 = 1.0f / sum0, inv1 = 1.0f / sum1;

    uint32_t pa[4][4];
#pragma unroll
    for (int t = 0; t < 4; t++) {
        __half2 h0 = __floats2half2_rn(s[2 * t][0], s[2 * t][1]);
        __half2 h1 = __floats2half2_rn(s[2 * t][2], s[2 * t][3]);
        __half2 h2 = __floats2half2_rn(s[2 * t + 1][0], s[2 * t + 1][1]);
        __half2 h3 = __floats2half2_rn(s[2 * t + 1][2], s[2 * t + 1][3]);
        pa[t][0] = *(uint32_t*)&h0;
        pa[t][1] = *(uint32_t*)&h1;
        pa[t][2] = *(uint32_t*)&h2;
        pa[t][3] = *(uint32_t*)&h3;
    }

    float o[8][4];
#pragma unroll
    for (int j = 0; j < 8; j++)
#pragma unroll
        for (int t = 0; t < 4; t++) o[j][t] = 0.f;
#pragma unroll
    for (int t = 0; t < 4; t++) {
        int k = t * 16 + 2 * cq;
#pragma unroll
        for (int j = 0; j < 8; j++) {
            uint32_t b0 = *(const uint32_t*)&avh[(j * 8 + g) * S2S + k];
            uint32_t b1 = *(const uint32_t*)&avh[(j * 8 + g) * S2S + k + 8];
            MMA16816(o[j], pa[t][0], pa[t][1], pa[t][2], pa[t][3], b0, b1);
        }
    }

    // store fp16 attention-out into g_acch (dwc adds in-place afterwards)
#pragma unroll
    for (int j = 0; j < 8; j++) {
        int d = 8 * j + 2 * cq;
        if (r0 < Nn) {
            __half2 v = __floats2half2_rn(o[j][0] * inv0, o[j][1] * inv0);
            *(__half2*)&g_acch[((size_t)(b * Nn + r0)) * Cc + h * Dd + d] = v;
        }
        if (r1 < Nn) {
            __half2 v = __floats2half2_rn(o[j][2] * inv1, o[j][3] * inv1);
            *(__half2*)&g_acch[((size_t)(b * Nn + r1)) * Cc + h * Dd + d] = v;
        }
    }
}

// ---------------- depthwise 3x3 conv on v (fp16), in-place add into g_acch -------
__global__ __launch_bounds__(256) void dwc_kernel(
    const float* __restrict__ w, const float* __restrict__ bias)
{
    size_t idx = (size_t)blockIdx.x * 256 + threadIdx.x;
    int c = (int)(idx % Cc);
    size_t bnv = idx / Cc;
    int n = (int)(bnv % Nn);
    int b = (int)(bnv / Nn);
    int y = n / Hpix, x = n % Hpix;
    float s = bias[c];
#pragma unroll
    for (int dy = -1; dy <= 1; dy++) {
        int yy = y + dy;
        if (yy < 0 || yy >= Hpix) continue;
#pragma unroll
        for (int dx = -1; dx <= 1; dx++) {
            int xx = x + dx;
            if (xx < 0 || xx >= Hpix) continue;
            float vv = __half2float(g_kvh[((size_t)(b * Nn + yy * Hpix + xx)) * 1024 + 512 + c]);
            s = fmaf(vv, w[c * 9 + (dy + 1) * 3 + (dx + 1)], s);
        }
    }
    g_acch[idx] = __float2half(__half2float(g_acch[idx]) + s);
}

// ---------------- launch ----------------
extern "C" void kernel_launch(void* const* d_in, const int* in_sizes, int n_in,
                              void* d_out, int out_size)
{
    const float* x      = (const float*)d_in[0];
    const float* q_w    = (const float*)d_in[1];
    const float* kv_w   = (const float*)d_in[2];
    const float* proj_w = (const float*)d_in[3];
    const float* proj_b = (const float*)d_in[4];
    const float* dwc_w  = (const float*)d_in[5];
    const float* dwc_b  = (const float*)d_in[6];
    const float* an_b   = (const float*)d_in[7];
    const float* na_b   = (const float*)d_in[8];
    const float* ah     = (const float*)d_in[9];
    const float* aw     = (const float*)d_in[10];
    const float* ha     = (const float*)d_in[11];
    const float* wa     = (const float*)d_in[12];

    __half *qhp, *xhp, *kvhp, *acchp, *wtp;
    cudaGetSymbolAddress((void**)&qhp, g_qh);
    cudaGetSymbolAddress((void**)&kvhp, g_kvh);
    cudaGetSymbolAddress((void**)&xhp, g_xh);
    cudaGetSymbolAddress((void**)&acchp, g_acch);
    cudaGetSymbolAddress((void**)&wtp, g_wTh);

    cudaFuncSetAttribute(gemm_h, cudaFuncAttributeMaxDynamicSharedMemorySize, GT_SMEM);
    cudaFuncSetAttribute(stage1_mma, cudaFuncAttributeMaxDynamicSharedMemorySize, S1_SMEM);

    const int M = Bn * Nn;  // 50176

    wtrans_kernel<<<dim3(512 / 32, 512 / 32), 256>>>(q_w, wtp + WT_Q, 512, 512);
    wtrans_kernel<<<dim3(1024 / 32, 512 / 32), 256>>>(kv_w, wtp + WT_KV, 512, 1024);
    wtrans_kernel<<<dim3(512 / 32, 512 / 32), 256>>>(proj_w, wtp + WT_PROJ, 512, 512);
    xconv_kernel<<<(int)(((size_t)M * Cc / 8) / 256), 256>>>(x, xhp);

    gemm_h<<<dim3(512 / 128, M / 128), 256, GT_SMEM>>>(xhp, wtp + WT_Q, nullptr, qhp, M, Cc, Cc, nullptr);
    gemm_h<<<dim3(1024 / 128, M / 128), 256, GT_SMEM>>>(xhp, wtp + WT_KV, nullptr, kvhp, M, Cc, 2 * Cc, nullptr);
    pool_kernel<<<(Bn * AG * Cc) / 256, 256>>>();
    biasak_kernel<<<(HEADS * AG * Nn) / 256, 256>>>(an_b, ah, aw);
    biasqa_kernel<<<(HEADS * Nn * AG) / 256, 256>>>(na_b, ha, wa);
    stage1_mma<<<Bn * HEADS, 256, S1_SMEM>>>();
    stage2_mma<<<dim3(25, Bn * HEADS), 256>>>();
    dwc_kernel<<<(int)(((size_t)Bn * Nn * Cc) / 256), 256>>>(dwc_w, dwc_b);
    gemm_h<<<dim3(512 / 128, M / 128), 256, GT_SMEM>>>(acchp, wtp + WT_PROJ, (float*)d_out, nullptr, M, Cc, Cc, proj_b);
}

// round 9
// speedup vs baseline: 5.2313x; 1.1724x over previous
#include <cuda_runtime.h>
#include <cuda_fp16.h>
#include <cstdint>
#include <math.h>

#define Bn 16
#define Nn 3136
#define Cc 512
#define Hpix 56
#define HEADS 8
#define Dd 64
#define AG 49
#define QKV 1536

// ---------------- scratch (device globals; no allocation allowed) ----------------
__device__ __half g_qkvh[(size_t)Bn * Nn * QKV];       // fp16: q[0,512) k[512,1024) v[1024,1536)
__device__ float g_agent[(size_t)Bn * AG * Cc];        // (b,a,c)
__device__ float g_bias_ak[(size_t)HEADS * AG * Nn + 128]; // (h,a,n) +pad for cp.async tail
__device__ float g_bias_qa[(size_t)HEADS * Nn * AG];   // (h,n,a)
__device__ float g_agentv[(size_t)Bn * HEADS * AG * Dd];
__device__ __half g_xh[(size_t)Bn * Nn * Cc];          // x in fp16
__device__ __half g_acch[(size_t)Bn * Nn * Cc];        // attn out, then += dwc
// transposed fp16 weights: [qT|kT|vT] rows 0..1535, projT rows after; K-major K=512
__device__ __half g_wTh[(size_t)2048 * 512];
#define WT_PROJ (1536 * 512)

#define MMA16816(acc, a0, a1, a2, a3, b0, b1)                                   \
    asm volatile(                                                               \
        "mma.sync.aligned.m16n8k16.row.col.f32.f16.f16.f32 "                    \
        "{%0,%1,%2,%3}, {%4,%5,%6,%7}, {%8,%9}, {%0,%1,%2,%3};"                 \
        : "+f"(acc[0]), "+f"(acc[1]), "+f"(acc[2]), "+f"(acc[3])                \
        : "r"(a0), "r"(a1), "r"(a2), "r"(a3), "r"(b0), "r"(b1))

#define LDSM_X4(r0, r1, r2, r3, addr)                                           \
    asm volatile("ldmatrix.sync.aligned.m8n8.x4.shared.b16 {%0,%1,%2,%3}, [%4];" \
                 : "=r"(r0), "=r"(r1), "=r"(r2), "=r"(r3) : "r"(addr))

#define CP_ASYNC16(dst, src)                                                    \
    asm volatile("cp.async.cg.shared.global [%0], [%1], 16;\n" :: "r"(dst), "l"(src))

// ---------------- fp16 tensor-core GEMM: C = A[M,K] @ Bt[Nc,K]^T (+bias) ----------
#define GAS 72
#define GBUF (128 * GAS)
#define GSTAGES 3
#define GT_SMEM (GSTAGES * 2 * GBUF * 2)   // 110592 bytes

__global__ __launch_bounds__(256, 2) void gemm_h(
    const __half* __restrict__ A, const __half* __restrict__ Bt,
    float* __restrict__ Cout, __half* __restrict__ CoutH,
    int M, int K, int Nc, const float* __restrict__ bias)
{
    extern __shared__ __half smh[];
    __half* smA = smh;
    __half* smB = smh + GSTAGES * GBUF;
    const int tid = threadIdx.x;
    const int wid = tid >> 5, lane = tid & 31;
    const int wm = wid & 3, wn = wid >> 2;
    const int g = lane >> 2, cq = lane & 3;
    const int bm = blockIdx.y * 128, bn = blockIdx.x * 128;

    const uint32_t smA_u = (uint32_t)__cvta_generic_to_shared(smA);
    const uint32_t smB_u = (uint32_t)__cvta_generic_to_shared(smB);
    const uint32_t aOff = (wm * 32 + (lane & 15)) * GAS * 2 + (lane >> 4) * 16;
    const uint32_t bOff = (wn * 64 + (lane & 15)) * GAS * 2 + (lane >> 4) * 16;

    float acc[2][8][4];
#pragma unroll
    for (int i = 0; i < 2; i++)
#pragma unroll
        for (int j = 0; j < 8; j++)
#pragma unroll
            for (int t = 0; t < 4; t++) acc[i][j][t] = 0.f;

    auto loadAB = [&](int s, int kc) {
        const __half* ga = A + (size_t)bm * K + kc * 64;
        const __half* gb = Bt + (size_t)bn * K + kc * 64;
        __half* da = smA + s * GBUF;
        __half* db = smB + s * GBUF;
#pragma unroll
        for (int i = 0; i < 4; i++) {
            int idx = i * 256 + tid;
            int row = idx >> 3, seg = idx & 7;
            uint32_t pa = (uint32_t)__cvta_generic_to_shared(da + row * GAS + seg * 8);
            uint32_t pb = (uint32_t)__cvta_generic_to_shared(db + row * GAS + seg * 8);
            CP_ASYNC16(pa, ga + (size_t)row * K + seg * 8);
            CP_ASYNC16(pb, gb + (size_t)row * K + seg * 8);
        }
        asm volatile("cp.async.commit_group;\n");
    };

    const int KT = K / 64;
    loadAB(0, 0);
    loadAB(1, 1);
    loadAB(2, 2);

    for (int c = 0; c < KT; c++) {
        int s = c % GSTAGES;
        if (c + 2 < KT)      asm volatile("cp.async.wait_group 2;\n");
        else if (c + 1 < KT) asm volatile("cp.async.wait_group 1;\n");
        else                 asm volatile("cp.async.wait_group 0;\n");
        __syncthreads();
        const uint32_t aP = smA_u + s * (GBUF * 2) + aOff;
        const uint32_t bP = smB_u + s * (GBUF * 2) + bOff;
#pragma unroll
        for (int ks = 0; ks < 4; ks++) {
            const uint32_t kb = ks * 32;
            uint32_t a[2][4];
            LDSM_X4(a[0][0], a[0][1], a[0][2], a[0][3], aP + kb);
            LDSM_X4(a[1][0], a[1][1], a[1][2], a[1][3], aP + 16 * GAS * 2 + kb);
#pragma unroll
            for (int jj = 0; jj < 4; jj++) {
                uint32_t rb0, rb1, rb2, rb3;
                LDSM_X4(rb0, rb1, rb2, rb3, bP + jj * (16 * GAS * 2) + kb);
#pragma unroll
                for (int i = 0; i < 2; i++) {
                    MMA16816(acc[i][2 * jj],     a[i][0], a[i][1], a[i][2], a[i][3], rb0, rb2);
                    MMA16816(acc[i][2 * jj + 1], a[i][0], a[i][1], a[i][2], a[i][3], rb1, rb3);
                }
            }
        }
        __syncthreads();
        if (c + GSTAGES < KT) loadAB(s, c + GSTAGES);
    }

#pragma unroll
    for (int j = 0; j < 8; j++) {
        int col = bn + wn * 64 + j * 8 + 2 * cq;
        float bx = 0.f, by = 0.f;
        if (bias) { bx = bias[col]; by = bias[col + 1]; }
#pragma unroll
        for (int i = 0; i < 2; i++) {
            int r0 = bm + wm * 32 + i * 16 + g;
            if (CoutH) {
                __half2 h0 = __floats2half2_rn(acc[i][j][0] + bx, acc[i][j][1] + by);
                __half2 h1 = __floats2half2_rn(acc[i][j][2] + bx, acc[i][j][3] + by);
                *(__half2*)&CoutH[(size_t)r0 * Nc + col] = h0;
                *(__half2*)&CoutH[(size_t)(r0 + 8) * Nc + col] = h1;
            } else {
                *(float2*)&Cout[(size_t)r0 * Nc + col] =
                    make_float2(acc[i][j][0] + bx, acc[i][j][1] + by);
                *(float2*)&Cout[(size_t)(r0 + 8) * Nc + col] =
                    make_float2(acc[i][j][2] + bx, acc[i][j][3] + by);
            }
        }
    }
}

// ---------------- weight transpose + fp16 convert: Wt[n][k] = half(W[k][n]) ------
__global__ __launch_bounds__(256) void wtrans_kernel(
    const float* __restrict__ W, __half* __restrict__ Wt, int K, int Nc)
{
    __shared__ float t[32][33];
    int k0 = blockIdx.y * 32, n0 = blockIdx.x * 32;
    int tx = threadIdx.x & 31, ty = threadIdx.x >> 5;
#pragma unroll
    for (int i = 0; i < 32; i += 8)
        t[ty + i][tx] = W[(size_t)(k0 + ty + i) * Nc + n0 + tx];
    __syncthreads();
#pragma unroll
    for (int i = 0; i < 32; i += 8)
        Wt[(size_t)(n0 + ty + i) * K + k0 + tx] = __float2half(t[tx][ty + i]);
}

// ---------------- fp32 -> fp16 cast ----------------
__global__ __launch_bounds__(256) void xconv_kernel(
    const float* __restrict__ src, __half* __restrict__ dst)
{
    size_t i = (size_t)blockIdx.x * 256 + threadIdx.x;
    float4 v0 = ((const float4*)src)[2 * i];
    float4 v1 = ((const float4*)src)[2 * i + 1];
    __half2 h0 = __floats2half2_rn(v0.x, v0.y);
    __half2 h1 = __floats2half2_rn(v0.z, v0.w);
    __half2 h2 = __floats2half2_rn(v1.x, v1.y);
    __half2 h3 = __floats2half2_rn(v1.z, v1.w);
    uint4 o;
    o.x = *(uint32_t*)&h0;
    o.y = *(uint32_t*)&h1;
    o.z = *(uint32_t*)&h2;
    o.w = *(uint32_t*)&h3;
    ((uint4*)dst)[i] = o;
}

// ---------------- 8x8 mean pool on fp16 q: agent[b,a,c] ----------------
__global__ __launch_bounds__(256) void pool_kernel()
{
    int idx = blockIdx.x * 256 + threadIdx.x;
    int c = idx % Cc;
    int ba = idx / Cc;
    int a = ba % AG;
    int b = ba / AG;
    int py = a / 7, px = a % 7;
    float s = 0.f;
#pragma unroll
    for (int dy = 0; dy < 8; dy++) {
        int n_base = (py * 8 + dy) * Hpix + px * 8;
#pragma unroll
        for (int dx = 0; dx < 8; dx++)
            s += __half2float(g_qkvh[((size_t)b * Nn + n_base + dx) * QKV + c]);
    }
    g_agent[idx] = s * (1.0f / 64.0f);
}

// ---------------- bilinear 7x7 -> 56x56 (half-pixel centers, edge clamp) ----------
__device__ __forceinline__ float bilerp7(const float* __restrict__ t, int y, int x)
{
    float sy = (y + 0.5f) * 0.125f - 0.5f;
    float sx = (x + 0.5f) * 0.125f - 0.5f;
    int y0f = (int)floorf(sy);
    int x0f = (int)floorf(sx);
    float wy = sy - (float)y0f;
    float wx = sx - (float)x0f;
    int y0 = min(6, max(0, y0f));
    int y1 = min(6, max(0, y0f + 1));
    int x0 = min(6, max(0, x0f));
    int x1 = min(6, max(0, x0f + 1));
    float v00 = t[y0 * 7 + x0], v01 = t[y0 * 7 + x1];
    float v10 = t[y1 * 7 + x0], v11 = t[y1 * 7 + x1];
    float top = v00 + wx * (v01 - v00);
    float bot = v10 + wx * (v11 - v10);
    return top + wy * (bot - top);
}

__global__ __launch_bounds__(256) void biasak_kernel(
    const float* __restrict__ an, const float* __restrict__ ah, const float* __restrict__ aw)
{
    int idx = blockIdx.x * 256 + threadIdx.x;
    int n = idx % Nn;
    int haa = idx / Nn;
    int y = n / Hpix, x = n % Hpix;
    g_bias_ak[idx] = bilerp7(an + haa * 49, y, x) + ah[haa] + aw[haa];
}

__global__ __launch_bounds__(256) void biasqa_kernel(
    const float* __restrict__ na, const float* __restrict__ ha, const float* __restrict__ wa)
{
    int idx = blockIdx.x * 256 + threadIdx.x;
    int a = idx % AG;
    int hn = idx / AG;
    int n = hn % Nn;
    int h = hn / Nn;
    int y = n / Hpix, x = n % Hpix;
    int haa = h * AG + a;
    g_bias_qa[idx] = bilerp7(na + haa * 49, y, x) + ha[haa] + wa[haa];
}

// ---------------- stage 1 (flash, tensor cores, double-buffered cp.async) --------
// agent_v = softmax(a·k^T + bias) @ v ; one block per (b,h); 8 warps (4 m x 2 n).
#define FS 72
#define VS 136
#define NCH 25                       // ceil(3136/128)
#define S1_AQ 0
#define S1_KS 9216                   // 2 x 128*72*2  = 36864
#define S1_VS 46080                  // 2 x 64*136*2  = 34816
#define S1_BI 80896                  // 2 x 49*132*4  = 51744
#define S1_SMEM 132640

__global__ __launch_bounds__(256) void stage1_mma()
{
    extern __shared__ char sm1[];
    __half* aq = (__half*)(sm1 + S1_AQ);
    float* mrg = (float*)(sm1 + S1_KS);    // end-merge reuses ks0

    const int bh = blockIdx.x;
    const int b = bh / HEADS, h = bh % HEADS;
    const int tid = threadIdx.x;
    const int wid = tid >> 5, lane = tid & 31;
    const int wm = wid & 3, wn = wid >> 2;
    const int g = lane >> 2, cq = lane & 3;

#pragma unroll
    for (int i = 0; i < 16; i++) {
        int f = i * 256 + tid;
        int a = f >> 6, d = f & 63;
        float v = (a < AG) ? g_agent[((size_t)b * AG + a) * Cc + h * Dd + d] * 0.125f : 0.f;
        aq[a * FS + d] = __float2half(v);
    }

    // cp.async loaders: k chunk + bias chunk
    auto issueKB = [&](int buf, int n0) {
        char* kdst = sm1 + S1_KS + buf * 18432;
#pragma unroll
        for (int i = 0; i < 4; i++) {
            int idx = i * 256 + tid;
            int r = idx >> 3, seg = idx & 7;
            int n = min(n0 + r, Nn - 1);
            uint32_t p = (uint32_t)__cvta_generic_to_shared(kdst + (r * FS + seg * 8) * 2);
            CP_ASYNC16(p, &g_qkvh[((size_t)(b * Nn + n)) * QKV + 512 + h * Dd + seg * 8]);
        }
        char* bdst = sm1 + S1_BI + buf * 25872;
        for (int f = tid; f < AG * 32; f += 256) {
            int a = f >> 5, seg = f & 31;
            uint32_t p = (uint32_t)__cvta_generic_to_shared(bdst + (a * 132 + seg * 4) * 4);
            CP_ASYNC16(p, &g_bias_ak[((size_t)(h * AG + a)) * Nn + n0 + seg * 4]);
        }
        asm volatile("cp.async.commit_group;\n");
    };

    __half2 vxr[8], vyr[8];
    auto loadVregs = [&](int n0) {
#pragma unroll
        for (int i = 0; i < 8; i++) {
            int idx = i * 256 + tid;
            int dp = idx & 31, np = idx >> 5;
            int na = min(n0 + 2 * np, Nn - 1);
            int nb = min(n0 + 2 * np + 1, Nn - 1);
            vxr[i] = *(const __half2*)&g_qkvh[((size_t)(b * Nn + na)) * QKV + 1024 + h * Dd + dp * 2];
            vyr[i] = *(const __half2*)&g_qkvh[((size_t)(b * Nn + nb)) * QKV + 1024 + h * Dd + dp * 2];
        }
    };
    auto stsV = [&](int buf) {
        __half* vd = (__half*)(sm1 + S1_VS + buf * 17408);
#pragma unroll
        for (int i = 0; i < 8; i++) {
            int idx = i * 256 + tid;
            int dp = idx & 31, np = idx >> 5;
            *(__half2*)&vd[(2 * dp) * VS + 2 * np] = __lows2half2(vxr[i], vyr[i]);
            *(__half2*)&vd[(2 * dp + 1) * VS + 2 * np] = __highs2half2(vxr[i], vyr[i]);
        }
    };

    float m0 = -1e30f, m1 = -1e30f, l0 = 0.f, l1 = 0.f;
    float o[8][4];
#pragma unroll
    for (int j = 0; j < 8; j++)
#pragma unroll
        for (int t = 0; t < 4; t++) o[j][t] = 0.f;

    const int a0r = wm * 16 + g, a1r = a0r + 8;

    // prologue: chunk 0
    issueKB(0, 0);
    loadVregs(0);
    asm volatile("cp.async.wait_group 0;\n");
    stsV(0);
    __syncthreads();

    for (int c = 0; c < NCH; c++) {
        const int cur = c & 1, nxt = cur ^ 1;
        const int n0 = c * 128;
        if (c + 1 < NCH) {
            issueKB(nxt, (c + 1) * 128);
            loadVregs((c + 1) * 128);
        }
        const __half* ksb = (const __half*)(sm1 + S1_KS + cur * 18432);
        const __half* vsb = (const __half*)(sm1 + S1_VS + cur * 17408);
        const float* bib = (const float*)(sm1 + S1_BI + cur * 25872);

        // ---- S = agents @ k^T ----
        float s[8][4];
#pragma unroll
        for (int j = 0; j < 8; j++)
#pragma unroll
            for (int t = 0; t < 4; t++) s[j][t] = 0.f;
#pragma unroll
        for (int t = 0; t < 4; t++) {
            int kk = t * 16 + 2 * cq;
            uint32_t A0 = *(const uint32_t*)&aq[(wm * 16 + g) * FS + kk];
            uint32_t A1 = *(const uint32_t*)&aq[(wm * 16 + g + 8) * FS + kk];
            uint32_t A2 = *(const uint32_t*)&aq[(wm * 16 + g) * FS + kk + 8];
            uint32_t A3 = *(const uint32_t*)&aq[(wm * 16 + g + 8) * FS + kk + 8];
#pragma unroll
            for (int j = 0; j < 8; j++) {
                int row = wn * 64 + j * 8 + g;
                uint32_t b0 = *(const uint32_t*)&ksb[row * FS + kk];
                uint32_t b1 = *(const uint32_t*)&ksb[row * FS + kk + 8];
                MMA16816(s[j], A0, A1, A2, A3, b0, b1);
            }
        }

        // ---- bias + mask + online softmax ----
        float cm0 = -1e30f, cm1 = -1e30f;
#pragma unroll
        for (int j = 0; j < 8; j++) {
            int nl = wn * 64 + j * 8 + 2 * cq;
            int n = n0 + nl;
            bool v0 = (n < Nn), v1 = (n + 1 < Nn);
            float ba00 = (a0r < AG) ? bib[a0r * 132 + nl] : 0.f;
            float ba01 = (a0r < AG) ? bib[a0r * 132 + nl + 1] : 0.f;
            float ba10 = (a1r < AG) ? bib[a1r * 132 + nl] : 0.f;
            float ba11 = (a1r < AG) ? bib[a1r * 132 + nl + 1] : 0.f;
            s[j][0] = v0 ? s[j][0] + ba00 : -1e30f;
            s[j][1] = v1 ? s[j][1] + ba01 : -1e30f;
            s[j][2] = v0 ? s[j][2] + ba10 : -1e30f;
            s[j][3] = v1 ? s[j][3] + ba11 : -1e30f;
            cm0 = fmaxf(cm0, fmaxf(s[j][0], s[j][1]));
            cm1 = fmaxf(cm1, fmaxf(s[j][2], s[j][3]));
        }
        cm0 = fmaxf(cm0, __shfl_xor_sync(0xffffffffu, cm0, 1));
        cm0 = fmaxf(cm0, __shfl_xor_sync(0xffffffffu, cm0, 2));
        cm1 = fmaxf(cm1, __shfl_xor_sync(0xffffffffu, cm1, 1));
        cm1 = fmaxf(cm1, __shfl_xor_sync(0xffffffffu, cm1, 2));

        float M0 = fmaxf(m0, cm0), M1 = fmaxf(m1, cm1);
        float r0 = __expf(m0 - M0), r1 = __expf(m1 - M1);
        float sum0 = 0.f, sum1 = 0.f;
#pragma unroll
        for (int j = 0; j < 8; j++) {
            s[j][0] = __expf(s[j][0] - M0);
            s[j][1] = __expf(s[j][1] - M0);
            s[j][2] = __expf(s[j][2] - M1);
            s[j][3] = __expf(s[j][3] - M1);
            sum0 += s[j][0] + s[j][1];
            sum1 += s[j][2] + s[j][3];
        }
        sum0 += __shfl_xor_sync(0xffffffffu, sum0, 1);
        sum0 += __shfl_xor_sync(0xffffffffu, sum0, 2);
        sum1 += __shfl_xor_sync(0xffffffffu, sum1, 1);
        sum1 += __shfl_xor_sync(0xffffffffu, sum1, 2);
        l0 = l0 * r0 + sum0;
        l1 = l1 * r1 + sum1;
        m0 = M0;
        m1 = M1;
#pragma unroll
        for (int j = 0; j < 8; j++) {
            o[j][0] *= r0; o[j][1] *= r0;
            o[j][2] *= r1; o[j][3] *= r1;
        }

        uint32_t pa[4][4];
#pragma unroll
        for (int t = 0; t < 4; t++) {
            __half2 h0 = __floats2half2_rn(s[2 * t][0], s[2 * t][1]);
            __half2 h1 = __floats2half2_rn(s[2 * t][2], s[2 * t][3]);
            __half2 h2 = __floats2half2_rn(s[2 * t + 1][0], s[2 * t + 1][1]);
            __half2 h3 = __floats2half2_rn(s[2 * t + 1][2], s[2 * t + 1][3]);
            pa[t][0] = *(uint32_t*)&h0;
            pa[t][1] = *(uint32_t*)&h1;
            pa[t][2] = *(uint32_t*)&h2;
            pa[t][3] = *(uint32_t*)&h3;
        }

#pragma unroll
        for (int t = 0; t < 4; t++) {
            int kk = wn * 64 + t * 16 + 2 * cq;
#pragma unroll
            for (int j = 0; j < 8; j++) {
                uint32_t b0 = *(const uint32_t*)&vsb[(j * 8 + g) * VS + kk];
                uint32_t b1 = *(const uint32_t*)&vsb[(j * 8 + g) * VS + kk + 8];
                MMA16816(o[j], pa[t][0], pa[t][1], pa[t][2], pa[t][3], b0, b1);
            }
        }

        if (c + 1 < NCH) {
            asm volatile("cp.async.wait_group 0;\n");
            stsV(nxt);
            __syncthreads();
        }
    }

    // ---- merge wn=1 partials into wn=0 and store ----
    __syncthreads();
    float* p = mrg + ((size_t)(wm * 32 + lane)) * 36;
    if (wn == 1) {
#pragma unroll
        for (int j = 0; j < 8; j++) {
            p[4 * j] = o[j][0]; p[4 * j + 1] = o[j][1];
            p[4 * j + 2] = o[j][2]; p[4 * j + 3] = o[j][3];
        }
        p[32] = m0; p[33] = m1; p[34] = l0; p[35] = l1;
    }
    __syncthreads();
    if (wn == 0) {
        float pm0 = p[32], pm1 = p[33], pl0 = p[34], pl1 = p[35];
        float M0 = fmaxf(m0, pm0), M1 = fmaxf(m1, pm1);
        float ra0 = __expf(m0 - M0), rb0 = __expf(pm0 - M0);
        float ra1 = __expf(m1 - M1), rb1 = __expf(pm1 - M1);
        float i0 = 1.0f / (l0 * ra0 + pl0 * rb0);
        float i1 = 1.0f / (l1 * ra1 + pl1 * rb1);
#pragma unroll
        for (int j = 0; j < 8; j++) {
            int d = j * 8 + 2 * cq;
            if (a0r < AG) {
                float2 v = make_float2((o[j][0] * ra0 + p[4 * j] * rb0) * i0,
                                       (o[j][1] * ra0 + p[4 * j + 1] * rb0) * i0);
                *(float2*)&g_agentv[((size_t)bh * AG + a0r) * Dd + d] = v;
            }
            if (a1r < AG) {
                float2 v = make_float2((o[j][2] * ra1 + p[4 * j + 2] * rb1) * i1,
                                       (o[j][3] * ra1 + p[4 * j + 3] * rb1) * i1);
                *(float2*)&g_agentv[((size_t)bh * AG + a1r) * Dd + d] = v;
            }
        }
    }
}

// ---------------- stage 2 (tensor-core fused): softmax(q·a^T + bias) @ agent_v ----
#define S2S 72
__global__ __launch_bounds__(256) void stage2_mma()
{
    __shared__ __half qh[128 * S2S];
    __shared__ __half a4h[64 * S2S];
    __shared__ __half avh[64 * S2S];
    const int bh = blockIdx.y;
    const int b = bh / HEADS, h = bh % HEADS;
    const int n0 = blockIdx.x * 128;
    const int tid = threadIdx.x;
    const int wid = tid >> 5, lane = tid & 31;
    const int g = lane >> 2, cq = lane & 3;

#pragma unroll
    for (int i = 0; i < 4; i++) {
        int idx = i * 256 + tid;
        int r = idx >> 3, seg = idx & 7;
        int n = min(n0 + r, Nn - 1);
        *(uint4*)&qh[r * S2S + seg * 8] =
            *(const uint4*)&g_qkvh[((size_t)(b * Nn + n)) * QKV + h * Dd + seg * 8];
    }
#pragma unroll
    for (int i = 0; i < 16; i++) {
        int idx = i * 256 + tid;
        int a = idx >> 6, d = idx & 63;
        float av = (a < AG) ? g_agent[((size_t)b * AG + a) * Cc + h * Dd + d] * 0.125f : 0.f;
        float vv = (a < AG) ? g_agentv[((size_t)bh * AG + a) * Dd + d] : 0.f;
        a4h[a * S2S + d] = __float2half(av);
        avh[d * S2S + a] = __float2half(vv);
    }
    __syncthreads();

    float s[8][4];
#pragma unroll
    for (int j = 0; j < 8; j++)
#pragma unroll
        for (int t = 0; t < 4; t++) s[j][t] = 0.f;

    const __half* qa = qh + (wid * 16) * S2S;
#pragma unroll
    for (int t = 0; t < 4; t++) {
        int k = t * 16 + 2 * cq;
        uint32_t a0 = *(const uint32_t*)&qa[g * S2S + k];
        uint32_t a1 = *(const uint32_t*)&qa[(g + 8) * S2S + k];
        uint32_t a2 = *(const uint32_t*)&qa[g * S2S + k + 8];
        uint32_t a3 = *(const uint32_t*)&qa[(g + 8) * S2S + k + 8];
#pragma unroll
        for (int j = 0; j < 8; j++) {
            uint32_t b0 = *(const uint32_t*)&a4h[(j * 8 + g) * S2S + k];
            uint32_t b1 = *(const uint32_t*)&a4h[(j * 8 + g) * S2S + k + 8];
            MMA16816(s[j], a0, a1, a2, a3, b0, b1);
        }
    }

    const int r0 = n0 + wid * 16 + g;
    const int r1 = r0 + 8;
    float m0 = -1e30f, m1 = -1e30f;
#pragma unroll
    for (int j = 0; j < 8; j++) {
        int a = 8 * j + 2 * cq;
        if (a < AG) {
            float b00 = (r0 < Nn) ? g_bias_qa[((size_t)h * Nn + r0) * AG + a] : 0.f;
            float b10 = (r1 < Nn) ? g_bias_qa[((size_t)h * Nn + r1) * AG + a] : 0.f;
            s[j][0] += b00;
            s[j][2] += b10;
            if (a + 1 < AG) {
                float b01 = (r0 < Nn) ? g_bias_qa[((size_t)h * Nn + r0) * AG + a + 1] : 0.f;
                float b11 = (r1 < Nn) ? g_bias_qa[((size_t)h * Nn + r1) * AG + a + 1] : 0.f;
                s[j][1] += b01;
                s[j][3] += b11;
            } else {
                s[j][1] = -1e30f;
                s[j][3] = -1e30f;
            }
        } else {
            s[j][0] = -1e30f; s[j][1] = -1e30f;
            s[j][2] = -1e30f; s[j][3] = -1e30f;
        }
        m0 = fmaxf(m0, fmaxf(s[j][0], s[j][1]));
        m1 = fmaxf(m1, fmaxf(s[j][2], s[j][3]));
    }
    m0 = fmaxf(m0, __shfl_xor_sync(0xffffffffu, m0, 1));
    m0 = fmaxf(m0, __shfl_xor_sync(0xffffffffu, m0, 2));
    m1 = fmaxf(m1, __shfl_xor_sync(0xffffffffu, m1, 1));
    m1 = fmaxf(m1, __shfl_xor_sync(0xffffffffu, m1, 2));

    float sum0 = 0.f, sum1 = 0.f;
#pragma unroll
    for (int j = 0; j < 8; j++) {
        s[j][0] = __expf(s[j][0] - m0);
        s[j][1] = __expf(s[j][1] - m0);
        s[j][2] = __expf(s[j][2] - m1);
        s[j][3] = __expf(s[j][3] - m1);
        sum0 += s[j][0] + s[j][1];
        sum1 += s[j][2] + s[j][3];
    }
    sum0 += __shfl_xor_sync(0xffffffffu, sum0, 1);
    sum0 += __shfl_xor_sync(0xffffffffu, sum0, 2);
    sum1 += __shfl_xor_sync(0xffffffffu, sum1, 1);
    sum1 += __shfl_xor_sync(0xffffffffu, sum1, 2);
    const float inv0 = 1.0f / sum0, inv1 = 1.0f / sum1;

    uint32_t pa[4][4];
#pragma unroll
    for (int t = 0; t < 4; t++) {
        __half2 h0 = __floats2half2_rn(s[2 * t][0], s[2 * t][1]);
        __half2 h1 = __floats2half2_rn(s[2 * t][2], s[2 * t][3]);
        __half2 h2 = __floats2half2_rn(s[2 * t + 1][0], s[2 * t + 1][1]);
        __half2 h3 = __floats2half2_rn(s[2 * t + 1][2], s[2 * t + 1][3]);
        pa[t][0] = *(uint32_t*)&h0;
        pa[t][1] = *(uint32_t*)&h1;
        pa[t][2] = *(uint32_t*)&h2;
        pa[t][3] = *(uint32_t*)&h3;
    }

    float o[8][4];
#pragma unroll
    for (int j = 0; j < 8; j++)
#pragma unroll
        for (int t = 0; t < 4; t++) o[j][t] = 0.f;
#pragma unroll
    for (int t = 0; t < 4; t++) {
        int k = t * 16 + 2 * cq;
#pragma unroll
        for (int j = 0; j < 8; j++) {
            uint32_t b0 = *(const uint32_t*)&avh[(j * 8 + g) * S2S + k];
            uint32_t b1 = *(const uint32_t*)&avh[(j * 8 + g) * S2S + k + 8];
            MMA16816(o[j], pa[t][0], pa[t][1], pa[t][2], pa[t][3], b0, b1);
        }
    }

#pragma unroll
    for (int j = 0; j < 8; j++) {
        int d = 8 * j + 2 * cq;
        if (r0 < Nn) {
            __half2 v = __floats2half2_rn(o[j][0] * inv0, o[j][1] * inv0);
            *(__half2*)&g_acch[((size_t)(b * Nn + r0)) * Cc + h * Dd + d] = v;
        }
        if (r1 < Nn) {
            __half2 v = __floats2half2_rn(o[j][2] * inv1, o[j][3] * inv1);
            *(__half2*)&g_acch[((size_t)(b * Nn + r1)) * Cc + h * Dd + d] = v;
        }
    }
}

// ---------------- depthwise 3x3 conv (vectorized 8 ch/thread), in-place add ------
__global__ __launch_bounds__(256) void dwc_kernel(
    const float* __restrict__ w, const float* __restrict__ bias)
{
    __shared__ float w_t[9 * 512];   // transposed [tap][c]
    for (int i = threadIdx.x; i < 9 * 512; i += 256) {
        int c = i / 9, tap = i % 9;
        w_t[tap * 512 + c] = w[i];
    }
    __syncthreads();

    int idx = blockIdx.x * 256 + threadIdx.x;   // < B*Nn*64 (exact)
    int cg = idx & 63;
    int pix = idx >> 6;
    int n = pix % Nn;
    int b = pix / Nn;
    int y = n / Hpix, x = n % Hpix;
    int c0 = cg * 8;

    float acc[8];
    {
        float4 b0 = *(const float4*)&bias[c0];
        float4 b1 = *(const float4*)&bias[c0 + 4];
        acc[0] = b0.x; acc[1] = b0.y; acc[2] = b0.z; acc[3] = b0.w;
        acc[4] = b1.x; acc[5] = b1.y; acc[6] = b1.z; acc[7] = b1.w;
    }
#pragma unroll
    for (int dy = -1; dy <= 1; dy++) {
        int yy = y + dy;
        if (yy < 0 || yy >= Hpix) continue;
#pragma unroll
        for (int dx = -1; dx <= 1; dx++) {
            int xx = x + dx;
            if (xx < 0 || xx >= Hpix) continue;
            int tap = (dy + 1) * 3 + (dx + 1);
            uint4 raw = *(const uint4*)&g_qkvh[((size_t)(b * Nn + yy * Hpix + xx)) * QKV + 1024 + c0];
            float4 wa = *(const float4*)&w_t[tap * 512 + c0];
            float4 wb = *(const float4*)&w_t[tap * 512 + c0 + 4];
            float2 f0 = __half22float2(*(__half2*)&raw.x);
            float2 f1 = __half22float2(*(__half2*)&raw.y);
            float2 f2 = __half22float2(*(__half2*)&raw.z);
            float2 f3 = __half22float2(*(__half2*)&raw.w);
            acc[0] = fmaf(f0.x, wa.x, acc[0]);
            acc[1] = fmaf(f0.y, wa.y, acc[1]);
            acc[2] = fmaf(f1.x, wa.z, acc[2]);
            acc[3] = fmaf(f1.y, wa.w, acc[3]);
            acc[4] = fmaf(f2.x, wb.x, acc[4]);
            acc[5] = fmaf(f2.y, wb.y, acc[5]);
            acc[6] = fmaf(f3.x, wb.z, acc[6]);
            acc[7] = fmaf(f3.y, wb.w, acc[7]);
        }
    }
    // RMW acch (8 halves)
    __half* ap = &g_acch[((size_t)(b * Nn + n)) * Cc + c0];
    uint4 old = *(const uint4*)ap;
    float2 o0 = __half22float2(*(__half2*)&old.x);
    float2 o1 = __half22float2(*(__half2*)&old.y);
    float2 o2 = __half22float2(*(__half2*)&old.z);
    float2 o3 = __half22float2(*(__half2*)&old.w);
    __half2 r0 = __floats2half2_rn(o0.x + acc[0], o0.y + acc[1]);
    __half2 r1 = __floats2half2_rn(o1.x + acc[2], o1.y + acc[3]);
    __half2 r2 = __floats2half2_rn(o2.x + acc[4], o2.y + acc[5]);
    __half2 r3 = __floats2half2_rn(o3.x + acc[6], o3.y + acc[7]);
    uint4 out;
    out.x = *(uint32_t*)&r0;
    out.y = *(uint32_t*)&r1;
    out.z = *(uint32_t*)&r2;
    out.w = *(uint32_t*)&r3;
    *(uint4*)ap = out;
}

// ---------------- launch ----------------
extern "C" void kernel_launch(void* const* d_in, const int* in_sizes, int n_in,
                              void* d_out, int out_size)
{
    const float* x      = (const float*)d_in[0];
    const float* q_w    = (const float*)d_in[1];
    const float* kv_w   = (const float*)d_in[2];
    const float* proj_w = (const float*)d_in[3];
    const float* proj_b = (const float*)d_in[4];
    const float* dwc_w  = (const float*)d_in[5];
    const float* dwc_b  = (const float*)d_in[6];
    const float* an_b   = (const float*)d_in[7];
    const float* na_b   = (const float*)d_in[8];
    const float* ah     = (const float*)d_in[9];
    const float* aw     = (const float*)d_in[10];
    const float* ha     = (const float*)d_in[11];
    const float* wa     = (const float*)d_in[12];

    __half *qkvp, *xhp, *acchp, *wtp;
    cudaGetSymbolAddress((void**)&qkvp, g_qkvh);
    cudaGetSymbolAddress((void**)&xhp, g_xh);
    cudaGetSymbolAddress((void**)&acchp, g_acch);
    cudaGetSymbolAddress((void**)&wtp, g_wTh);

    cudaFuncSetAttribute(gemm_h, cudaFuncAttributeMaxDynamicSharedMemorySize, GT_SMEM);
    cudaFuncSetAttribute(stage1_mma, cudaFuncAttributeMaxDynamicSharedMemorySize, S1_SMEM);

    const int M = Bn * Nn;  // 50176

    // weights: rows 0..511 = q, 512..1535 = kv, then proj
    wtrans_kernel<<<dim3(512 / 32, 512 / 32), 256>>>(q_w, wtp, 512, 512);
    wtrans_kernel<<<dim3(1024 / 32, 512 / 32), 256>>>(kv_w, wtp + 512 * 512, 512, 1024);
    wtrans_kernel<<<dim3(512 / 32, 512 / 32), 256>>>(proj_w, wtp + WT_PROJ, 512, 512);
    xconv_kernel<<<(int)(((size_t)M * Cc / 8) / 256), 256>>>(x, xhp);

    // fused q+kv GEMM: Nc = 1536
    gemm_h<<<dim3(QKV / 128, M / 128), 256, GT_SMEM>>>(xhp, wtp, nullptr, qkvp, M, Cc, QKV, nullptr);
    pool_kernel<<<(Bn * AG * Cc) / 256, 256>>>();
    biasak_kernel<<<(HEADS * AG * Nn) / 256, 256>>>(an_b, ah, aw);
    biasqa_kernel<<<(HEADS * Nn * AG) / 256, 256>>>(na_b, ha, wa);
    stage1_mma<<<Bn * HEADS, 256, S1_SMEM>>>();
    stage2_mma<<<dim3(25, Bn * HEADS), 256>>>();
    dwc_kernel<<<(int)(((size_t)Bn * Nn * 64) / 256), 256>>>(dwc_w, dwc_b);
    gemm_h<<<dim3(Cc / 128, M / 128), 256, GT_SMEM>>>(acchp, wtp + WT_PROJ, (float*)d_out, nullptr, M, Cc, Cc, proj_b);
}